// round 6
// baseline (speedup 1.0000x reference)
#include <cuda_runtime.h>
#include <math.h>

#define Nn 2
#define Hh 8
#define Ss 1024
#define DHh 64
#define Dd 512
#define Pp 2047   // 2S-1
#define TPAD 2048 // padded head stride for g_T (Pp is odd -> float2 misalign)

__device__ float g_ENC[Pp * Dd];
__device__ float g_R[Hh * Pp * DHh];
__device__ float g_T[Hh * TPAD];

__device__ __forceinline__ unsigned f2tf(float x) {
    unsigned r;
    asm("cvt.rna.tf32.f32 %0, %1;" : "=r"(r) : "f"(x));
    return r;
}
__device__ __forceinline__ float tf32f(float x) { return __uint_as_float(f2tf(x)); }
__device__ __forceinline__ void mma_tf32(float c[4], unsigned a0, unsigned a1,
                                         unsigned a2, unsigned a3,
                                         unsigned b0, unsigned b1) {
    asm volatile(
        "mma.sync.aligned.m16n8k8.row.col.f32.tf32.tf32.f32 "
        "{%0,%1,%2,%3},{%4,%5,%6,%7},{%8,%9},{%0,%1,%2,%3};"
        : "+f"(c[0]), "+f"(c[1]), "+f"(c[2]), "+f"(c[3])
        : "r"(a0), "r"(a1), "r"(a2), "r"(a3), "r"(b0), "r"(b1));
}
__device__ __forceinline__ unsigned ldb(const float* p) { return __float_as_uint(*p); }

// ---------------------------------------------------------------------------
// Kernel 0: positional encodings by incremental rotation. grid 64 x 256 thr.
// ---------------------------------------------------------------------------
__global__ void __launch_bounds__(256) enc_rot_kernel() {
    int i = threadIdx.x;                  // freq index 0..255
    int p0 = blockIdx.x * 32;
    int steps = Pp - p0; if (steps > 32) steps = 32;
    const float coef = -9.210340371976184f / 512.0f;  // -ln(1e4)/D
    float invf = __expf((float)(2 * i) * coef);
    float s, c;
    sincosf((float)(1023 - p0) * invf, &s, &c);
    float rs, rc;
    sincosf(invf, &rs, &rc);              // step = multiply by e^{-i*invf}
    for (int t = 0; t < steps; t++) {
        *(float2*)&g_ENC[(size_t)(p0 + t) * Dd + 2 * i] = make_float2(s, c);
        float s2 = s * rc - c * rs;
        float c2 = c * rc + s * rs;
        s = s2; c = c2;
    }
}

// ---------------------------------------------------------------------------
// Kernel 1: r-projection (tf32 mma) + per-head rank-1 vector g_T.
// ---------------------------------------------------------------------------
__global__ void __launch_bounds__(256) rproj_mma_kernel(
    const float* __restrict__ W, const float* __restrict__ u_bias,
    const float* __restrict__ v_bias)
{
    __shared__ float As[64 * 36];
    __shared__ float Bsm[64 * 36];
    __shared__ float scr[2 * 64];

    int tid = threadIdx.x;
    int warp = tid >> 5, lane = tid & 31;
    int g = lane >> 2, tg = lane & 3;
    int wm = (warp & 3) * 16;
    int wn = warp >> 2;

    int p0 = blockIdx.x * 64;
    int h = blockIdx.y;
    int c0 = h * 64;

    float acc[4][4] = {};

    for (int j0 = 0; j0 < Dd; j0 += 32) {
        __syncthreads();
#pragma unroll
        for (int r = 0; r < 2; r++) {
            int q = tid + r * 256;
            int row = q >> 3, qq = q & 7;
            int p = p0 + row;
            float4 e = make_float4(0.f, 0.f, 0.f, 0.f);
            if (p < Pp) e = *(const float4*)&g_ENC[(size_t)p * Dd + j0 + 4 * qq];
            float4 o; o.x = tf32f(e.x); o.y = tf32f(e.y); o.z = tf32f(e.z); o.w = tf32f(e.w);
            *(float4*)&As[row * 36 + 4 * qq] = o;
        }
#pragma unroll
        for (int r = 0; r < 2; r++) {
            int q2 = tid + r * 256;
            int row = q2 >> 3, qq = q2 & 7;
            float4 w = *(const float4*)&W[(size_t)(c0 + row) * Dd + j0 + 4 * qq];
            float4 o; o.x = tf32f(w.x); o.y = tf32f(w.y); o.z = tf32f(w.z); o.w = tf32f(w.w);
            *(float4*)&Bsm[row * 36 + 4 * qq] = o;
        }
        __syncthreads();
#pragma unroll
        for (int k0 = 0; k0 < 32; k0 += 8) {
            unsigned a0 = ldb(&As[(wm + g) * 36 + k0 + tg]);
            unsigned a1 = ldb(&As[(wm + g + 8) * 36 + k0 + tg]);
            unsigned a2 = ldb(&As[(wm + g) * 36 + k0 + tg + 4]);
            unsigned a3 = ldb(&As[(wm + g + 8) * 36 + k0 + tg + 4]);
#pragma unroll
            for (int nt = 0; nt < 4; nt++) {
                int n0 = wn * 32 + nt * 8;
                unsigned b0 = ldb(&Bsm[(n0 + g) * 36 + k0 + tg]);
                unsigned b1 = ldb(&Bsm[(n0 + g) * 36 + k0 + tg + 4]);
                mma_tf32(acc[nt], a0, a1, a2, a3, b0, b1);
            }
        }
    }
    int pA = p0 + wm + g, pB = pA + 8;
    float* Rh = g_R + (size_t)h * (Pp * DHh);
#pragma unroll
    for (int nt = 0; nt < 4; nt++) {
        int n0 = wn * 32 + nt * 8;
        if (pA < Pp)
            *(float2*)&Rh[(size_t)pA * DHh + n0 + 2 * tg] = make_float2(acc[nt][0], acc[nt][1]);
        if (pB < Pp)
            *(float2*)&Rh[(size_t)pB * DHh + n0 + 2 * tg] = make_float2(acc[nt][2], acc[nt][3]);
    }

    // ---- g_T[h][p] = (v_bias - u_bias) . R[h][p][:] ----
    float localA = 0.0f, localB = 0.0f;
#pragma unroll
    for (int nt = 0; nt < 4; nt++) {
        int n0 = wn * 32 + nt * 8;
        float2 u2 = *(const float2*)&u_bias[h * DHh + n0 + 2 * tg];
        float2 v2 = *(const float2*)&v_bias[h * DHh + n0 + 2 * tg];
        float db0 = v2.x - u2.x, db1 = v2.y - u2.y;
        localA += acc[nt][0] * db0 + acc[nt][1] * db1;
        localB += acc[nt][2] * db0 + acc[nt][3] * db1;
    }
    localA += __shfl_xor_sync(0xffffffffu, localA, 1);
    localA += __shfl_xor_sync(0xffffffffu, localA, 2);
    localB += __shfl_xor_sync(0xffffffffu, localB, 1);
    localB += __shfl_xor_sync(0xffffffffu, localB, 2);
    if (tg == 0) {
        scr[wn * 64 + wm + g] = localA;
        scr[wn * 64 + wm + g + 8] = localB;
    }
    __syncthreads();
    if (tid < 64 && p0 + tid < Pp)
        g_T[h * TPAD + p0 + tid] = scr[tid] + scr[64 + tid];
}

// ---------------------------------------------------------------------------
// Kernel 2: fused causal flash attention. 512 threads, grid (8,16),
// paired qtiles {15-bx, bx}. Permuted frag layout, merged AC/BD, rank-1 tvec,
// one-exchange softmax (4 barriers/iter), register prefetch.
// ---------------------------------------------------------------------------
#define SQU 0
#define SKS (SQU + 64*68)
#define SVS (SKS + 64*68)          // [64][72]
#define SRS (SVS + 64*72)          // ring 2 x [64][68]
#define SSC (SRS + 2*64*68)        // P (raw fp32), perm cols [64][68]
#define SBS (SSC + 64*68)          // BD ring 2 x [64][68] (tvec folded in)
#define SPM (SBS + 2*64*68)        // partial max [4][64]
#define SPS (SPM + 256)            // partial sum [4][64]
#define STOT (SPS + 256)

__global__ void __launch_bounds__(512) attn_kernel(
    const float* __restrict__ seqs, const float* __restrict__ keys,
    const float* __restrict__ values, const float* __restrict__ u_bias,
    float* __restrict__ out)
{
    extern __shared__ float sm[];
    float* Qu = sm + SQU;
    float* Ks = sm + SKS;
    float* Vs = sm + SVS;
    float* Rs = sm + SRS;
    float* Sc = sm + SSC;
    float* Bs = sm + SBS;
    float* sPM = sm + SPM;
    float* sPS = sm + SPS;

    int tid = threadIdx.x;
    int warp = tid >> 5, lane = tid & 31;
    int g = lane >> 2, tg = lane & 3;
    int wm = (warp & 3) * 16;
    int wn = warp >> 2;             // 0..3, 16-col slice
    int rA = wm + g, rB = wm + g + 8;

    int bx = blockIdx.x;
    int head = blockIdx.y;
    int n = head >> 3, h = head & 7;

    const float* sq = seqs   + ((size_t)(n * Hh + h) * Ss) * DHh;
    const float* kq = keys   + ((size_t)(n * Hh + h) * Ss) * DHh;
    const float* vq = values + ((size_t)(n * Hh + h) * Ss) * DHh;
    const float* Rh = g_R + (size_t)h * (Pp * DHh);
    const float* Th = g_T + (size_t)h * TPAD;

    int lrow = tid >> 4;            // 0..31
    int lq4  = tid & 15;
    int b8 = (lq4 >> 1) * 8 + (lq4 & 1);   // permuted dest base for a float4

    float4 ub4 = *(const float4*)&u_bias[h * DHh + lq4 * 4];
    const float scale = 0.125f;

    for (int ph = 0; ph < 2; ph++) {
        int qt = (ph == 0) ? (15 - bx) : bx;
        int i0 = qt * 64;
        int pb0 = (Ss - 1) - i0 - 63;

        // prologue prefetch (regs only)
        float4 pQ0 = *(const float4*)&sq[(size_t)(i0 + lrow) * DHh + lq4 * 4];
        float4 pQ1 = *(const float4*)&sq[(size_t)(i0 + lrow + 32) * DHh + lq4 * 4];
        float4 pK0 = *(const float4*)&kq[(size_t)(lrow) * DHh + lq4 * 4];
        float4 pK1 = *(const float4*)&kq[(size_t)(lrow + 32) * DHh + lq4 * 4];
        float4 pV0 = *(const float4*)&vq[(size_t)(lrow) * DHh + lq4 * 4];
        float4 pV1 = *(const float4*)&vq[(size_t)(lrow + 32) * DHh + lq4 * 4];
        float4 pR0 = *(const float4*)&Rh[(size_t)(pb0 + lrow) * DHh + lq4 * 4];
        float4 pR1 = *(const float4*)&Rh[(size_t)(pb0 + lrow + 32) * DHh + lq4 * 4];
        float4 pR2 = *(const float4*)&Rh[(size_t)(pb0 + lrow + 64) * DHh + lq4 * 4];
        float4 pR3 = *(const float4*)&Rh[(size_t)(pb0 + lrow + 96) * DHh + lq4 * 4];

        __syncthreads();   // previous phase fully consumed
        {
            float* q0 = &Qu[lrow * 68 + b8];
            q0[0] = tf32f(pQ0.x + ub4.x); q0[2] = tf32f(pQ0.y + ub4.y);
            q0[4] = tf32f(pQ0.z + ub4.z); q0[6] = tf32f(pQ0.w + ub4.w);
            float* q1 = &Qu[(lrow + 32) * 68 + b8];
            q1[0] = tf32f(pQ1.x + ub4.x); q1[2] = tf32f(pQ1.y + ub4.y);
            q1[4] = tf32f(pQ1.z + ub4.z); q1[6] = tf32f(pQ1.w + ub4.w);
        }

        float mA_run = -INFINITY, mB_run = -INFINITY;
        float lA_run = 0.0f, lB_run = 0.0f;
        float O[2][4];
#pragma unroll
        for (int a = 0; a < 2; a++)
#pragma unroll
            for (int b = 0; b < 4; b++) O[a][b] = 0.0f;

        for (int kt = 0; kt <= qt; kt++) {
            int j0 = kt * 64;
            int pbase = (Ss - 1) - i0 + j0 - 63;
            int bufLow = kt & 1, bufHigh = bufLow ^ 1;

            if (kt > 0) __syncthreads();   // S1 (kt==0 covered by phase sync)

            // stage K, V, R from prefetched regs
            {
                float* k0p = &Ks[lrow * 68 + b8];
                k0p[0] = tf32f(pK0.x); k0p[2] = tf32f(pK0.y);
                k0p[4] = tf32f(pK0.z); k0p[6] = tf32f(pK0.w);
                float* k1p = &Ks[(lrow + 32) * 68 + b8];
                k1p[0] = tf32f(pK1.x); k1p[2] = tf32f(pK1.y);
                k1p[4] = tf32f(pK1.z); k1p[6] = tf32f(pK1.w);
                float4 v0; v0.x = tf32f(pV0.x); v0.y = tf32f(pV0.y);
                v0.z = tf32f(pV0.z); v0.w = tf32f(pV0.w);
                *(float4*)&Vs[lrow * 72 + lq4 * 4] = v0;
                float4 v1; v1.x = tf32f(pV1.x); v1.y = tf32f(pV1.y);
                v1.z = tf32f(pV1.z); v1.w = tf32f(pV1.w);
                *(float4*)&Vs[(lrow + 32) * 72 + lq4 * 4] = v1;
            }
            if (kt == 0) {
                float* r0p = &Rs[lrow * 68 + b8];
                r0p[0] = tf32f(pR0.x); r0p[2] = tf32f(pR0.y);
                r0p[4] = tf32f(pR0.z); r0p[6] = tf32f(pR0.w);
                float* r1p = &Rs[(lrow + 32) * 68 + b8];
                r1p[0] = tf32f(pR1.x); r1p[2] = tf32f(pR1.y);
                r1p[4] = tf32f(pR1.z); r1p[6] = tf32f(pR1.w);
                float* r2p = &Rs[(lrow + 64) * 68 + b8];
                r2p[0] = tf32f(pR2.x); r2p[2] = tf32f(pR2.y);
                r2p[4] = tf32f(pR2.z); r2p[6] = tf32f(pR2.w);
                float* r3p = &Rs[(lrow + 96) * 68 + b8];
                r3p[0] = tf32f(pR3.x); r3p[2] = tf32f(pR3.y);
                r3p[4] = tf32f(pR3.z); r3p[6] = tf32f(pR3.w);
            } else {
                float* Rd = Rs + bufHigh * (64 * 68);
                float* r0p = &Rd[lrow * 68 + b8];
                r0p[0] = tf32f(pR0.x); r0p[2] = tf32f(pR0.y);
                r0p[4] = tf32f(pR0.z); r0p[6] = tf32f(pR0.w);
                float* r1p = &Rd[(lrow + 32) * 68 + b8];
                r1p[0] = tf32f(pR1.x); r1p[2] = tf32f(pR1.y);
                r1p[4] = tf32f(pR1.z); r1p[6] = tf32f(pR1.w);
            }

            // tvec prefetch for Bs store
            float2 tv[4];
            if (kt == 0) {
#pragma unroll
                for (int nt = 0; nt < 4; nt++)
                    tv[nt] = *(const float2*)&Th[pbase + wn * 32 + nt * 8 + 2 * tg];
            } else {
#pragma unroll
                for (int nt = 0; nt < 2; nt++)
                    tv[nt] = *(const float2*)&Th[pbase + 64 + wn * 16 + nt * 8 + 2 * tg];
            }
            __syncthreads();   // S2

            // prefetch next iteration's tiles into regs
            if (kt < qt) {
                int jn = j0 + 64;
                int pn = pbase + 128;
                pK0 = *(const float4*)&kq[(size_t)(jn + lrow) * DHh + lq4 * 4];
                pK1 = *(const float4*)&kq[(size_t)(jn + lrow + 32) * DHh + lq4 * 4];
                pV0 = *(const float4*)&vq[(size_t)(jn + lrow) * DHh + lq4 * 4];
                pV1 = *(const float4*)&vq[(size_t)(jn + lrow + 32) * DHh + lq4 * 4];
                pR0 = *(const float4*)&Rh[(size_t)(pn + lrow) * DHh + lq4 * 4];
                pR1 = *(const float4*)&Rh[(size_t)(pn + lrow + 32) * DHh + lq4 * 4];
            }

            // ---- merged AC + BD mma ----
            float cS[2][4];
#pragma unroll
            for (int t = 0; t < 2; t++)
#pragma unroll
                for (int e = 0; e < 4; e++) cS[t][e] = 0.0f;

            if (kt == 0) {
                float cB[4][4];
#pragma unroll
                for (int t = 0; t < 4; t++)
#pragma unroll
                    for (int e = 0; e < 4; e++) cB[t][e] = 0.0f;
#pragma unroll
                for (int k0 = 0; k0 < 64; k0 += 8) {
                    float2 aA = *(const float2*)&Qu[rA * 68 + k0 + 2 * tg];
                    float2 aB = *(const float2*)&Qu[rB * 68 + k0 + 2 * tg];
                    unsigned a0 = __float_as_uint(aA.x), a2 = __float_as_uint(aA.y);
                    unsigned a1 = __float_as_uint(aB.x), a3 = __float_as_uint(aB.y);
#pragma unroll
                    for (int nt = 0; nt < 2; nt++) {
                        int n0 = wn * 16 + nt * 8;
                        float2 b = *(const float2*)&Ks[(n0 + g) * 68 + k0 + 2 * tg];
                        mma_tf32(cS[nt], a0, a1, a2, a3,
                                 __float_as_uint(b.x), __float_as_uint(b.y));
                    }
#pragma unroll
                    for (int nt = 0; nt < 4; nt++) {
                        int o0 = wn * 32 + nt * 8;
                        float2 b = *(const float2*)&Rs[(o0 + g) * 68 + k0 + 2 * tg];
                        mma_tf32(cB[nt], a0, a1, a2, a3,
                                 __float_as_uint(b.x), __float_as_uint(b.y));
                    }
                }
#pragma unroll
                for (int nt = 0; nt < 4; nt++) {
                    int o0 = wn * 32 + nt * 8;
                    float* Bd = Bs + (o0 >> 6) * (64 * 68) + (o0 & 63) + 2 * tg;
                    *(float2*)&Bd[rA * 68] = make_float2(cB[nt][0] + tv[nt].x, cB[nt][1] + tv[nt].y);
                    *(float2*)&Bd[rB * 68] = make_float2(cB[nt][2] + tv[nt].x, cB[nt][3] + tv[nt].y);
                }
            } else {
                float cB[2][4];
#pragma unroll
                for (int t = 0; t < 2; t++)
#pragma unroll
                    for (int e = 0; e < 4; e++) cB[t][e] = 0.0f;
                const float* Rb = Rs + bufHigh * (64 * 68);
#pragma unroll
                for (int k0 = 0; k0 < 64; k0 += 8) {
                    float2 aA = *(const float2*)&Qu[rA * 68 + k0 + 2 * tg];
                    float2 aB = *(const float2*)&Qu[rB * 68 + k0 + 2 * tg];
                    unsigned a0 = __float_as_uint(aA.x), a2 = __float_as_uint(aA.y);
                    unsigned a1 = __float_as_uint(aB.x), a3 = __float_as_uint(aB.y);
#pragma unroll
                    for (int nt = 0; nt < 2; nt++) {
                        int n0 = wn * 16 + nt * 8;
                        float2 b = *(const float2*)&Ks[(n0 + g) * 68 + k0 + 2 * tg];
                        mma_tf32(cS[nt], a0, a1, a2, a3,
                                 __float_as_uint(b.x), __float_as_uint(b.y));
                    }
#pragma unroll
                    for (int nt = 0; nt < 2; nt++) {
                        int r0 = wn * 16 + nt * 8;
                        float2 b = *(const float2*)&Rb[(r0 + g) * 68 + k0 + 2 * tg];
                        mma_tf32(cB[nt], a0, a1, a2, a3,
                                 __float_as_uint(b.x), __float_as_uint(b.y));
                    }
                }
                float* Bd0 = Bs + bufHigh * (64 * 68);
#pragma unroll
                for (int nt = 0; nt < 2; nt++) {
                    int r0 = wn * 16 + nt * 8;
                    float* Bd = Bd0 + r0 + 2 * tg;
                    *(float2*)&Bd[rA * 68] = make_float2(cB[nt][0] + tv[nt].x, cB[nt][1] + tv[nt].y);
                    *(float2*)&Bd[rB * 68] = make_float2(cB[nt][2] + tv[nt].x, cB[nt][3] + tv[nt].y);
                }
            }
            __syncthreads();   // S3a: Bs visible

            // ---- scores, warp-local softmax, P store ----
            float sv[2][4];
            float mAl = -INFINITY, mBl = -INFINITY;
            int diag = (kt == qt);
#pragma unroll
            for (int nt = 0; nt < 2; nt++) {
                int colbase = wn * 16 + nt * 8 + 2 * tg;
#pragma unroll
                for (int e = 0; e < 4; e++) {
                    int j = colbase + (e & 1);
                    int row = (e < 2) ? rA : rB;
                    int o = j - row + 63;
                    float bd = Bs[(bufLow ^ (o >> 6)) * (64 * 68) + row * 68 + (o & 63)];
                    float s = (cS[nt][e] + bd) * scale;
                    if (diag && j > row) s = -INFINITY;
                    sv[nt][e] = s;
                    if (e < 2) mAl = fmaxf(mAl, s); else mBl = fmaxf(mBl, s);
                }
            }
            mAl = fmaxf(mAl, __shfl_xor_sync(0xffffffffu, mAl, 1));
            mAl = fmaxf(mAl, __shfl_xor_sync(0xffffffffu, mAl, 2));
            mBl = fmaxf(mBl, __shfl_xor_sync(0xffffffffu, mBl, 1));
            mBl = fmaxf(mBl, __shfl_xor_sync(0xffffffffu, mBl, 2));
            mAl = fmaxf(mAl, -1e30f);
            mBl = fmaxf(mBl, -1e30f);

            float sumA = 0.0f, sumB = 0.0f;
            int pos0 = (tg & 1) * 4 + (tg >> 1);
#pragma unroll
            for (int nt = 0; nt < 2; nt++) {
                int base8 = wn * 16 + nt * 8;
                float e0 = __expf(sv[nt][0] - mAl);
                float e1 = __expf(sv[nt][1] - mAl);
                float e2 = __expf(sv[nt][2] - mBl);
                float e3 = __expf(sv[nt][3] - mBl);
                sumA += e0 + e1; sumB += e2 + e3;
                Sc[rA * 68 + base8 + pos0]     = e0;
                Sc[rA * 68 + base8 + pos0 + 2] = e1;
                Sc[rB * 68 + base8 + pos0]     = e2;
                Sc[rB * 68 + base8 + pos0 + 2] = e3;
            }
            sumA += __shfl_xor_sync(0xffffffffu, sumA, 1);
            sumA += __shfl_xor_sync(0xffffffffu, sumA, 2);
            sumB += __shfl_xor_sync(0xffffffffu, sumB, 1);
            sumB += __shfl_xor_sync(0xffffffffu, sumB, 2);
            if (tg == 0) {
                sPM[wn * 64 + rA] = mAl; sPM[wn * 64 + rB] = mBl;
                sPS[wn * 64 + rA] = sumA; sPS[wn * 64 + rB] = sumB;
            }
            __syncthreads();   // S3b: P + partials visible

            // ---- combine partials (per-thread, redundant, register state) ----
            float fA[4], fB[4];
            {
                float m0 = sPM[rA], m1 = sPM[64 + rA], m2 = sPM[128 + rA], m3 = sPM[192 + rA];
                float mg = fmaxf(fmaxf(mA_run, fmaxf(m0, m1)), fmaxf(m2, m3));
                float corr = __expf(mA_run - mg);
                fA[0] = __expf(m0 - mg); fA[1] = __expf(m1 - mg);
                fA[2] = __expf(m2 - mg); fA[3] = __expf(m3 - mg);
                lA_run = lA_run * corr
                       + sPS[rA] * fA[0] + sPS[64 + rA] * fA[1]
                       + sPS[128 + rA] * fA[2] + sPS[192 + rA] * fA[3];
                mA_run = mg;
#pragma unroll
                for (int nt = 0; nt < 2; nt++) { O[nt][0] *= corr; O[nt][1] *= corr; }
            }
            {
                float m0 = sPM[rB], m1 = sPM[64 + rB], m2 = sPM[128 + rB], m3 = sPM[192 + rB];
                float mg = fmaxf(fmaxf(mB_run, fmaxf(m0, m1)), fmaxf(m2, m3));
                float corr = __expf(mB_run - mg);
                fB[0] = __expf(m0 - mg); fB[1] = __expf(m1 - mg);
                fB[2] = __expf(m2 - mg); fB[3] = __expf(m3 - mg);
                lB_run = lB_run * corr
                       + sPS[rB] * fB[0] + sPS[64 + rB] * fB[1]
                       + sPS[128 + rB] * fB[2] + sPS[192 + rB] * fB[3];
                mB_run = mg;
#pragma unroll
                for (int nt = 0; nt < 2; nt++) { O[nt][2] *= corr; O[nt][3] *= corr; }
            }

            // ---- O += (f .* P) @ V ----
#pragma unroll
            for (int k0 = 0; k0 < 64; k0 += 8) {
                const int w = k0 >> 4;
                float2 pA = *(const float2*)&Sc[rA * 68 + k0 + 2 * tg];
                float2 pB = *(const float2*)&Sc[rB * 68 + k0 + 2 * tg];
                unsigned a0 = f2tf(pA.x * fA[w]), a2 = f2tf(pA.y * fA[w]);
                unsigned a1 = f2tf(pB.x * fB[w]), a3 = f2tf(pB.y * fB[w]);
#pragma unroll
                for (int nt = 0; nt < 2; nt++) {
                    int n0 = wn * 16 + nt * 8;
                    unsigned b0 = ldb(&Vs[(k0 + tg) * 72 + n0 + g]);
                    unsigned b1 = ldb(&Vs[(k0 + tg + 4) * 72 + n0 + g]);
                    mma_tf32(O[nt], a0, a1, a2, a3, b0, b1);
                }
            }
        }

        // ---- epilogue ----
        float invA = 1.0f / lA_run;
        float invB = 1.0f / lB_run;
        float* op = out + ((size_t)(n * Hh + h) * Ss + i0) * DHh;
#pragma unroll
        for (int nt = 0; nt < 2; nt++) {
            int n0 = wn * 16 + nt * 8;
            *(float2*)&op[(size_t)rA * DHh + n0 + 2 * tg] =
                make_float2(O[nt][0] * invA, O[nt][1] * invA);
            *(float2*)&op[(size_t)rB * DHh + n0 + 2 * tg] =
                make_float2(O[nt][2] * invB, O[nt][3] * invB);
        }
    }
}

// ---------------------------------------------------------------------------
extern "C" void kernel_launch(void* const* d_in, const int* in_sizes, int n_in,
                              void* d_out, int out_size) {
    const float* seqs   = (const float*)d_in[0];
    const float* keys   = (const float*)d_in[1];
    const float* values = (const float*)d_in[2];
    const float* u_bias = (const float*)d_in[3];
    const float* v_bias = (const float*)d_in[4];
    const float* rproj  = (const float*)d_in[5];
    (void)in_sizes; (void)n_in; (void)out_size;

    const int smem_bytes = STOT * sizeof(float);   // ~139 KB
    cudaFuncSetAttribute(attn_kernel, cudaFuncAttributeMaxDynamicSharedMemorySize,
                         smem_bytes);

    enc_rot_kernel<<<64, 256>>>();
    rproj_mma_kernel<<<dim3(32, 8), 256>>>(rproj, u_bias, v_bias);
    attn_kernel<<<dim3(8, 16), 512, smem_bytes>>>(seqs, keys, values,
                                                  u_bias, (float*)d_out);
}

// round 7
// speedup vs baseline: 1.1860x; 1.1860x over previous
#include <cuda_runtime.h>
#include <math.h>

#define Nn 2
#define Hh 8
#define Ss 1024
#define DHh 64
#define Dd 512
#define Pp 2047   // 2S-1
#define TPAD 2048 // padded head stride for g_T (Pp odd -> float2 misalign)

__device__ float g_ENC[Pp * Dd];
__device__ float g_R[Hh * Pp * DHh];
__device__ float g_T[Hh * TPAD];

__device__ __forceinline__ unsigned f2tf(float x) {
    unsigned r;
    asm("cvt.rna.tf32.f32 %0, %1;" : "=r"(r) : "f"(x));
    return r;
}
__device__ __forceinline__ float tf32f(float x) { return __uint_as_float(f2tf(x)); }
__device__ __forceinline__ void mma_tf32(float c[4], unsigned a0, unsigned a1,
                                         unsigned a2, unsigned a3,
                                         unsigned b0, unsigned b1) {
    asm volatile(
        "mma.sync.aligned.m16n8k8.row.col.f32.tf32.tf32.f32 "
        "{%0,%1,%2,%3},{%4,%5,%6,%7},{%8,%9},{%0,%1,%2,%3};"
        : "+f"(c[0]), "+f"(c[1]), "+f"(c[2]), "+f"(c[3])
        : "r"(a0), "r"(a1), "r"(a2), "r"(a3), "r"(b0), "r"(b1));
}
__device__ __forceinline__ unsigned ldb(const float* p) { return __float_as_uint(*p); }

// ---------------------------------------------------------------------------
// Kernel 0: positional encodings by incremental rotation.
// ---------------------------------------------------------------------------
__global__ void __launch_bounds__(256) enc_rot_kernel() {
    int i = threadIdx.x;
    int p0 = blockIdx.x * 32;
    int steps = Pp - p0; if (steps > 32) steps = 32;
    const float coef = -9.210340371976184f / 512.0f;
    float invf = __expf((float)(2 * i) * coef);
    float s, c;
    sincosf((float)(1023 - p0) * invf, &s, &c);
    float rs, rc;
    sincosf(invf, &rs, &rc);
    for (int t = 0; t < steps; t++) {
        *(float2*)&g_ENC[(size_t)(p0 + t) * Dd + 2 * i] = make_float2(s, c);
        float s2 = s * rc - c * rs;
        float c2 = c * rc + s * rs;
        s = s2; c = c2;
    }
}

// ---------------------------------------------------------------------------
// Kernel 1: r-projection (tf32 mma) + per-head rank-1 vector g_T.
// ---------------------------------------------------------------------------
__global__ void __launch_bounds__(256) rproj_mma_kernel(
    const float* __restrict__ W, const float* __restrict__ u_bias,
    const float* __restrict__ v_bias)
{
    __shared__ float As[64 * 36];
    __shared__ float Bsm[64 * 36];
    __shared__ float scr[2 * 64];

    int tid = threadIdx.x;
    int warp = tid >> 5, lane = tid & 31;
    int g = lane >> 2, tg = lane & 3;
    int wm = (warp & 3) * 16;
    int wn = warp >> 2;

    int p0 = blockIdx.x * 64;
    int h = blockIdx.y;
    int c0 = h * 64;

    float acc[4][4] = {};

    for (int j0 = 0; j0 < Dd; j0 += 32) {
        __syncthreads();
#pragma unroll
        for (int r = 0; r < 2; r++) {
            int q = tid + r * 256;
            int row = q >> 3, qq = q & 7;
            int p = p0 + row;
            float4 e = make_float4(0.f, 0.f, 0.f, 0.f);
            if (p < Pp) e = *(const float4*)&g_ENC[(size_t)p * Dd + j0 + 4 * qq];
            float4 o; o.x = tf32f(e.x); o.y = tf32f(e.y); o.z = tf32f(e.z); o.w = tf32f(e.w);
            *(float4*)&As[row * 36 + 4 * qq] = o;
        }
#pragma unroll
        for (int r = 0; r < 2; r++) {
            int q2 = tid + r * 256;
            int row = q2 >> 3, qq = q2 & 7;
            float4 w = *(const float4*)&W[(size_t)(c0 + row) * Dd + j0 + 4 * qq];
            float4 o; o.x = tf32f(w.x); o.y = tf32f(w.y); o.z = tf32f(w.z); o.w = tf32f(w.w);
            *(float4*)&Bsm[row * 36 + 4 * qq] = o;
        }
        __syncthreads();
#pragma unroll
        for (int k0 = 0; k0 < 32; k0 += 8) {
            unsigned a0 = ldb(&As[(wm + g) * 36 + k0 + tg]);
            unsigned a1 = ldb(&As[(wm + g + 8) * 36 + k0 + tg]);
            unsigned a2 = ldb(&As[(wm + g) * 36 + k0 + tg + 4]);
            unsigned a3 = ldb(&As[(wm + g + 8) * 36 + k0 + tg + 4]);
#pragma unroll
            for (int nt = 0; nt < 4; nt++) {
                int n0 = wn * 32 + nt * 8;
                unsigned b0 = ldb(&Bsm[(n0 + g) * 36 + k0 + tg]);
                unsigned b1 = ldb(&Bsm[(n0 + g) * 36 + k0 + tg + 4]);
                mma_tf32(acc[nt], a0, a1, a2, a3, b0, b1);
            }
        }
    }
    int pA = p0 + wm + g, pB = pA + 8;
    float* Rh = g_R + (size_t)h * (Pp * DHh);
#pragma unroll
    for (int nt = 0; nt < 4; nt++) {
        int n0 = wn * 32 + nt * 8;
        if (pA < Pp)
            *(float2*)&Rh[(size_t)pA * DHh + n0 + 2 * tg] = make_float2(acc[nt][0], acc[nt][1]);
        if (pB < Pp)
            *(float2*)&Rh[(size_t)pB * DHh + n0 + 2 * tg] = make_float2(acc[nt][2], acc[nt][3]);
    }

    // ---- g_T[h][p] = (v_bias - u_bias) . R[h][p][:] ----
    float localA = 0.0f, localB = 0.0f;
#pragma unroll
    for (int nt = 0; nt < 4; nt++) {
        int n0 = wn * 32 + nt * 8;
        float2 u2 = *(const float2*)&u_bias[h * DHh + n0 + 2 * tg];
        float2 v2 = *(const float2*)&v_bias[h * DHh + n0 + 2 * tg];
        float db0 = v2.x - u2.x, db1 = v2.y - u2.y;
        localA += acc[nt][0] * db0 + acc[nt][1] * db1;
        localB += acc[nt][2] * db0 + acc[nt][3] * db1;
    }
    localA += __shfl_xor_sync(0xffffffffu, localA, 1);
    localA += __shfl_xor_sync(0xffffffffu, localA, 2);
    localB += __shfl_xor_sync(0xffffffffu, localB, 1);
    localB += __shfl_xor_sync(0xffffffffu, localB, 2);
    if (tg == 0) {
        scr[wn * 64 + wm + g] = localA;
        scr[wn * 64 + wm + g + 8] = localB;
    }
    __syncthreads();
    if (tid < 64 && p0 + tid < Pp)
        g_T[h * TPAD + p0 + tid] = scr[tid] + scr[64 + tid];
}

// ---------------------------------------------------------------------------
// Kernel 2: fused causal flash attention. 512 threads, grid (8,16),
// paired qtiles {15-bx, bx}. R4 layout (conflict-free scalar frags, no
// prefetch) + rank-1 tvec merged AC/BD + register-resident softmax.
// ---------------------------------------------------------------------------
#define SQU 0
#define SKS (SQU + 64*68)
#define SVS (SKS + 64*68)          // [64][72]
#define SRS (SVS + 64*72)          // ring 2 x [64][68]
#define SSC (SRS + 2*64*68)        // P raw fp32 [64][68]
#define SBS (SSC + 64*68)          // BD ring 2 x [64][68] (tvec folded)
#define SPM (SBS + 2*64*68)        // partial max [4][64]
#define SPS (SPM + 256)            // partial sum [4][64]
#define STOT (SPS + 256)

__global__ void __launch_bounds__(512) attn_kernel(
    const float* __restrict__ seqs, const float* __restrict__ keys,
    const float* __restrict__ values, const float* __restrict__ u_bias,
    float* __restrict__ out)
{
    extern __shared__ float sm[];
    float* Qu = sm + SQU;
    float* Ks = sm + SKS;
    float* Vs = sm + SVS;
    float* Rs = sm + SRS;
    float* Sc = sm + SSC;
    float* Bs = sm + SBS;
    float* sPM = sm + SPM;
    float* sPS = sm + SPS;

    int tid = threadIdx.x;
    int warp = tid >> 5, lane = tid & 31;
    int g = lane >> 2, tg = lane & 3;
    int wm = (warp & 3) * 16;
    int wn = warp >> 2;             // 0..3, 16-col slice
    int rA = wm + g, rB = wm + g + 8;

    int bx = blockIdx.x;
    int head = blockIdx.y;
    int n = head >> 3, h = head & 7;

    const float* sq = seqs   + ((size_t)(n * Hh + h) * Ss) * DHh;
    const float* kq = keys   + ((size_t)(n * Hh + h) * Ss) * DHh;
    const float* vq = values + ((size_t)(n * Hh + h) * Ss) * DHh;
    const float* Rh = g_R + (size_t)h * (Pp * DHh);
    const float* Th = g_T + (size_t)h * TPAD;

    int lrow = tid >> 4;            // 0..31
    int lq4  = tid & 15;

    float4 ub4 = *(const float4*)&u_bias[h * DHh + lq4 * 4];
    const float scale = 0.125f;

    for (int ph = 0; ph < 2; ph++) {
        int qt = (ph == 0) ? (15 - bx) : bx;
        int i0 = qt * 64;

        __syncthreads();   // previous phase fully consumed
#pragma unroll
        for (int r = 0; r < 2; r++) {
            int row = lrow + r * 32;
            float4 s4 = *(const float4*)&sq[(size_t)(i0 + row) * DHh + lq4 * 4];
            Qu[row * 68 + lq4 * 4 + 0] = tf32f(s4.x + ub4.x);
            Qu[row * 68 + lq4 * 4 + 1] = tf32f(s4.y + ub4.y);
            Qu[row * 68 + lq4 * 4 + 2] = tf32f(s4.z + ub4.z);
            Qu[row * 68 + lq4 * 4 + 3] = tf32f(s4.w + ub4.w);
        }

        float mA_run = -INFINITY, mB_run = -INFINITY;
        float lA_run = 0.0f, lB_run = 0.0f;
        float O[2][4];
#pragma unroll
        for (int a = 0; a < 2; a++)
#pragma unroll
            for (int b = 0; b < 4; b++) O[a][b] = 0.0f;

        for (int kt = 0; kt <= qt; kt++) {
            int j0 = kt * 64;
            int pbase = (Ss - 1) - i0 + j0 - 63;
            int bufLow = kt & 1, bufHigh = bufLow ^ 1;

            if (kt > 0) __syncthreads();   // S1

            // stage K, V (64 rows each)
#pragma unroll
            for (int r = 0; r < 2; r++) {
                int row = lrow + r * 32;
                float4 k4 = *(const float4*)&kq[(size_t)(j0 + row) * DHh + lq4 * 4];
                float4 v4 = *(const float4*)&vq[(size_t)(j0 + row) * DHh + lq4 * 4];
                Ks[row * 68 + lq4 * 4 + 0] = tf32f(k4.x);
                Ks[row * 68 + lq4 * 4 + 1] = tf32f(k4.y);
                Ks[row * 68 + lq4 * 4 + 2] = tf32f(k4.z);
                Ks[row * 68 + lq4 * 4 + 3] = tf32f(k4.w);
                Vs[row * 72 + lq4 * 4 + 0] = tf32f(v4.x);
                Vs[row * 72 + lq4 * 4 + 1] = tf32f(v4.y);
                Vs[row * 72 + lq4 * 4 + 2] = tf32f(v4.z);
                Vs[row * 72 + lq4 * 4 + 3] = tf32f(v4.w);
            }
            // stage R band
            if (kt == 0) {
#pragma unroll
                for (int r = 0; r < 4; r++) {
                    int row = lrow + r * 32;   // 0..127 contiguous over ring
                    float4 r4 = *(const float4*)&Rh[(size_t)(pbase + row) * DHh + lq4 * 4];
                    Rs[row * 68 + lq4 * 4 + 0] = tf32f(r4.x);
                    Rs[row * 68 + lq4 * 4 + 1] = tf32f(r4.y);
                    Rs[row * 68 + lq4 * 4 + 2] = tf32f(r4.z);
                    Rs[row * 68 + lq4 * 4 + 3] = tf32f(r4.w);
                }
            } else {
                float* Rd = Rs + bufHigh * (64 * 68);
#pragma unroll
                for (int r = 0; r < 2; r++) {
                    int row = lrow + r * 32;
                    float4 r4 = *(const float4*)&Rh[(size_t)(pbase + 64 + row) * DHh + lq4 * 4];
                    Rd[row * 68 + lq4 * 4 + 0] = tf32f(r4.x);
                    Rd[row * 68 + lq4 * 4 + 1] = tf32f(r4.y);
                    Rd[row * 68 + lq4 * 4 + 2] = tf32f(r4.z);
                    Rd[row * 68 + lq4 * 4 + 3] = tf32f(r4.w);
                }
            }
            // tvec for Bs store (aligned: TPAD even, pbase even, offsets even)
            float2 tv[4];
            if (kt == 0) {
#pragma unroll
                for (int nt = 0; nt < 4; nt++)
                    tv[nt] = *(const float2*)&Th[pbase + wn * 32 + nt * 8 + 2 * tg];
            } else {
#pragma unroll
                for (int nt = 0; nt < 2; nt++)
                    tv[nt] = *(const float2*)&Th[pbase + 64 + wn * 16 + nt * 8 + 2 * tg];
            }
            __syncthreads();   // S2: tiles ready

            // ---- merged AC + BD (shared A-fragments) ----
            float cS[2][4];
#pragma unroll
            for (int t = 0; t < 2; t++)
#pragma unroll
                for (int e = 0; e < 4; e++) cS[t][e] = 0.0f;

            if (kt == 0) {
                float cB[4][4];
#pragma unroll
                for (int t = 0; t < 4; t++)
#pragma unroll
                    for (int e = 0; e < 4; e++) cB[t][e] = 0.0f;
#pragma unroll
                for (int k0 = 0; k0 < 64; k0 += 8) {
                    unsigned a0 = ldb(&Qu[rA * 68 + k0 + tg]);
                    unsigned a1 = ldb(&Qu[rB * 68 + k0 + tg]);
                    unsigned a2 = ldb(&Qu[rA * 68 + k0 + tg + 4]);
                    unsigned a3 = ldb(&Qu[rB * 68 + k0 + tg + 4]);
#pragma unroll
                    for (int nt = 0; nt < 2; nt++) {
                        int n0 = wn * 16 + nt * 8;
                        unsigned b0 = ldb(&Ks[(n0 + g) * 68 + k0 + tg]);
                        unsigned b1 = ldb(&Ks[(n0 + g) * 68 + k0 + tg + 4]);
                        mma_tf32(cS[nt], a0, a1, a2, a3, b0, b1);
                    }
#pragma unroll
                    for (int nt = 0; nt < 4; nt++) {
                        int o0 = wn * 32 + nt * 8;
                        unsigned b0 = ldb(&Rs[(o0 + g) * 68 + k0 + tg]);
                        unsigned b1 = ldb(&Rs[(o0 + g) * 68 + k0 + tg + 4]);
                        mma_tf32(cB[nt], a0, a1, a2, a3, b0, b1);
                    }
                }
#pragma unroll
                for (int nt = 0; nt < 4; nt++) {
                    int o0 = wn * 32 + nt * 8;
                    float* Bd = Bs + (o0 >> 6) * (64 * 68) + (o0 & 63) + 2 * tg;
                    *(float2*)&Bd[rA * 68] = make_float2(cB[nt][0] + tv[nt].x, cB[nt][1] + tv[nt].y);
                    *(float2*)&Bd[rB * 68] = make_float2(cB[nt][2] + tv[nt].x, cB[nt][3] + tv[nt].y);
                }
            } else {
                float cB[2][4];
#pragma unroll
                for (int t = 0; t < 2; t++)
#pragma unroll
                    for (int e = 0; e < 4; e++) cB[t][e] = 0.0f;
                const float* Rb = Rs + bufHigh * (64 * 68);
#pragma unroll
                for (int k0 = 0; k0 < 64; k0 += 8) {
                    unsigned a0 = ldb(&Qu[rA * 68 + k0 + tg]);
                    unsigned a1 = ldb(&Qu[rB * 68 + k0 + tg]);
                    unsigned a2 = ldb(&Qu[rA * 68 + k0 + tg + 4]);
                    unsigned a3 = ldb(&Qu[rB * 68 + k0 + tg + 4]);
#pragma unroll
                    for (int nt = 0; nt < 2; nt++) {
                        int n0 = wn * 16 + nt * 8;
                        unsigned b0 = ldb(&Ks[(n0 + g) * 68 + k0 + tg]);
                        unsigned b1 = ldb(&Ks[(n0 + g) * 68 + k0 + tg + 4]);
                        mma_tf32(cS[nt], a0, a1, a2, a3, b0, b1);
                    }
#pragma unroll
                    for (int nt = 0; nt < 2; nt++) {
                        int r0 = wn * 16 + nt * 8;
                        unsigned b0 = ldb(&Rb[(r0 + g) * 68 + k0 + tg]);
                        unsigned b1 = ldb(&Rb[(r0 + g) * 68 + k0 + tg + 4]);
                        mma_tf32(cB[nt], a0, a1, a2, a3, b0, b1);
                    }
                }
                float* Bd0 = Bs + bufHigh * (64 * 68);
#pragma unroll
                for (int nt = 0; nt < 2; nt++) {
                    int r0 = wn * 16 + nt * 8;
                    float* Bd = Bd0 + r0 + 2 * tg;
                    *(float2*)&Bd[rA * 68] = make_float2(cB[nt][0] + tv[nt].x, cB[nt][1] + tv[nt].y);
                    *(float2*)&Bd[rB * 68] = make_float2(cB[nt][2] + tv[nt].x, cB[nt][3] + tv[nt].y);
                }
            }
            __syncthreads();   // S3a: Bs visible

            // ---- scores + warp-local softmax ----
            float sv[2][4];
            float mAl = -INFINITY, mBl = -INFINITY;
            int diag = (kt == qt);
#pragma unroll
            for (int nt = 0; nt < 2; nt++) {
                int colbase = wn * 16 + nt * 8 + 2 * tg;
#pragma unroll
                for (int e = 0; e < 4; e++) {
                    int j = colbase + (e & 1);
                    int row = (e < 2) ? rA : rB;
                    int o = j - row + 63;
                    float bd = Bs[(bufLow ^ (o >> 6)) * (64 * 68) + row * 68 + (o & 63)];
                    float s = (cS[nt][e] + bd) * scale;
                    if (diag && j > row) s = -INFINITY;
                    sv[nt][e] = s;
                    if (e < 2) mAl = fmaxf(mAl, s); else mBl = fmaxf(mBl, s);
                }
            }
            mAl = fmaxf(mAl, __shfl_xor_sync(0xffffffffu, mAl, 1));
            mAl = fmaxf(mAl, __shfl_xor_sync(0xffffffffu, mAl, 2));
            mBl = fmaxf(mBl, __shfl_xor_sync(0xffffffffu, mBl, 1));
            mBl = fmaxf(mBl, __shfl_xor_sync(0xffffffffu, mBl, 2));
            mAl = fmaxf(mAl, -1e30f);
            mBl = fmaxf(mBl, -1e30f);

            float sumA = 0.0f, sumB = 0.0f;
#pragma unroll
            for (int nt = 0; nt < 2; nt++) {
                int colbase = wn * 16 + nt * 8 + 2 * tg;
                float e0 = __expf(sv[nt][0] - mAl);
                float e1 = __expf(sv[nt][1] - mAl);
                float e2 = __expf(sv[nt][2] - mBl);
                float e3 = __expf(sv[nt][3] - mBl);
                sumA += e0 + e1; sumB += e2 + e3;
                *(float2*)&Sc[rA * 68 + colbase] = make_float2(e0, e1);
                *(float2*)&Sc[rB * 68 + colbase] = make_float2(e2, e3);
            }
            sumA += __shfl_xor_sync(0xffffffffu, sumA, 1);
            sumA += __shfl_xor_sync(0xffffffffu, sumA, 2);
            sumB += __shfl_xor_sync(0xffffffffu, sumB, 1);
            sumB += __shfl_xor_sync(0xffffffffu, sumB, 2);
            if (tg == 0) {
                sPM[wn * 64 + rA] = mAl; sPM[wn * 64 + rB] = mBl;
                sPS[wn * 64 + rA] = sumA; sPS[wn * 64 + rB] = sumB;
            }
            __syncthreads();   // S3b: P + partials visible

            // ---- combine partials (register-resident m/l) ----
            float fA[4], fB[4];
            {
                float m0 = sPM[rA], m1 = sPM[64 + rA], m2 = sPM[128 + rA], m3 = sPM[192 + rA];
                float mg = fmaxf(fmaxf(mA_run, fmaxf(m0, m1)), fmaxf(m2, m3));
                float corr = __expf(mA_run - mg);
                fA[0] = __expf(m0 - mg); fA[1] = __expf(m1 - mg);
                fA[2] = __expf(m2 - mg); fA[3] = __expf(m3 - mg);
                lA_run = lA_run * corr
                       + sPS[rA] * fA[0] + sPS[64 + rA] * fA[1]
                       + sPS[128 + rA] * fA[2] + sPS[192 + rA] * fA[3];
                mA_run = mg;
#pragma unroll
                for (int nt = 0; nt < 2; nt++) { O[nt][0] *= corr; O[nt][1] *= corr; }
            }
            {
                float m0 = sPM[rB], m1 = sPM[64 + rB], m2 = sPM[128 + rB], m3 = sPM[192 + rB];
                float mg = fmaxf(fmaxf(mB_run, fmaxf(m0, m1)), fmaxf(m2, m3));
                float corr = __expf(mB_run - mg);
                fB[0] = __expf(m0 - mg); fB[1] = __expf(m1 - mg);
                fB[2] = __expf(m2 - mg); fB[3] = __expf(m3 - mg);
                lB_run = lB_run * corr
                       + sPS[rB] * fB[0] + sPS[64 + rB] * fB[1]
                       + sPS[128 + rB] * fB[2] + sPS[192 + rB] * fB[3];
                mB_run = mg;
#pragma unroll
                for (int nt = 0; nt < 2; nt++) { O[nt][2] *= corr; O[nt][3] *= corr; }
            }

            // ---- O += (f .* P) @ V ----
#pragma unroll
            for (int k0 = 0; k0 < 64; k0 += 8) {
                const int w = k0 >> 4;
                unsigned a0 = f2tf(Sc[rA * 68 + k0 + tg]     * fA[w]);
                unsigned a1 = f2tf(Sc[rB * 68 + k0 + tg]     * fB[w]);
                unsigned a2 = f2tf(Sc[rA * 68 + k0 + tg + 4] * fA[w]);
                unsigned a3 = f2tf(Sc[rB * 68 + k0 + tg + 4] * fB[w]);
#pragma unroll
                for (int nt = 0; nt < 2; nt++) {
                    int n0 = wn * 16 + nt * 8;
                    unsigned b0 = ldb(&Vs[(k0 + tg) * 72 + n0 + g]);
                    unsigned b1 = ldb(&Vs[(k0 + tg + 4) * 72 + n0 + g]);
                    mma_tf32(O[nt], a0, a1, a2, a3, b0, b1);
                }
            }
        }

        // ---- epilogue (m/l in registers, quad-uniform) ----
        float invA = 1.0f / lA_run;
        float invB = 1.0f / lB_run;
        float* op = out + ((size_t)(n * Hh + h) * Ss + i0) * DHh;
#pragma unroll
        for (int nt = 0; nt < 2; nt++) {
            int n0 = wn * 16 + nt * 8;
            *(float2*)&op[(size_t)rA * DHh + n0 + 2 * tg] =
                make_float2(O[nt][0] * invA, O[nt][1] * invA);
            *(float2*)&op[(size_t)rB * DHh + n0 + 2 * tg] =
                make_float2(O[nt][2] * invB, O[nt][3] * invB);
        }
    }
}

// ---------------------------------------------------------------------------
extern "C" void kernel_launch(void* const* d_in, const int* in_sizes, int n_in,
                              void* d_out, int out_size) {
    const float* seqs   = (const float*)d_in[0];
    const float* keys   = (const float*)d_in[1];
    const float* values = (const float*)d_in[2];
    const float* u_bias = (const float*)d_in[3];
    const float* v_bias = (const float*)d_in[4];
    const float* rproj  = (const float*)d_in[5];
    (void)in_sizes; (void)n_in; (void)out_size;

    const int smem_bytes = STOT * sizeof(float);   // ~122 KB
    cudaFuncSetAttribute(attn_kernel, cudaFuncAttributeMaxDynamicSharedMemorySize,
                         smem_bytes);

    enc_rot_kernel<<<64, 256>>>();
    rproj_mma_kernel<<<dim3(32, 8), 256>>>(rproj, u_bias, v_bias);
    attn_kernel<<<dim3(8, 16), 512, smem_bytes>>>(seqs, keys, values,
                                                  u_bias, (float*)d_out);
}

// round 8
// speedup vs baseline: 1.2687x; 1.0697x over previous
#include <cuda_runtime.h>
#include <math.h>

#define Nn 2
#define Hh 8
#define Ss 1024
#define DHh 64
#define Dd 512
#define Pp 2047   // 2S-1
#define TPAD 2048 // padded head stride for g_T

__device__ float g_ENC[Pp * Dd];
__device__ float g_R[Hh * Pp * DHh];
__device__ float g_T[Hh * TPAD];

__device__ __forceinline__ unsigned f2tf(float x) {
    unsigned r;
    asm("cvt.rna.tf32.f32 %0, %1;" : "=r"(r) : "f"(x));
    return r;
}
__device__ __forceinline__ float tf32f(float x) { return __uint_as_float(f2tf(x)); }
__device__ __forceinline__ void mma_tf32(float c[4], unsigned a0, unsigned a1,
                                         unsigned a2, unsigned a3,
                                         unsigned b0, unsigned b1) {
    asm volatile(
        "mma.sync.aligned.m16n8k8.row.col.f32.tf32.tf32.f32 "
        "{%0,%1,%2,%3},{%4,%5,%6,%7},{%8,%9},{%0,%1,%2,%3};"
        : "+f"(c[0]), "+f"(c[1]), "+f"(c[2]), "+f"(c[3])
        : "r"(a0), "r"(a1), "r"(a2), "r"(a3), "r"(b0), "r"(b1));
}
__device__ __forceinline__ unsigned ldb(const float* p) { return __float_as_uint(*p); }

// ---------------------------------------------------------------------------
// Kernel 0: positional encodings by incremental rotation.
// ---------------------------------------------------------------------------
__global__ void __launch_bounds__(256) enc_rot_kernel() {
    int i = threadIdx.x;
    int p0 = blockIdx.x * 32;
    int steps = Pp - p0; if (steps > 32) steps = 32;
    const float coef = -9.210340371976184f / 512.0f;
    float invf = __expf((float)(2 * i) * coef);
    float s, c;
    sincosf((float)(1023 - p0) * invf, &s, &c);
    float rs, rc;
    sincosf(invf, &rs, &rc);
    for (int t = 0; t < steps; t++) {
        *(float2*)&g_ENC[(size_t)(p0 + t) * Dd + 2 * i] = make_float2(s, c);
        float s2 = s * rc - c * rs;
        float c2 = c * rc + s * rs;
        s = s2; c = c2;
    }
}

// ---------------------------------------------------------------------------
// Kernel 1: r-projection (tf32 mma) + per-head rank-1 vector g_T.
// ---------------------------------------------------------------------------
__global__ void __launch_bounds__(256) rproj_mma_kernel(
    const float* __restrict__ W, const float* __restrict__ u_bias,
    const float* __restrict__ v_bias)
{
    __shared__ float As[64 * 36];
    __shared__ float Bsm[64 * 36];
    __shared__ float scr[2 * 64];

    int tid = threadIdx.x;
    int warp = tid >> 5, lane = tid & 31;
    int g = lane >> 2, tg = lane & 3;
    int wm = (warp & 3) * 16;
    int wn = warp >> 2;

    int p0 = blockIdx.x * 64;
    int h = blockIdx.y;
    int c0 = h * 64;

    float acc[4][4] = {};

    for (int j0 = 0; j0 < Dd; j0 += 32) {
        __syncthreads();
#pragma unroll
        for (int r = 0; r < 2; r++) {
            int q = tid + r * 256;
            int row = q >> 3, qq = q & 7;
            int p = p0 + row;
            float4 e = make_float4(0.f, 0.f, 0.f, 0.f);
            if (p < Pp) e = *(const float4*)&g_ENC[(size_t)p * Dd + j0 + 4 * qq];
            float4 o; o.x = tf32f(e.x); o.y = tf32f(e.y); o.z = tf32f(e.z); o.w = tf32f(e.w);
            *(float4*)&As[row * 36 + 4 * qq] = o;
        }
#pragma unroll
        for (int r = 0; r < 2; r++) {
            int q2 = tid + r * 256;
            int row = q2 >> 3, qq = q2 & 7;
            float4 w = *(const float4*)&W[(size_t)(c0 + row) * Dd + j0 + 4 * qq];
            float4 o; o.x = tf32f(w.x); o.y = tf32f(w.y); o.z = tf32f(w.z); o.w = tf32f(w.w);
            *(float4*)&Bsm[row * 36 + 4 * qq] = o;
        }
        __syncthreads();
#pragma unroll
        for (int k0 = 0; k0 < 32; k0 += 8) {
            unsigned a0 = ldb(&As[(wm + g) * 36 + k0 + tg]);
            unsigned a1 = ldb(&As[(wm + g + 8) * 36 + k0 + tg]);
            unsigned a2 = ldb(&As[(wm + g) * 36 + k0 + tg + 4]);
            unsigned a3 = ldb(&As[(wm + g + 8) * 36 + k0 + tg + 4]);
#pragma unroll
            for (int nt = 0; nt < 4; nt++) {
                int n0 = wn * 32 + nt * 8;
                unsigned b0 = ldb(&Bsm[(n0 + g) * 36 + k0 + tg]);
                unsigned b1 = ldb(&Bsm[(n0 + g) * 36 + k0 + tg + 4]);
                mma_tf32(acc[nt], a0, a1, a2, a3, b0, b1);
            }
        }
    }
    int pA = p0 + wm + g, pB = pA + 8;
    float* Rh = g_R + (size_t)h * (Pp * DHh);
#pragma unroll
    for (int nt = 0; nt < 4; nt++) {
        int n0 = wn * 32 + nt * 8;
        if (pA < Pp)
            *(float2*)&Rh[(size_t)pA * DHh + n0 + 2 * tg] = make_float2(acc[nt][0], acc[nt][1]);
        if (pB < Pp)
            *(float2*)&Rh[(size_t)pB * DHh + n0 + 2 * tg] = make_float2(acc[nt][2], acc[nt][3]);
    }

    // g_T[h][p] = (v_bias - u_bias) . R[h][p][:]
    float localA = 0.0f, localB = 0.0f;
#pragma unroll
    for (int nt = 0; nt < 4; nt++) {
        int n0 = wn * 32 + nt * 8;
        float2 u2 = *(const float2*)&u_bias[h * DHh + n0 + 2 * tg];
        float2 v2 = *(const float2*)&v_bias[h * DHh + n0 + 2 * tg];
        float db0 = v2.x - u2.x, db1 = v2.y - u2.y;
        localA += acc[nt][0] * db0 + acc[nt][1] * db1;
        localB += acc[nt][2] * db0 + acc[nt][3] * db1;
    }
    localA += __shfl_xor_sync(0xffffffffu, localA, 1);
    localA += __shfl_xor_sync(0xffffffffu, localA, 2);
    localB += __shfl_xor_sync(0xffffffffu, localB, 1);
    localB += __shfl_xor_sync(0xffffffffu, localB, 2);
    if (tg == 0) {
        scr[wn * 64 + wm + g] = localA;
        scr[wn * 64 + wm + g + 8] = localB;
    }
    __syncthreads();
    if (tid < 64 && p0 + tid < Pp)
        g_T[h * TPAD + p0 + tid] = scr[tid] + scr[64 + tid];
}

// ---------------------------------------------------------------------------
// Kernel 2: fused causal flash attention, k-split PV with warp-local softmax.
// 512 threads, grid (8,16), paired qtiles {15-bx, bx}. 3 barriers/iter,
// P never leaves registers; split-k merge once per phase.
// ---------------------------------------------------------------------------
#define SQU 0
#define SKS (SQU + 64*68)
#define SVS (SKS + 64*68)          // [64][72]
#define SRS (SVS + 64*72)          // ring 2 x [64][68]
#define SBS (SRS + 2*64*68)        // BD ring 2 x [64][68] (tvec folded)
#define STOT (SBS + 2*64*68)       // 26112 floats (~102 KB)
// epilogue overlay (after final barrier): Xo [4][64][68], mArr/lArr [4][64]
#define EPX 0
#define EPM (EPX + 4*64*68)
#define EPL (EPM + 256)

__global__ void __launch_bounds__(512) attn_kernel(
    const float* __restrict__ seqs, const float* __restrict__ keys,
    const float* __restrict__ values, const float* __restrict__ u_bias,
    float* __restrict__ out)
{
    extern __shared__ float sm[];
    float* Qu = sm + SQU;
    float* Ks = sm + SKS;
    float* Vs = sm + SVS;
    float* Rs = sm + SRS;
    float* Bs = sm + SBS;

    int tid = threadIdx.x;
    int lane = tid & 31;
    int warp = tid >> 5;
    int g = lane >> 2, tg = lane & 3;
    int wm = (warp & 3) * 16;
    int wn = warp >> 2;             // 0..3: this warp's 16-col k-slice
    int rA = wm + g, rB = wm + g + 8;

    int bx = blockIdx.x;
    int head = blockIdx.y;
    int n = head >> 3, h = head & 7;

    const float* sq = seqs   + ((size_t)(n * Hh + h) * Ss) * DHh;
    const float* kq = keys   + ((size_t)(n * Hh + h) * Ss) * DHh;
    const float* vq = values + ((size_t)(n * Hh + h) * Ss) * DHh;
    const float* Rh = g_R + (size_t)h * (Pp * DHh);
    const float* Th = g_T + (size_t)h * TPAD;

    int lrow = tid >> 4;            // 0..31
    int lq4  = tid & 15;

    float4 ub4 = *(const float4*)&u_bias[h * DHh + lq4 * 4];
    const float scale = 0.125f;

    for (int ph = 0; ph < 2; ph++) {
        int qt = (ph == 0) ? (15 - bx) : bx;
        int i0 = qt * 64;

        __syncthreads();   // previous phase (incl. its epilogue reads) done
#pragma unroll
        for (int r = 0; r < 2; r++) {
            int row = lrow + r * 32;
            float4 s4 = *(const float4*)&sq[(size_t)(i0 + row) * DHh + lq4 * 4];
            Qu[row * 68 + lq4 * 4 + 0] = tf32f(s4.x + ub4.x);
            Qu[row * 68 + lq4 * 4 + 1] = tf32f(s4.y + ub4.y);
            Qu[row * 68 + lq4 * 4 + 2] = tf32f(s4.z + ub4.z);
            Qu[row * 68 + lq4 * 4 + 3] = tf32f(s4.w + ub4.w);
        }

        // warp-local softmax state + k-split partial O over all 64 out dims
        float mA_run = -1e30f, mB_run = -1e30f;
        float lA_run = 0.0f, lB_run = 0.0f;
        float O[8][4];
#pragma unroll
        for (int a = 0; a < 8; a++)
#pragma unroll
            for (int b = 0; b < 4; b++) O[a][b] = 0.0f;

        for (int kt = 0; kt <= qt; kt++) {
            int j0 = kt * 64;
            int pbase = (Ss - 1) - i0 + j0 - 63;
            int bufLow = kt & 1, bufHigh = bufLow ^ 1;

            if (kt > 0) __syncthreads();   // S1: prev-iter consumers done

            // stage K, V
#pragma unroll
            for (int r = 0; r < 2; r++) {
                int row = lrow + r * 32;
                float4 k4 = *(const float4*)&kq[(size_t)(j0 + row) * DHh + lq4 * 4];
                float4 v4 = *(const float4*)&vq[(size_t)(j0 + row) * DHh + lq4 * 4];
                Ks[row * 68 + lq4 * 4 + 0] = tf32f(k4.x);
                Ks[row * 68 + lq4 * 4 + 1] = tf32f(k4.y);
                Ks[row * 68 + lq4 * 4 + 2] = tf32f(k4.z);
                Ks[row * 68 + lq4 * 4 + 3] = tf32f(k4.w);
                Vs[row * 72 + lq4 * 4 + 0] = tf32f(v4.x);
                Vs[row * 72 + lq4 * 4 + 1] = tf32f(v4.y);
                Vs[row * 72 + lq4 * 4 + 2] = tf32f(v4.z);
                Vs[row * 72 + lq4 * 4 + 3] = tf32f(v4.w);
            }
            // stage R band
            if (kt == 0) {
#pragma unroll
                for (int r = 0; r < 4; r++) {
                    int row = lrow + r * 32;   // 0..127 contiguous over ring
                    float4 r4 = *(const float4*)&Rh[(size_t)(pbase + row) * DHh + lq4 * 4];
                    Rs[row * 68 + lq4 * 4 + 0] = tf32f(r4.x);
                    Rs[row * 68 + lq4 * 4 + 1] = tf32f(r4.y);
                    Rs[row * 68 + lq4 * 4 + 2] = tf32f(r4.z);
                    Rs[row * 68 + lq4 * 4 + 3] = tf32f(r4.w);
                }
            } else {
                float* Rd = Rs + bufHigh * (64 * 68);
#pragma unroll
                for (int r = 0; r < 2; r++) {
                    int row = lrow + r * 32;
                    float4 r4 = *(const float4*)&Rh[(size_t)(pbase + 64 + row) * DHh + lq4 * 4];
                    Rd[row * 68 + lq4 * 4 + 0] = tf32f(r4.x);
                    Rd[row * 68 + lq4 * 4 + 1] = tf32f(r4.y);
                    Rd[row * 68 + lq4 * 4 + 2] = tf32f(r4.z);
                    Rd[row * 68 + lq4 * 4 + 3] = tf32f(r4.w);
                }
            }
            // tvec for Bs store
            float2 tv[4];
            if (kt == 0) {
#pragma unroll
                for (int nt = 0; nt < 4; nt++)
                    tv[nt] = *(const float2*)&Th[pbase + wn * 32 + nt * 8 + 2 * tg];
            } else {
#pragma unroll
                for (int nt = 0; nt < 2; nt++)
                    tv[nt] = *(const float2*)&Th[pbase + 64 + wn * 16 + nt * 8 + 2 * tg];
            }
            __syncthreads();   // S2: tiles ready

            // ---- merged AC + BD (shared A-fragments) ----
            float cS[2][4];
#pragma unroll
            for (int t = 0; t < 2; t++)
#pragma unroll
                for (int e = 0; e < 4; e++) cS[t][e] = 0.0f;

            if (kt == 0) {
                float cB[4][4];
#pragma unroll
                for (int t = 0; t < 4; t++)
#pragma unroll
                    for (int e = 0; e < 4; e++) cB[t][e] = 0.0f;
#pragma unroll
                for (int k0 = 0; k0 < 64; k0 += 8) {
                    unsigned a0 = ldb(&Qu[rA * 68 + k0 + tg]);
                    unsigned a1 = ldb(&Qu[rB * 68 + k0 + tg]);
                    unsigned a2 = ldb(&Qu[rA * 68 + k0 + tg + 4]);
                    unsigned a3 = ldb(&Qu[rB * 68 + k0 + tg + 4]);
#pragma unroll
                    for (int nt = 0; nt < 2; nt++) {
                        int n0 = wn * 16 + nt * 8;
                        unsigned b0 = ldb(&Ks[(n0 + g) * 68 + k0 + tg]);
                        unsigned b1 = ldb(&Ks[(n0 + g) * 68 + k0 + tg + 4]);
                        mma_tf32(cS[nt], a0, a1, a2, a3, b0, b1);
                    }
#pragma unroll
                    for (int nt = 0; nt < 4; nt++) {
                        int o0 = wn * 32 + nt * 8;
                        unsigned b0 = ldb(&Rs[(o0 + g) * 68 + k0 + tg]);
                        unsigned b1 = ldb(&Rs[(o0 + g) * 68 + k0 + tg + 4]);
                        mma_tf32(cB[nt], a0, a1, a2, a3, b0, b1);
                    }
                }
#pragma unroll
                for (int nt = 0; nt < 4; nt++) {
                    int o0 = wn * 32 + nt * 8;
                    float* Bd = Bs + (o0 >> 6) * (64 * 68) + (o0 & 63) + 2 * tg;
                    *(float2*)&Bd[rA * 68] = make_float2(cB[nt][0] + tv[nt].x, cB[nt][1] + tv[nt].y);
                    *(float2*)&Bd[rB * 68] = make_float2(cB[nt][2] + tv[nt].x, cB[nt][3] + tv[nt].y);
                }
            } else {
                float cB[2][4];
#pragma unroll
                for (int t = 0; t < 2; t++)
#pragma unroll
                    for (int e = 0; e < 4; e++) cB[t][e] = 0.0f;
                const float* Rb = Rs + bufHigh * (64 * 68);
#pragma unroll
                for (int k0 = 0; k0 < 64; k0 += 8) {
                    unsigned a0 = ldb(&Qu[rA * 68 + k0 + tg]);
                    unsigned a1 = ldb(&Qu[rB * 68 + k0 + tg]);
                    unsigned a2 = ldb(&Qu[rA * 68 + k0 + tg + 4]);
                    unsigned a3 = ldb(&Qu[rB * 68 + k0 + tg + 4]);
#pragma unroll
                    for (int nt = 0; nt < 2; nt++) {
                        int n0 = wn * 16 + nt * 8;
                        unsigned b0 = ldb(&Ks[(n0 + g) * 68 + k0 + tg]);
                        unsigned b1 = ldb(&Ks[(n0 + g) * 68 + k0 + tg + 4]);
                        mma_tf32(cS[nt], a0, a1, a2, a3, b0, b1);
                    }
#pragma unroll
                    for (int nt = 0; nt < 2; nt++) {
                        int r0 = wn * 16 + nt * 8;
                        unsigned b0 = ldb(&Rb[(r0 + g) * 68 + k0 + tg]);
                        unsigned b1 = ldb(&Rb[(r0 + g) * 68 + k0 + tg + 4]);
                        mma_tf32(cB[nt], a0, a1, a2, a3, b0, b1);
                    }
                }
                float* Bd0 = Bs + bufHigh * (64 * 68);
#pragma unroll
                for (int nt = 0; nt < 2; nt++) {
                    int r0 = wn * 16 + nt * 8;
                    float* Bd = Bd0 + r0 + 2 * tg;
                    *(float2*)&Bd[rA * 68] = make_float2(cB[nt][0] + tv[nt].x, cB[nt][1] + tv[nt].y);
                    *(float2*)&Bd[rB * 68] = make_float2(cB[nt][2] + tv[nt].x, cB[nt][3] + tv[nt].y);
                }
            }
            __syncthreads();   // S3: Bs visible (last barrier this iter)

            // ---- scores + WARP-LOCAL online softmax (no cross-warp traffic) ----
            float sv[2][4];
            float mAl = -INFINITY, mBl = -INFINITY;
            int diag = (kt == qt);
#pragma unroll
            for (int nt = 0; nt < 2; nt++) {
                int colbase = wn * 16 + nt * 8 + 2 * tg;
#pragma unroll
                for (int e = 0; e < 4; e++) {
                    int j = colbase + (e & 1);
                    int row = (e < 2) ? rA : rB;
                    int o = j - row + 63;
                    float bd = Bs[(bufLow ^ (o >> 6)) * (64 * 68) + row * 68 + (o & 63)];
                    float s = (cS[nt][e] + bd) * scale;
                    if (diag && j > row) s = -INFINITY;
                    sv[nt][e] = s;
                    if (e < 2) mAl = fmaxf(mAl, s); else mBl = fmaxf(mBl, s);
                }
            }
            mAl = fmaxf(mAl, __shfl_xor_sync(0xffffffffu, mAl, 1));
            mAl = fmaxf(mAl, __shfl_xor_sync(0xffffffffu, mAl, 2));
            mBl = fmaxf(mBl, __shfl_xor_sync(0xffffffffu, mBl, 1));
            mBl = fmaxf(mBl, __shfl_xor_sync(0xffffffffu, mBl, 2));

            float mgA = fmaxf(mA_run, mAl);
            float mgB = fmaxf(mB_run, mBl);
            float corrA = __expf(mA_run - mgA);
            float corrB = __expf(mB_run - mgB);

            float peA0[2], peA1[2], peB0[2], peB1[2];
            float sumA = 0.0f, sumB = 0.0f;
#pragma unroll
            for (int nt = 0; nt < 2; nt++) {
                peA0[nt] = __expf(sv[nt][0] - mgA);
                peA1[nt] = __expf(sv[nt][1] - mgA);
                peB0[nt] = __expf(sv[nt][2] - mgB);
                peB1[nt] = __expf(sv[nt][3] - mgB);
                sumA += peA0[nt] + peA1[nt];
                sumB += peB0[nt] + peB1[nt];
            }
            sumA += __shfl_xor_sync(0xffffffffu, sumA, 1);
            sumA += __shfl_xor_sync(0xffffffffu, sumA, 2);
            sumB += __shfl_xor_sync(0xffffffffu, sumB, 1);
            sumB += __shfl_xor_sync(0xffffffffu, sumB, 2);
            lA_run = lA_run * corrA + sumA;
            lB_run = lB_run * corrB + sumB;
            mA_run = mgA; mB_run = mgB;

            // rescale partial O
#pragma unroll
            for (int jn = 0; jn < 8; jn++) {
                O[jn][0] *= corrA; O[jn][1] *= corrA;
                O[jn][2] *= corrB; O[jn][3] *= corrB;
            }

            // ---- k-split PV: A-frags from registers via quad shfl ----
#pragma unroll
            for (int nt = 0; nt < 2; nt++) {
                int kbase = wn * 16 + nt * 8;
                int src1 = tg >> 1;          // col tg
                int src2 = (tg >> 1) + 2;    // col tg+4
                float lo, hi;
                lo = __shfl_sync(0xffffffffu, peA0[nt], src1, 4);
                hi = __shfl_sync(0xffffffffu, peA1[nt], src1, 4);
                float a0f = (tg & 1) ? hi : lo;
                lo = __shfl_sync(0xffffffffu, peA0[nt], src2, 4);
                hi = __shfl_sync(0xffffffffu, peA1[nt], src2, 4);
                float a2f = (tg & 1) ? hi : lo;
                lo = __shfl_sync(0xffffffffu, peB0[nt], src1, 4);
                hi = __shfl_sync(0xffffffffu, peB1[nt], src1, 4);
                float a1f = (tg & 1) ? hi : lo;
                lo = __shfl_sync(0xffffffffu, peB0[nt], src2, 4);
                hi = __shfl_sync(0xffffffffu, peB1[nt], src2, 4);
                float a3f = (tg & 1) ? hi : lo;
                unsigned a0 = f2tf(a0f), a1 = f2tf(a1f);
                unsigned a2 = f2tf(a2f), a3 = f2tf(a3f);
#pragma unroll
                for (int jn = 0; jn < 8; jn++) {
                    int n0 = jn * 8;
                    unsigned b0 = ldb(&Vs[(kbase + tg) * 72 + n0 + g]);
                    unsigned b1 = ldb(&Vs[(kbase + tg + 4) * 72 + n0 + g]);
                    mma_tf32(O[jn], a0, a1, a2, a3, b0, b1);
                }
            }
        }

        // ---- split-k merge across the 4 warps of each m-slice ----
        __syncthreads();   // all PV reads of Vs done; tiles dead, overlay OK
        {
            float* Xo = sm + EPX;          // [4][64][68]
            float* mArr = sm + EPM;        // [4][64]
            float* lArr = sm + EPL;        // [4][64]
#pragma unroll
            for (int jn = 0; jn < 8; jn++) {
                int n0 = jn * 8;
                *(float2*)&Xo[wn * 4352 + rA * 68 + n0 + 2 * tg] =
                    make_float2(O[jn][0], O[jn][1]);
                *(float2*)&Xo[wn * 4352 + rB * 68 + n0 + 2 * tg] =
                    make_float2(O[jn][2], O[jn][3]);
            }
            if (tg == 0) {
                mArr[wn * 64 + rA] = mA_run; lArr[wn * 64 + rA] = lA_run;
                mArr[wn * 64 + rB] = mB_run; lArr[wn * 64 + rB] = lB_run;
            }
            __syncthreads();

            int row = tid >> 3, cb = (tid & 7) * 8;
            float m0 = mArr[row], m1 = mArr[64 + row];
            float m2 = mArr[128 + row], m3 = mArr[192 + row];
            float mg = fmaxf(fmaxf(m0, m1), fmaxf(m2, m3));
            float f0 = __expf(m0 - mg), f1 = __expf(m1 - mg);
            float f2 = __expf(m2 - mg), f3 = __expf(m3 - mg);
            float lg = lArr[row] * f0 + lArr[64 + row] * f1
                     + lArr[128 + row] * f2 + lArr[192 + row] * f3;
            float inv = 1.0f / lg;
            float* op = out + ((size_t)(n * Hh + h) * Ss + i0 + row) * DHh + cb;
#pragma unroll
            for (int c = 0; c < 8; c += 4) {
                float4 x0 = *(const float4*)&Xo[0 * 4352 + row * 68 + cb + c];
                float4 x1 = *(const float4*)&Xo[1 * 4352 + row * 68 + cb + c];
                float4 x2 = *(const float4*)&Xo[2 * 4352 + row * 68 + cb + c];
                float4 x3 = *(const float4*)&Xo[3 * 4352 + row * 68 + cb + c];
                float4 o4;
                o4.x = (x0.x * f0 + x1.x * f1 + x2.x * f2 + x3.x * f3) * inv;
                o4.y = (x0.y * f0 + x1.y * f1 + x2.y * f2 + x3.y * f3) * inv;
                o4.z = (x0.z * f0 + x1.z * f1 + x2.z * f2 + x3.z * f3) * inv;
                o4.w = (x0.w * f0 + x1.w * f1 + x2.w * f2 + x3.w * f3) * inv;
                *(float4*)&op[c] = o4;
            }
        }
    }
}

// ---------------------------------------------------------------------------
extern "C" void kernel_launch(void* const* d_in, const int* in_sizes, int n_in,
                              void* d_out, int out_size) {
    const float* seqs   = (const float*)d_in[0];
    const float* keys   = (const float*)d_in[1];
    const float* values = (const float*)d_in[2];
    const float* u_bias = (const float*)d_in[3];
    const float* v_bias = (const float*)d_in[4];
    const float* rproj  = (const float*)d_in[5];
    (void)in_sizes; (void)n_in; (void)out_size;

    const int smem_bytes = STOT * sizeof(float);   // ~102 KB
    cudaFuncSetAttribute(attn_kernel, cudaFuncAttributeMaxDynamicSharedMemorySize,
                         smem_bytes);

    enc_rot_kernel<<<64, 256>>>();
    rproj_mma_kernel<<<dim3(32, 8), 256>>>(rproj, u_bias, v_bias);
    attn_kernel<<<dim3(8, 16), 512, smem_bytes>>>(seqs, keys, values,
                                                  u_bias, (float*)d_out);
}

// round 9
// speedup vs baseline: 1.4023x; 1.1053x over previous
#include <cuda_runtime.h>
#include <math.h>

#define Nn 2
#define Hh 8
#define Ss 1024
#define DHh 64
#define Dd 512
#define Pp 2047   // 2S-1
#define TPAD 2048 // padded head stride for g_T

__device__ float g_ENC[Pp * Dd];
__device__ float g_R[Hh * Pp * DHh];
__device__ float g_T[Hh * TPAD];

__device__ __forceinline__ unsigned f2tf(float x) {
    unsigned r;
    asm("cvt.rna.tf32.f32 %0, %1;" : "=r"(r) : "f"(x));
    return r;
}
__device__ __forceinline__ float tf32f(float x) { return __uint_as_float(f2tf(x)); }
__device__ __forceinline__ void mma_tf32(float c[4], unsigned a0, unsigned a1,
                                         unsigned a2, unsigned a3,
                                         unsigned b0, unsigned b1) {
    asm volatile(
        "mma.sync.aligned.m16n8k8.row.col.f32.tf32.tf32.f32 "
        "{%0,%1,%2,%3},{%4,%5,%6,%7},{%8,%9},{%0,%1,%2,%3};"
        : "+f"(c[0]), "+f"(c[1]), "+f"(c[2]), "+f"(c[3])
        : "r"(a0), "r"(a1), "r"(a2), "r"(a3), "r"(b0), "r"(b1));
}
__device__ __forceinline__ unsigned ldb(const float* p) { return __float_as_uint(*p); }
__device__ __forceinline__ void cpa16(unsigned dst, const float* src) {
    asm volatile("cp.async.cg.shared.global [%0], [%1], 16;" :: "r"(dst), "l"(src));
}
#define CP_COMMIT() asm volatile("cp.async.commit_group;")
#define CP_WAIT0()  asm volatile("cp.async.wait_group 0;")

// ---------------------------------------------------------------------------
// Kernel 0: positional encodings by incremental rotation.
// ---------------------------------------------------------------------------
__global__ void __launch_bounds__(256) enc_rot_kernel() {
    int i = threadIdx.x;
    int p0 = blockIdx.x * 32;
    int steps = Pp - p0; if (steps > 32) steps = 32;
    const float coef = -9.210340371976184f / 512.0f;
    float invf = __expf((float)(2 * i) * coef);
    float s, c;
    sincosf((float)(1023 - p0) * invf, &s, &c);
    float rs, rc;
    sincosf(invf, &rs, &rc);
    for (int t = 0; t < steps; t++) {
        *(float2*)&g_ENC[(size_t)(p0 + t) * Dd + 2 * i] = make_float2(s, c);
        float s2 = s * rc - c * rs;
        float c2 = c * rc + s * rs;
        s = s2; c = c2;
    }
}

// ---------------------------------------------------------------------------
// Kernel 1: r-projection (tf32 mma) + per-head rank-1 vector g_T.
// ---------------------------------------------------------------------------
__global__ void __launch_bounds__(256) rproj_mma_kernel(
    const float* __restrict__ W, const float* __restrict__ u_bias,
    const float* __restrict__ v_bias)
{
    __shared__ float As[64 * 36];
    __shared__ float Bsm[64 * 36];
    __shared__ float scr[2 * 64];

    int tid = threadIdx.x;
    int warp = tid >> 5, lane = tid & 31;
    int g = lane >> 2, tg = lane & 3;
    int wm = (warp & 3) * 16;
    int wn = warp >> 2;

    int p0 = blockIdx.x * 64;
    int h = blockIdx.y;
    int c0 = h * 64;

    float acc[4][4] = {};

    for (int j0 = 0; j0 < Dd; j0 += 32) {
        __syncthreads();
#pragma unroll
        for (int r = 0; r < 2; r++) {
            int q = tid + r * 256;
            int row = q >> 3, qq = q & 7;
            int p = p0 + row;
            float4 e = make_float4(0.f, 0.f, 0.f, 0.f);
            if (p < Pp) e = *(const float4*)&g_ENC[(size_t)p * Dd + j0 + 4 * qq];
            float4 o; o.x = tf32f(e.x); o.y = tf32f(e.y); o.z = tf32f(e.z); o.w = tf32f(e.w);
            *(float4*)&As[row * 36 + 4 * qq] = o;
        }
#pragma unroll
        for (int r = 0; r < 2; r++) {
            int q2 = tid + r * 256;
            int row = q2 >> 3, qq = q2 & 7;
            float4 w = *(const float4*)&W[(size_t)(c0 + row) * Dd + j0 + 4 * qq];
            float4 o; o.x = tf32f(w.x); o.y = tf32f(w.y); o.z = tf32f(w.z); o.w = tf32f(w.w);
            *(float4*)&Bsm[row * 36 + 4 * qq] = o;
        }
        __syncthreads();
#pragma unroll
        for (int k0 = 0; k0 < 32; k0 += 8) {
            unsigned a0 = ldb(&As[(wm + g) * 36 + k0 + tg]);
            unsigned a1 = ldb(&As[(wm + g + 8) * 36 + k0 + tg]);
            unsigned a2 = ldb(&As[(wm + g) * 36 + k0 + tg + 4]);
            unsigned a3 = ldb(&As[(wm + g + 8) * 36 + k0 + tg + 4]);
#pragma unroll
            for (int nt = 0; nt < 4; nt++) {
                int n0 = wn * 32 + nt * 8;
                unsigned b0 = ldb(&Bsm[(n0 + g) * 36 + k0 + tg]);
                unsigned b1 = ldb(&Bsm[(n0 + g) * 36 + k0 + tg + 4]);
                mma_tf32(acc[nt], a0, a1, a2, a3, b0, b1);
            }
        }
    }
    int pA = p0 + wm + g, pB = pA + 8;
    float* Rh = g_R + (size_t)h * (Pp * DHh);
#pragma unroll
    for (int nt = 0; nt < 4; nt++) {
        int n0 = wn * 32 + nt * 8;
        if (pA < Pp)
            *(float2*)&Rh[(size_t)pA * DHh + n0 + 2 * tg] = make_float2(acc[nt][0], acc[nt][1]);
        if (pB < Pp)
            *(float2*)&Rh[(size_t)pB * DHh + n0 + 2 * tg] = make_float2(acc[nt][2], acc[nt][3]);
    }

    // g_T[h][p] = (v_bias - u_bias) . R[h][p][:]
    float localA = 0.0f, localB = 0.0f;
#pragma unroll
    for (int nt = 0; nt < 4; nt++) {
        int n0 = wn * 32 + nt * 8;
        float2 u2 = *(const float2*)&u_bias[h * DHh + n0 + 2 * tg];
        float2 v2 = *(const float2*)&v_bias[h * DHh + n0 + 2 * tg];
        float db0 = v2.x - u2.x, db1 = v2.y - u2.y;
        localA += acc[nt][0] * db0 + acc[nt][1] * db1;
        localB += acc[nt][2] * db0 + acc[nt][3] * db1;
    }
    localA += __shfl_xor_sync(0xffffffffu, localA, 1);
    localA += __shfl_xor_sync(0xffffffffu, localA, 2);
    localB += __shfl_xor_sync(0xffffffffu, localB, 1);
    localB += __shfl_xor_sync(0xffffffffu, localB, 2);
    if (tg == 0) {
        scr[wn * 64 + wm + g] = localA;
        scr[wn * 64 + wm + g + 8] = localB;
    }
    __syncthreads();
    if (tid < 64 && p0 + tid < Pp)
        g_T[h * TPAD + p0 + tid] = scr[tid] + scr[64 + tid];
}

// ---------------------------------------------------------------------------
// Kernel 2: fused causal flash attention. 512 threads, grid (8,16),
// paired qtiles {15-bx, bx}. k-split PV + warp-local softmax + cp.async
// double-buffered K/V/R staging (raw fp32, HW tf32 truncation). 2 barriers/iter.
// ---------------------------------------------------------------------------
#define SQU 0
#define SKS 4352                    // K ring: 2 x [64][68]
#define SVS (SKS + 2*4352)          // V ring: 2 x [64][72]
#define SRS (SVS + 2*4608)          // R ring: 2 x [64][68]
#define SBS (SRS + 2*4352)          // BD ring: 2 x [64][68]
#define STOT (SBS + 2*4352)         // 39680 floats (~155 KB)
// epilogue overlay: Xo [4][64][68], mArr/lArr [4][64]
#define EPX 0
#define EPM (EPX + 4*64*68)
#define EPL (EPM + 256)

__global__ void __launch_bounds__(512) attn_kernel(
    const float* __restrict__ seqs, const float* __restrict__ keys,
    const float* __restrict__ values, const float* __restrict__ u_bias,
    float* __restrict__ out)
{
    extern __shared__ float sm[];
    float* Qu = sm + SQU;
    float* Ks = sm + SKS;
    float* Vs = sm + SVS;
    float* Rs = sm + SRS;
    float* Bs = sm + SBS;
    unsigned smb = (unsigned)__cvta_generic_to_shared(sm);

    int tid = threadIdx.x;
    int lane = tid & 31;
    int warp = tid >> 5;
    int g = lane >> 2, tg = lane & 3;
    int wm = (warp & 3) * 16;
    int wn = warp >> 2;             // 0..3: this warp's 16-col k-slice
    int rA = wm + g, rB = wm + g + 8;

    int bx = blockIdx.x;
    int head = blockIdx.y;
    int n = head >> 3, h = head & 7;

    const float* sq = seqs   + ((size_t)(n * Hh + h) * Ss) * DHh;
    const float* kq = keys   + ((size_t)(n * Hh + h) * Ss) * DHh;
    const float* vq = values + ((size_t)(n * Hh + h) * Ss) * DHh;
    const float* Rh = g_R + (size_t)h * (Pp * DHh);
    const float* Th = g_T + (size_t)h * TPAD;

    int lrow = tid >> 4;            // 0..31
    int lq4  = tid & 15;

    float4 ub4 = *(const float4*)&u_bias[h * DHh + lq4 * 4];
    const float scale = 0.125f;

    for (int ph = 0; ph < 2; ph++) {
        int qt = (ph == 0) ? (15 - bx) : bx;
        int i0 = qt * 64;
        int pb0 = (Ss - 1) - i0 - 63;

        __syncthreads();   // previous phase epilogue fully consumed

        // ---- async prologue: K/V tile 0 -> buf0, R rows 0..127 ----
#pragma unroll
        for (int r = 0; r < 2; r++) {
            int row = lrow + r * 32;
            cpa16(smb + 4u * (SKS + row * 68 + lq4 * 4), kq + (size_t)row * DHh + lq4 * 4);
            cpa16(smb + 4u * (SVS + row * 72 + lq4 * 4), vq + (size_t)row * DHh + lq4 * 4);
        }
#pragma unroll
        for (int r = 0; r < 4; r++) {
            int row = lrow + r * 32;
            cpa16(smb + 4u * (SRS + row * 68 + lq4 * 4),
                  Rh + (size_t)(pb0 + row) * DHh + lq4 * 4);
        }
        CP_COMMIT();

        // stage Qu (rounded tf32)
#pragma unroll
        for (int r = 0; r < 2; r++) {
            int row = lrow + r * 32;
            float4 s4 = *(const float4*)&sq[(size_t)(i0 + row) * DHh + lq4 * 4];
            Qu[row * 68 + lq4 * 4 + 0] = tf32f(s4.x + ub4.x);
            Qu[row * 68 + lq4 * 4 + 1] = tf32f(s4.y + ub4.y);
            Qu[row * 68 + lq4 * 4 + 2] = tf32f(s4.z + ub4.z);
            Qu[row * 68 + lq4 * 4 + 3] = tf32f(s4.w + ub4.w);
        }

        float mA_run = -1e30f, mB_run = -1e30f;
        float lA_run = 0.0f, lB_run = 0.0f;
        float O[8][4];
#pragma unroll
        for (int a = 0; a < 8; a++)
#pragma unroll
            for (int b = 0; b < 4; b++) O[a][b] = 0.0f;

        for (int kt = 0; kt <= qt; kt++) {
            int j0 = kt * 64;
            int pbase = (Ss - 1) - i0 + j0 - 63;
            int bufLow = kt & 1, bufHigh = bufLow ^ 1;

            CP_WAIT0();
            __syncthreads();   // S1: tiles for kt landed + prev compute done

            // prefetch next K/V into the other buffer
            if (kt < qt) {
                int jn = j0 + 64, b1 = bufHigh;
#pragma unroll
                for (int r = 0; r < 2; r++) {
                    int row = lrow + r * 32;
                    cpa16(smb + 4u * (SKS + b1 * 4352 + row * 68 + lq4 * 4),
                          kq + (size_t)(jn + row) * DHh + lq4 * 4);
                    cpa16(smb + 4u * (SVS + b1 * 4608 + row * 72 + lq4 * 4),
                          vq + (size_t)(jn + row) * DHh + lq4 * 4);
                }
                CP_COMMIT();
            }

            const float* Ksb = Ks + bufLow * 4352;
            const float* Vsb = Vs + bufLow * 4608;

            // tvec for Bs store
            float2 tv[4];
            if (kt == 0) {
#pragma unroll
                for (int nt = 0; nt < 4; nt++)
                    tv[nt] = *(const float2*)&Th[pbase + wn * 32 + nt * 8 + 2 * tg];
            } else {
#pragma unroll
                for (int nt = 0; nt < 2; nt++)
                    tv[nt] = *(const float2*)&Th[pbase + 64 + wn * 16 + nt * 8 + 2 * tg];
            }

            // ---- merged AC + BD (shared A-fragments) ----
            float cS[2][4];
#pragma unroll
            for (int t = 0; t < 2; t++)
#pragma unroll
                for (int e = 0; e < 4; e++) cS[t][e] = 0.0f;

            if (kt == 0) {
                float cB[4][4];
#pragma unroll
                for (int t = 0; t < 4; t++)
#pragma unroll
                    for (int e = 0; e < 4; e++) cB[t][e] = 0.0f;
#pragma unroll
                for (int k0 = 0; k0 < 64; k0 += 8) {
                    unsigned a0 = ldb(&Qu[rA * 68 + k0 + tg]);
                    unsigned a1 = ldb(&Qu[rB * 68 + k0 + tg]);
                    unsigned a2 = ldb(&Qu[rA * 68 + k0 + tg + 4]);
                    unsigned a3 = ldb(&Qu[rB * 68 + k0 + tg + 4]);
#pragma unroll
                    for (int nt = 0; nt < 2; nt++) {
                        int n0 = wn * 16 + nt * 8;
                        unsigned b0 = ldb(&Ksb[(n0 + g) * 68 + k0 + tg]);
                        unsigned b1 = ldb(&Ksb[(n0 + g) * 68 + k0 + tg + 4]);
                        mma_tf32(cS[nt], a0, a1, a2, a3, b0, b1);
                    }
#pragma unroll
                    for (int nt = 0; nt < 4; nt++) {
                        int o0 = wn * 32 + nt * 8;
                        unsigned b0 = ldb(&Rs[(o0 + g) * 68 + k0 + tg]);
                        unsigned b1 = ldb(&Rs[(o0 + g) * 68 + k0 + tg + 4]);
                        mma_tf32(cB[nt], a0, a1, a2, a3, b0, b1);
                    }
                }
#pragma unroll
                for (int nt = 0; nt < 4; nt++) {
                    int o0 = wn * 32 + nt * 8;
                    float* Bd = Bs + (o0 >> 6) * 4352 + (o0 & 63) + 2 * tg;
                    *(float2*)&Bd[rA * 68] = make_float2(cB[nt][0] + tv[nt].x, cB[nt][1] + tv[nt].y);
                    *(float2*)&Bd[rB * 68] = make_float2(cB[nt][2] + tv[nt].x, cB[nt][3] + tv[nt].y);
                }
            } else {
                float cB[2][4];
#pragma unroll
                for (int t = 0; t < 2; t++)
#pragma unroll
                    for (int e = 0; e < 4; e++) cB[t][e] = 0.0f;
                const float* Rb = Rs + bufHigh * 4352;
#pragma unroll
                for (int k0 = 0; k0 < 64; k0 += 8) {
                    unsigned a0 = ldb(&Qu[rA * 68 + k0 + tg]);
                    unsigned a1 = ldb(&Qu[rB * 68 + k0 + tg]);
                    unsigned a2 = ldb(&Qu[rA * 68 + k0 + tg + 4]);
                    unsigned a3 = ldb(&Qu[rB * 68 + k0 + tg + 4]);
#pragma unroll
                    for (int nt = 0; nt < 2; nt++) {
                        int n0 = wn * 16 + nt * 8;
                        unsigned b0 = ldb(&Ksb[(n0 + g) * 68 + k0 + tg]);
                        unsigned b1 = ldb(&Ksb[(n0 + g) * 68 + k0 + tg + 4]);
                        mma_tf32(cS[nt], a0, a1, a2, a3, b0, b1);
                    }
#pragma unroll
                    for (int nt = 0; nt < 2; nt++) {
                        int r0 = wn * 16 + nt * 8;
                        unsigned b0 = ldb(&Rb[(r0 + g) * 68 + k0 + tg]);
                        unsigned b1 = ldb(&Rb[(r0 + g) * 68 + k0 + tg + 4]);
                        mma_tf32(cB[nt], a0, a1, a2, a3, b0, b1);
                    }
                }
                float* Bd0 = Bs + bufHigh * 4352;
#pragma unroll
                for (int nt = 0; nt < 2; nt++) {
                    int r0 = wn * 16 + nt * 8;
                    float* Bd = Bd0 + r0 + 2 * tg;
                    *(float2*)&Bd[rA * 68] = make_float2(cB[nt][0] + tv[nt].x, cB[nt][1] + tv[nt].y);
                    *(float2*)&Bd[rB * 68] = make_float2(cB[nt][2] + tv[nt].x, cB[nt][3] + tv[nt].y);
                }
            }
            __syncthreads();   // S3: Bs visible; Rs[bufLow] now MMA-dead

            // prefetch next R rows into the retiring buffer
            if (kt < qt) {
#pragma unroll
                for (int r = 0; r < 2; r++) {
                    int row = lrow + r * 32;
                    cpa16(smb + 4u * (SRS + bufLow * 4352 + row * 68 + lq4 * 4),
                          Rh + (size_t)(pbase + 128 + row) * DHh + lq4 * 4);
                }
                CP_COMMIT();
            }

            // ---- scores + warp-local online softmax ----
            float sv[2][4];
            float mAl = -INFINITY, mBl = -INFINITY;
            int diag = (kt == qt);
#pragma unroll
            for (int nt = 0; nt < 2; nt++) {
                int colbase = wn * 16 + nt * 8 + 2 * tg;
#pragma unroll
                for (int e = 0; e < 4; e++) {
                    int j = colbase + (e & 1);
                    int row = (e < 2) ? rA : rB;
                    int o = j - row + 63;
                    float bd = Bs[(bufLow ^ (o >> 6)) * 4352 + row * 68 + (o & 63)];
                    float s = (cS[nt][e] + bd) * scale;
                    if (diag && j > row) s = -INFINITY;
                    sv[nt][e] = s;
                    if (e < 2) mAl = fmaxf(mAl, s); else mBl = fmaxf(mBl, s);
                }
            }
            mAl = fmaxf(mAl, __shfl_xor_sync(0xffffffffu, mAl, 1));
            mAl = fmaxf(mAl, __shfl_xor_sync(0xffffffffu, mAl, 2));
            mBl = fmaxf(mBl, __shfl_xor_sync(0xffffffffu, mBl, 1));
            mBl = fmaxf(mBl, __shfl_xor_sync(0xffffffffu, mBl, 2));

            float mgA = fmaxf(mA_run, mAl);
            float mgB = fmaxf(mB_run, mBl);
            float corrA = __expf(mA_run - mgA);
            float corrB = __expf(mB_run - mgB);

            float peA0[2], peA1[2], peB0[2], peB1[2];
            float sumA = 0.0f, sumB = 0.0f;
#pragma unroll
            for (int nt = 0; nt < 2; nt++) {
                peA0[nt] = __expf(sv[nt][0] - mgA);
                peA1[nt] = __expf(sv[nt][1] - mgA);
                peB0[nt] = __expf(sv[nt][2] - mgB);
                peB1[nt] = __expf(sv[nt][3] - mgB);
                sumA += peA0[nt] + peA1[nt];
                sumB += peB0[nt] + peB1[nt];
            }
            sumA += __shfl_xor_sync(0xffffffffu, sumA, 1);
            sumA += __shfl_xor_sync(0xffffffffu, sumA, 2);
            sumB += __shfl_xor_sync(0xffffffffu, sumB, 1);
            sumB += __shfl_xor_sync(0xffffffffu, sumB, 2);
            lA_run = lA_run * corrA + sumA;
            lB_run = lB_run * corrB + sumB;
            mA_run = mgA; mB_run = mgB;

#pragma unroll
            for (int jn = 0; jn < 8; jn++) {
                O[jn][0] *= corrA; O[jn][1] *= corrA;
                O[jn][2] *= corrB; O[jn][3] *= corrB;
            }

            // ---- k-split PV: A-frags assembled from registers via quad shfl ----
#pragma unroll
            for (int nt = 0; nt < 2; nt++) {
                int kbase = wn * 16 + nt * 8;
                int src1 = tg >> 1;
                int src2 = (tg >> 1) + 2;
                float lo, hi;
                lo = __shfl_sync(0xffffffffu, peA0[nt], src1, 4);
                hi = __shfl_sync(0xffffffffu, peA1[nt], src1, 4);
                float a0f = (tg & 1) ? hi : lo;
                lo = __shfl_sync(0xffffffffu, peA0[nt], src2, 4);
                hi = __shfl_sync(0xffffffffu, peA1[nt], src2, 4);
                float a2f = (tg & 1) ? hi : lo;
                lo = __shfl_sync(0xffffffffu, peB0[nt], src1, 4);
                hi = __shfl_sync(0xffffffffu, peB1[nt], src1, 4);
                float a1f = (tg & 1) ? hi : lo;
                lo = __shfl_sync(0xffffffffu, peB0[nt], src2, 4);
                hi = __shfl_sync(0xffffffffu, peB1[nt], src2, 4);
                float a3f = (tg & 1) ? hi : lo;
                unsigned a0 = f2tf(a0f), a1 = f2tf(a1f);
                unsigned a2 = f2tf(a2f), a3 = f2tf(a3f);
#pragma unroll
                for (int jn = 0; jn < 8; jn++) {
                    int n0 = jn * 8;
                    unsigned b0 = ldb(&Vsb[(kbase + tg) * 72 + n0 + g]);
                    unsigned b1 = ldb(&Vsb[(kbase + tg + 4) * 72 + n0 + g]);
                    mma_tf32(O[jn], a0, a1, a2, a3, b0, b1);
                }
            }
        }

        // ---- split-k merge across the 4 k-slice warps ----
        __syncthreads();
        {
            float* Xo = sm + EPX;
            float* mArr = sm + EPM;
            float* lArr = sm + EPL;
#pragma unroll
            for (int jn = 0; jn < 8; jn++) {
                int n0 = jn * 8;
                *(float2*)&Xo[wn * 4352 + rA * 68 + n0 + 2 * tg] =
                    make_float2(O[jn][0], O[jn][1]);
                *(float2*)&Xo[wn * 4352 + rB * 68 + n0 + 2 * tg] =
                    make_float2(O[jn][2], O[jn][3]);
            }
            if (tg == 0) {
                mArr[wn * 64 + rA] = mA_run; lArr[wn * 64 + rA] = lA_run;
                mArr[wn * 64 + rB] = mB_run; lArr[wn * 64 + rB] = lB_run;
            }
            __syncthreads();

            int row = tid >> 3, cb = (tid & 7) * 8;
            float m0 = mArr[row], m1 = mArr[64 + row];
            float m2 = mArr[128 + row], m3 = mArr[192 + row];
            float mg = fmaxf(fmaxf(m0, m1), fmaxf(m2, m3));
            float f0 = __expf(m0 - mg), f1 = __expf(m1 - mg);
            float f2 = __expf(m2 - mg), f3 = __expf(m3 - mg);
            float lg = lArr[row] * f0 + lArr[64 + row] * f1
                     + lArr[128 + row] * f2 + lArr[192 + row] * f3;
            float inv = 1.0f / lg;
            float* op = out + ((size_t)(n * Hh + h) * Ss + i0 + row) * DHh + cb;
#pragma unroll
            for (int c = 0; c < 8; c += 4) {
                float4 x0 = *(const float4*)&Xo[0 * 4352 + row * 68 + cb + c];
                float4 x1 = *(const float4*)&Xo[1 * 4352 + row * 68 + cb + c];
                float4 x2 = *(const float4*)&Xo[2 * 4352 + row * 68 + cb + c];
                float4 x3 = *(const float4*)&Xo[3 * 4352 + row * 68 + cb + c];
                float4 o4;
                o4.x = (x0.x * f0 + x1.x * f1 + x2.x * f2 + x3.x * f3) * inv;
                o4.y = (x0.y * f0 + x1.y * f1 + x2.y * f2 + x3.y * f3) * inv;
                o4.z = (x0.z * f0 + x1.z * f1 + x2.z * f2 + x3.z * f3) * inv;
                o4.w = (x0.w * f0 + x1.w * f1 + x2.w * f2 + x3.w * f3) * inv;
                *(float4*)&op[c] = o4;
            }
        }
    }
}

// ---------------------------------------------------------------------------
extern "C" void kernel_launch(void* const* d_in, const int* in_sizes, int n_in,
                              void* d_out, int out_size) {
    const float* seqs   = (const float*)d_in[0];
    const float* keys   = (const float*)d_in[1];
    const float* values = (const float*)d_in[2];
    const float* u_bias = (const float*)d_in[3];
    const float* v_bias = (const float*)d_in[4];
    const float* rproj  = (const float*)d_in[5];
    (void)in_sizes; (void)n_in; (void)out_size;

    const int smem_bytes = STOT * sizeof(float);   // ~155 KB
    cudaFuncSetAttribute(attn_kernel, cudaFuncAttributeMaxDynamicSharedMemorySize,
                         smem_bytes);

    enc_rot_kernel<<<64, 256>>>();
    rproj_mma_kernel<<<dim3(32, 8), 256>>>(rproj, u_bias, v_bias);
    attn_kernel<<<dim3(8, 16), 512, smem_bytes>>>(seqs, keys, values,
                                                  u_bias, (float*)d_out);
}

// round 10
// speedup vs baseline: 1.5215x; 1.0850x over previous
#include <cuda_runtime.h>
#include <cuda_fp16.h>
#include <math.h>

#define Nn 2
#define Hh 8
#define Ss 1024
#define DHh 64
#define Dd 512
#define Pp 2047   // 2S-1
#define TPAD 2048 // padded head stride for g_T

__device__ float g_ENC[Pp * Dd];
__device__ __half g_Rh[Hh * Pp * DHh];     // rounded fp16 R
__device__ __half g_Quh[Nn * Hh * Ss * DHh]; // rounded fp16 (seqs + u_bias)
__device__ __half g_Kh[Nn * Hh * Ss * DHh];  // rounded fp16 keys
__device__ float g_T[Hh * TPAD];

__device__ __forceinline__ unsigned f2tf(float x) {
    unsigned r;
    asm("cvt.rna.tf32.f32 %0, %1;" : "=r"(r) : "f"(x));
    return r;
}
__device__ __forceinline__ float tf32f(float x) { return __uint_as_float(f2tf(x)); }
__device__ __forceinline__ void mma_tf32(float c[4], unsigned a0, unsigned a1,
                                         unsigned a2, unsigned a3,
                                         unsigned b0, unsigned b1) {
    asm volatile(
        "mma.sync.aligned.m16n8k8.row.col.f32.tf32.tf32.f32 "
        "{%0,%1,%2,%3},{%4,%5,%6,%7},{%8,%9},{%0,%1,%2,%3};"
        : "+f"(c[0]), "+f"(c[1]), "+f"(c[2]), "+f"(c[3])
        : "r"(a0), "r"(a1), "r"(a2), "r"(a3), "r"(b0), "r"(b1));
}
__device__ __forceinline__ void mma_f16(float c[4], unsigned a0, unsigned a1,
                                        unsigned a2, unsigned a3,
                                        unsigned b0, unsigned b1) {
    asm volatile(
        "mma.sync.aligned.m16n8k16.row.col.f32.f16.f16.f32 "
        "{%0,%1,%2,%3},{%4,%5,%6,%7},{%8,%9},{%0,%1,%2,%3};"
        : "+f"(c[0]), "+f"(c[1]), "+f"(c[2]), "+f"(c[3])
        : "r"(a0), "r"(a1), "r"(a2), "r"(a3), "r"(b0), "r"(b1));
}
__device__ __forceinline__ unsigned ldh(const __half* p) { return *(const unsigned*)p; }
__device__ __forceinline__ void cpa16(unsigned dst, const void* src) {
    asm volatile("cp.async.cg.shared.global [%0], [%1], 16;" :: "r"(dst), "l"(src));
}
#define CP_COMMIT() asm volatile("cp.async.commit_group;")
#define CP_WAIT0()  asm volatile("cp.async.wait_group 0;")

// ---------------------------------------------------------------------------
// Kernel 0: positional encodings by incremental rotation.
// ---------------------------------------------------------------------------
__global__ void __launch_bounds__(256) enc_rot_kernel() {
    int i = threadIdx.x;
    int p0 = blockIdx.x * 32;
    int steps = Pp - p0; if (steps > 32) steps = 32;
    const float coef = -9.210340371976184f / 512.0f;
    float invf = __expf((float)(2 * i) * coef);
    float s, c;
    sincosf((float)(1023 - p0) * invf, &s, &c);
    float rs, rc;
    sincosf(invf, &rs, &rc);
    for (int t = 0; t < steps; t++) {
        *(float2*)&g_ENC[(size_t)(p0 + t) * Dd + 2 * i] = make_float2(s, c);
        float s2 = s * rc - c * rs;
        float c2 = c * rc + s * rs;
        s = s2; c = c2;
    }
}

// ---------------------------------------------------------------------------
// Kernel 0b: rounded fp16 conversion of Qu (=seqs+u_bias) and K.
// 512 blocks x 256 threads, 8 elems each.
// ---------------------------------------------------------------------------
__global__ void __launch_bounds__(256) cvt_kernel(
    const float* __restrict__ seqs, const float* __restrict__ keys,
    const float* __restrict__ u_bias)
{
    size_t base = ((size_t)blockIdx.x * 256 + threadIdx.x) * 8;
    int h = (int)((base >> 16) & 7);
    int d0 = (int)(base & 63);
    float4 s0 = *(const float4*)&seqs[base];
    float4 s1 = *(const float4*)&seqs[base + 4];
    float4 k0 = *(const float4*)&keys[base];
    float4 k1 = *(const float4*)&keys[base + 4];
    float4 u0 = *(const float4*)&u_bias[h * DHh + d0];
    float4 u1 = *(const float4*)&u_bias[h * DHh + d0 + 4];
    __half2* q2 = (__half2*)&g_Quh[base];
    __half2* k2 = (__half2*)&g_Kh[base];
    q2[0] = __floats2half2_rn(s0.x + u0.x, s0.y + u0.y);
    q2[1] = __floats2half2_rn(s0.z + u0.z, s0.w + u0.w);
    q2[2] = __floats2half2_rn(s1.x + u1.x, s1.y + u1.y);
    q2[3] = __floats2half2_rn(s1.z + u1.z, s1.w + u1.w);
    k2[0] = __floats2half2_rn(k0.x, k0.y);
    k2[1] = __floats2half2_rn(k0.z, k0.w);
    k2[2] = __floats2half2_rn(k1.x, k1.y);
    k2[3] = __floats2half2_rn(k1.z, k1.w);
}

// ---------------------------------------------------------------------------
// Kernel 1: r-projection (tf32 mma) -> rounded fp16 g_Rh + rank-1 g_T.
// ---------------------------------------------------------------------------
__global__ void __launch_bounds__(256) rproj_mma_kernel(
    const float* __restrict__ W, const float* __restrict__ u_bias,
    const float* __restrict__ v_bias)
{
    __shared__ float As[64 * 36];
    __shared__ float Bsm[64 * 36];
    __shared__ float scr[2 * 64];

    int tid = threadIdx.x;
    int warp = tid >> 5, lane = tid & 31;
    int g = lane >> 2, tg = lane & 3;
    int wm = (warp & 3) * 16;
    int wn = warp >> 2;

    int p0 = blockIdx.x * 64;
    int h = blockIdx.y;
    int c0 = h * 64;

    float acc[4][4] = {};

    for (int j0 = 0; j0 < Dd; j0 += 32) {
        __syncthreads();
#pragma unroll
        for (int r = 0; r < 2; r++) {
            int q = tid + r * 256;
            int row = q >> 3, qq = q & 7;
            int p = p0 + row;
            float4 e = make_float4(0.f, 0.f, 0.f, 0.f);
            if (p < Pp) e = *(const float4*)&g_ENC[(size_t)p * Dd + j0 + 4 * qq];
            float4 o; o.x = tf32f(e.x); o.y = tf32f(e.y); o.z = tf32f(e.z); o.w = tf32f(e.w);
            *(float4*)&As[row * 36 + 4 * qq] = o;
        }
#pragma unroll
        for (int r = 0; r < 2; r++) {
            int q2 = tid + r * 256;
            int row = q2 >> 3, qq = q2 & 7;
            float4 w = *(const float4*)&W[(size_t)(c0 + row) * Dd + j0 + 4 * qq];
            float4 o; o.x = tf32f(w.x); o.y = tf32f(w.y); o.z = tf32f(w.z); o.w = tf32f(w.w);
            *(float4*)&Bsm[row * 36 + 4 * qq] = o;
        }
        __syncthreads();
#pragma unroll
        for (int k0 = 0; k0 < 32; k0 += 8) {
            unsigned a0 = __float_as_uint(As[(wm + g) * 36 + k0 + tg]);
            unsigned a1 = __float_as_uint(As[(wm + g + 8) * 36 + k0 + tg]);
            unsigned a2 = __float_as_uint(As[(wm + g) * 36 + k0 + tg + 4]);
            unsigned a3 = __float_as_uint(As[(wm + g + 8) * 36 + k0 + tg + 4]);
#pragma unroll
            for (int nt = 0; nt < 4; nt++) {
                int n0 = wn * 32 + nt * 8;
                unsigned b0 = __float_as_uint(Bsm[(n0 + g) * 36 + k0 + tg]);
                unsigned b1 = __float_as_uint(Bsm[(n0 + g) * 36 + k0 + tg + 4]);
                mma_tf32(acc[nt], a0, a1, a2, a3, b0, b1);
            }
        }
    }
    int pA = p0 + wm + g, pB = pA + 8;
    __half* Rh = g_Rh + (size_t)h * (Pp * DHh);
#pragma unroll
    for (int nt = 0; nt < 4; nt++) {
        int n0 = wn * 32 + nt * 8;
        if (pA < Pp)
            *(__half2*)&Rh[(size_t)pA * DHh + n0 + 2 * tg] =
                __floats2half2_rn(acc[nt][0], acc[nt][1]);
        if (pB < Pp)
            *(__half2*)&Rh[(size_t)pB * DHh + n0 + 2 * tg] =
                __floats2half2_rn(acc[nt][2], acc[nt][3]);
    }

    // g_T[h][p] = (v_bias - u_bias) . R[h][p][:]
    float localA = 0.0f, localB = 0.0f;
#pragma unroll
    for (int nt = 0; nt < 4; nt++) {
        int n0 = wn * 32 + nt * 8;
        float2 u2 = *(const float2*)&u_bias[h * DHh + n0 + 2 * tg];
        float2 v2 = *(const float2*)&v_bias[h * DHh + n0 + 2 * tg];
        float db0 = v2.x - u2.x, db1 = v2.y - u2.y;
        localA += acc[nt][0] * db0 + acc[nt][1] * db1;
        localB += acc[nt][2] * db0 + acc[nt][3] * db1;
    }
    localA += __shfl_xor_sync(0xffffffffu, localA, 1);
    localA += __shfl_xor_sync(0xffffffffu, localA, 2);
    localB += __shfl_xor_sync(0xffffffffu, localB, 1);
    localB += __shfl_xor_sync(0xffffffffu, localB, 2);
    if (tg == 0) {
        scr[wn * 64 + wm + g] = localA;
        scr[wn * 64 + wm + g + 8] = localB;
    }
    __syncthreads();
    if (tid < 64 && p0 + tid < Pp)
        g_T[h * TPAD + p0 + tid] = scr[tid] + scr[64 + tid];
}

// ---------------------------------------------------------------------------
// Kernel 2: fused causal flash attention. 512 threads, grid (8,16), paired
// qtiles {15-bx, bx}. fp16 m16n8k16 AC/BD, tf32 PV (rounded V frags),
// k-split PV + warp-local softmax, cp.async double-buffered staging.
// ---------------------------------------------------------------------------
// smem layout (bytes):
#define SQU_B 0                     // Qu fp16 [64][72]   9216 B
#define SKH_B 9216                  // K ring 2 x [64][72]h  18432 B
#define SRH_B 27648                 // R ring 2 x [64][72]h  18432 B (contiguous 128 rows)
#define SVS_B 46080                 // V ring 2 x [64][68]f  34816 B
#define SBS_B 80896                 // BD ring 2 x [64][68]f 34816 B
#define SMEM_BYTES 115712
// epilogue overlay (bytes from base): Xo 4x64x68 f (69632), m/l 4x64 each
#define EPX_B 0
#define EPM_B 69632
#define EPL_B 70656

__global__ void __launch_bounds__(512) attn_kernel(
    const float* __restrict__ values, float* __restrict__ out)
{
    extern __shared__ char smc[];
    __half* Quh = (__half*)(smc + SQU_B);
    __half* Khs = (__half*)(smc + SKH_B);
    __half* Rhs = (__half*)(smc + SRH_B);
    float*  Vs  = (float*)(smc + SVS_B);
    float*  Bs  = (float*)(smc + SBS_B);
    unsigned smb = (unsigned)__cvta_generic_to_shared(smc);

    int tid = threadIdx.x;
    int lane = tid & 31;
    int warp = tid >> 5;
    int g = lane >> 2, tg = lane & 3;
    int wm = (warp & 3) * 16;
    int wn = warp >> 2;             // 0..3: this warp's 16-col k-slice
    int rA = wm + g, rB = wm + g + 8;

    int bx = blockIdx.x;
    int head = blockIdx.y;
    int n = head >> 3, h = head & 7;

    size_t hoff = (size_t)(n * Hh + h) * Ss * DHh;
    const __half* qug = g_Quh + hoff;
    const __half* khg = g_Kh + hoff;
    const float*  vq  = values + hoff;
    const __half* Rhg = g_Rh + (size_t)h * (Pp * DHh);
    const float*  Th  = g_T + (size_t)h * TPAD;

    int row8 = tid >> 3, ch8 = tid & 7;     // 64-row x 8x16B maps (half tiles)
    int row16 = tid >> 4, ch16 = tid & 15;  // 32-row x 16x16B maps (V fp32)

    const float scale = 0.125f;

    for (int ph = 0; ph < 2; ph++) {
        int qt = (ph == 0) ? (15 - bx) : bx;
        int i0 = qt * 64;
        int pb0 = (Ss - 1) - i0 - 63;

        __syncthreads();   // previous phase epilogue fully consumed

        // ---- async prologue: Qu, K/V tile 0, R rows 0..127 ----
        cpa16(smb + SQU_B + row8 * 144 + ch8 * 16,
              qug + (size_t)(i0 + row8) * DHh + ch8 * 8);
        cpa16(smb + SKH_B + row8 * 144 + ch8 * 16,
              khg + (size_t)row8 * DHh + ch8 * 8);
#pragma unroll
        for (int r = 0; r < 2; r++) {
            int row = row16 + r * 32;
            cpa16(smb + SVS_B + row * 272 + ch16 * 16,
                  vq + (size_t)row * DHh + ch16 * 4);
        }
#pragma unroll
        for (int r = 0; r < 2; r++) {
            int row = row8 + r * 64;     // 0..127 contiguous over R ring
            cpa16(smb + SRH_B + row * 144 + ch8 * 16,
                  Rhg + (size_t)(pb0 + row) * DHh + ch8 * 8);
        }
        CP_COMMIT();

        float mA_run = -1e30f, mB_run = -1e30f;
        float lA_run = 0.0f, lB_run = 0.0f;
        float O[8][4];
#pragma unroll
        for (int a = 0; a < 8; a++)
#pragma unroll
            for (int b = 0; b < 4; b++) O[a][b] = 0.0f;

        for (int kt = 0; kt <= qt; kt++) {
            int j0 = kt * 64;
            int pbase = (Ss - 1) - i0 + j0 - 63;
            int bufLow = kt & 1, bufHigh = bufLow ^ 1;

            CP_WAIT0();
            __syncthreads();   // S1: tiles for kt landed + prev compute done

            // prefetch next K/V into the other buffer
            if (kt < qt) {
                int jn = j0 + 64;
                cpa16(smb + SKH_B + bufHigh * 9216 + row8 * 144 + ch8 * 16,
                      khg + (size_t)(jn + row8) * DHh + ch8 * 8);
#pragma unroll
                for (int r = 0; r < 2; r++) {
                    int row = row16 + r * 32;
                    cpa16(smb + SVS_B + bufHigh * 17408 + row * 272 + ch16 * 16,
                          vq + (size_t)(jn + row) * DHh + ch16 * 4);
                }
                CP_COMMIT();
            }

            const __half* Khb = Khs + bufLow * 4608;   // 64*72 halves
            const float*  Vsb = Vs + bufLow * 4352;

            // tvec for Bs store
            float2 tv[4];
            if (kt == 0) {
#pragma unroll
                for (int nt = 0; nt < 4; nt++)
                    tv[nt] = *(const float2*)&Th[pbase + wn * 32 + nt * 8 + 2 * tg];
            } else {
#pragma unroll
                for (int nt = 0; nt < 2; nt++)
                    tv[nt] = *(const float2*)&Th[pbase + 64 + wn * 16 + nt * 8 + 2 * tg];
            }

            // ---- merged AC + BD, fp16 m16n8k16 (shared A-fragments) ----
            float cS[2][4];
#pragma unroll
            for (int t = 0; t < 2; t++)
#pragma unroll
                for (int e = 0; e < 4; e++) cS[t][e] = 0.0f;

            if (kt == 0) {
                float cB[4][4];
#pragma unroll
                for (int t = 0; t < 4; t++)
#pragma unroll
                    for (int e = 0; e < 4; e++) cB[t][e] = 0.0f;
#pragma unroll
                for (int k0 = 0; k0 < 64; k0 += 16) {
                    unsigned a0 = ldh(&Quh[rA * 72 + k0 + 2 * tg]);
                    unsigned a1 = ldh(&Quh[rB * 72 + k0 + 2 * tg]);
                    unsigned a2 = ldh(&Quh[rA * 72 + k0 + 8 + 2 * tg]);
                    unsigned a3 = ldh(&Quh[rB * 72 + k0 + 8 + 2 * tg]);
#pragma unroll
                    for (int nt = 0; nt < 2; nt++) {
                        int n0 = wn * 16 + nt * 8;
                        unsigned b0 = ldh(&Khb[(n0 + g) * 72 + k0 + 2 * tg]);
                        unsigned b1 = ldh(&Khb[(n0 + g) * 72 + k0 + 8 + 2 * tg]);
                        mma_f16(cS[nt], a0, a1, a2, a3, b0, b1);
                    }
#pragma unroll
                    for (int nt = 0; nt < 4; nt++) {
                        int o0 = wn * 32 + nt * 8;   // band row 0..127 contiguous
                        unsigned b0 = ldh(&Rhs[(o0 + g) * 72 + k0 + 2 * tg]);
                        unsigned b1 = ldh(&Rhs[(o0 + g) * 72 + k0 + 8 + 2 * tg]);
                        mma_f16(cB[nt], a0, a1, a2, a3, b0, b1);
                    }
                }
#pragma unroll
                for (int nt = 0; nt < 4; nt++) {
                    int o0 = wn * 32 + nt * 8;
                    float* Bd = Bs + (o0 >> 6) * 4352 + (o0 & 63) + 2 * tg;
                    *(float2*)&Bd[rA * 68] = make_float2(cB[nt][0] + tv[nt].x, cB[nt][1] + tv[nt].y);
                    *(float2*)&Bd[rB * 68] = make_float2(cB[nt][2] + tv[nt].x, cB[nt][3] + tv[nt].y);
                }
            } else {
                float cB[2][4];
#pragma unroll
                for (int t = 0; t < 2; t++)
#pragma unroll
                    for (int e = 0; e < 4; e++) cB[t][e] = 0.0f;
                const __half* Rb = Rhs + bufHigh * 4608;
#pragma unroll
                for (int k0 = 0; k0 < 64; k0 += 16) {
                    unsigned a0 = ldh(&Quh[rA * 72 + k0 + 2 * tg]);
                    unsigned a1 = ldh(&Quh[rB * 72 + k0 + 2 * tg]);
                    unsigned a2 = ldh(&Quh[rA * 72 + k0 + 8 + 2 * tg]);
                    unsigned a3 = ldh(&Quh[rB * 72 + k0 + 8 + 2 * tg]);
#pragma unroll
                    for (int nt = 0; nt < 2; nt++) {
                        int n0 = wn * 16 + nt * 8;
                        unsigned b0 = ldh(&Khb[(n0 + g) * 72 + k0 + 2 * tg]);
                        unsigned b1 = ldh(&Khb[(n0 + g) * 72 + k0 + 8 + 2 * tg]);
                        mma_f16(cS[nt], a0, a1, a2, a3, b0, b1);
                    }
#pragma unroll
                    for (int nt = 0; nt < 2; nt++) {
                        int r0 = wn * 16 + nt * 8;
                        unsigned b0 = ldh(&Rb[(r0 + g) * 72 + k0 + 2 * tg]);
                        unsigned b1 = ldh(&Rb[(r0 + g) * 72 + k0 + 8 + 2 * tg]);
                        mma_f16(cB[nt], a0, a1, a2, a3, b0, b1);
                    }
                }
                float* Bd0 = Bs + bufHigh * 4352;
#pragma unroll
                for (int nt = 0; nt < 2; nt++) {
                    int r0 = wn * 16 + nt * 8;
                    float* Bd = Bd0 + r0 + 2 * tg;
                    *(float2*)&Bd[rA * 68] = make_float2(cB[nt][0] + tv[nt].x, cB[nt][1] + tv[nt].y);
                    *(float2*)&Bd[rB * 68] = make_float2(cB[nt][2] + tv[nt].x, cB[nt][3] + tv[nt].y);
                }
            }
            __syncthreads();   // S3: Bs visible; R[bufLow] now MMA-dead

            // prefetch next R rows into the retiring buffer
            if (kt < qt) {
                cpa16(smb + SRH_B + bufLow * 9216 + row8 * 144 + ch8 * 16,
                      Rhg + (size_t)(pbase + 128 + row8) * DHh + ch8 * 8);
                CP_COMMIT();
            }

            // ---- scores + warp-local online softmax ----
            float sv[2][4];
            float mAl = -INFINITY, mBl = -INFINITY;
            int diag = (kt == qt);
#pragma unroll
            for (int nt = 0; nt < 2; nt++) {
                int colbase = wn * 16 + nt * 8 + 2 * tg;
#pragma unroll
                for (int e = 0; e < 4; e++) {
                    int j = colbase + (e & 1);
                    int row = (e < 2) ? rA : rB;
                    int o = j - row + 63;
                    float bd = Bs[(bufLow ^ (o >> 6)) * 4352 + row * 68 + (o & 63)];
                    float s = (cS[nt][e] + bd) * scale;
                    if (diag && j > row) s = -INFINITY;
                    sv[nt][e] = s;
                    if (e < 2) mAl = fmaxf(mAl, s); else mBl = fmaxf(mBl, s);
                }
            }
            mAl = fmaxf(mAl, __shfl_xor_sync(0xffffffffu, mAl, 1));
            mAl = fmaxf(mAl, __shfl_xor_sync(0xffffffffu, mAl, 2));
            mBl = fmaxf(mBl, __shfl_xor_sync(0xffffffffu, mBl, 1));
            mBl = fmaxf(mBl, __shfl_xor_sync(0xffffffffu, mBl, 2));

            float mgA = fmaxf(mA_run, mAl);
            float mgB = fmaxf(mB_run, mBl);
            float corrA = __expf(mA_run - mgA);
            float corrB = __expf(mB_run - mgB);

            float peA0[2], peA1[2], peB0[2], peB1[2];
            float sumA = 0.0f, sumB = 0.0f;
#pragma unroll
            for (int nt = 0; nt < 2; nt++) {
                peA0[nt] = __expf(sv[nt][0] - mgA);
                peA1[nt] = __expf(sv[nt][1] - mgA);
                peB0[nt] = __expf(sv[nt][2] - mgB);
                peB1[nt] = __expf(sv[nt][3] - mgB);
                sumA += peA0[nt] + peA1[nt];
                sumB += peB0[nt] + peB1[nt];
            }
            sumA += __shfl_xor_sync(0xffffffffu, sumA, 1);
            sumA += __shfl_xor_sync(0xffffffffu, sumA, 2);
            sumB += __shfl_xor_sync(0xffffffffu, sumB, 1);
            sumB += __shfl_xor_sync(0xffffffffu, sumB, 2);
            lA_run = lA_run * corrA + sumA;
            lB_run = lB_run * corrB + sumB;
            mA_run = mgA; mB_run = mgB;

#pragma unroll
            for (int jn = 0; jn < 8; jn++) {
                O[jn][0] *= corrA; O[jn][1] *= corrA;
                O[jn][2] *= corrB; O[jn][3] *= corrB;
            }

            // ---- k-split PV (tf32): A-frags from registers via quad shfl ----
#pragma unroll
            for (int nt = 0; nt < 2; nt++) {
                int kbase = wn * 16 + nt * 8;
                int src1 = tg >> 1;
                int src2 = (tg >> 1) + 2;
                float lo, hi;
                lo = __shfl_sync(0xffffffffu, peA0[nt], src1, 4);
                hi = __shfl_sync(0xffffffffu, peA1[nt], src1, 4);
                float a0f = (tg & 1) ? hi : lo;
                lo = __shfl_sync(0xffffffffu, peA0[nt], src2, 4);
                hi = __shfl_sync(0xffffffffu, peA1[nt], src2, 4);
                float a2f = (tg & 1) ? hi : lo;
                lo = __shfl_sync(0xffffffffu, peB0[nt], src1, 4);
                hi = __shfl_sync(0xffffffffu, peB1[nt], src1, 4);
                float a1f = (tg & 1) ? hi : lo;
                lo = __shfl_sync(0xffffffffu, peB0[nt], src2, 4);
                hi = __shfl_sync(0xffffffffu, peB1[nt], src2, 4);
                float a3f = (tg & 1) ? hi : lo;
                unsigned a0 = f2tf(a0f), a1 = f2tf(a1f);
                unsigned a2 = f2tf(a2f), a3 = f2tf(a3f);
#pragma unroll
                for (int jn = 0; jn < 8; jn++) {
                    int n0 = jn * 8;
                    unsigned b0 = f2tf(Vsb[(kbase + tg) * 68 + n0 + g]);
                    unsigned b1 = f2tf(Vsb[(kbase + tg + 4) * 68 + n0 + g]);
                    mma_tf32(O[jn], a0, a1, a2, a3, b0, b1);
                }
            }
        }

        // ---- split-k merge across the 4 k-slice warps ----
        __syncthreads();
        {
            float* Xo = (float*)(smc + EPX_B);
            float* mArr = (float*)(smc + EPM_B);
            float* lArr = (float*)(smc + EPL_B);
#pragma unroll
            for (int jn = 0; jn < 8; jn++) {
                int n0 = jn * 8;
                *(float2*)&Xo[wn * 4352 + rA * 68 + n0 + 2 * tg] =
                    make_float2(O[jn][0], O[jn][1]);
                *(float2*)&Xo[wn * 4352 + rB * 68 + n0 + 2 * tg] =
                    make_float2(O[jn][2], O[jn][3]);
            }
            if (tg == 0) {
                mArr[wn * 64 + rA] = mA_run; lArr[wn * 64 + rA] = lA_run;
                mArr[wn * 64 + rB] = mB_run; lArr[wn * 64 + rB] = lB_run;
            }
            __syncthreads();

            int row = tid >> 3, cb = (tid & 7) * 8;
            float m0 = mArr[row], m1 = mArr[64 + row];
            float m2 = mArr[128 + row], m3 = mArr[192 + row];
            float mg = fmaxf(fmaxf(m0, m1), fmaxf(m2, m3));
            float f0 = __expf(m0 - mg), f1 = __expf(m1 - mg);
            float f2 = __expf(m2 - mg), f3 = __expf(m3 - mg);
            float lg = lArr[row] * f0 + lArr[64 + row] * f1
                     + lArr[128 + row] * f2 + lArr[192 + row] * f3;
            float inv = 1.0f / lg;
            float* op = out + hoff + (size_t)(i0 + row) * DHh + cb;
#pragma unroll
            for (int c = 0; c < 8; c += 4) {
                float4 x0 = *(const float4*)&Xo[0 * 4352 + row * 68 + cb + c];
                float4 x1 = *(const float4*)&Xo[1 * 4352 + row * 68 + cb + c];
                float4 x2 = *(const float4*)&Xo[2 * 4352 + row * 68 + cb + c];
                float4 x3 = *(const float4*)&Xo[3 * 4352 + row * 68 + cb + c];
                float4 o4;
                o4.x = (x0.x * f0 + x1.x * f1 + x2.x * f2 + x3.x * f3) * inv;
                o4.y = (x0.y * f0 + x1.y * f1 + x2.y * f2 + x3.y * f3) * inv;
                o4.z = (x0.z * f0 + x1.z * f1 + x2.z * f2 + x3.z * f3) * inv;
                o4.w = (x0.w * f0 + x1.w * f1 + x2.w * f2 + x3.w * f3) * inv;
                *(float4*)&op[c] = o4;
            }
        }
    }
}

// ---------------------------------------------------------------------------
extern "C" void kernel_launch(void* const* d_in, const int* in_sizes, int n_in,
                              void* d_out, int out_size) {
    const float* seqs   = (const float*)d_in[0];
    const float* keys   = (const float*)d_in[1];
    const float* values = (const float*)d_in[2];
    const float* u_bias = (const float*)d_in[3];
    const float* v_bias = (const float*)d_in[4];
    const float* rproj  = (const float*)d_in[5];
    (void)in_sizes; (void)n_in; (void)out_size;

    cudaFuncSetAttribute(attn_kernel, cudaFuncAttributeMaxDynamicSharedMemorySize,
                         SMEM_BYTES);

    enc_rot_kernel<<<64, 256>>>();
    cvt_kernel<<<512, 256>>>(seqs, keys, u_bias);
    rproj_mma_kernel<<<dim3(32, 8), 256>>>(rproj, u_bias, v_bias);
    attn_kernel<<<dim3(8, 16), 512, SMEM_BYTES>>>(values, (float*)d_out);
}

// round 11
// speedup vs baseline: 1.5292x; 1.0051x over previous
#include <cuda_runtime.h>
#include <cuda_fp16.h>
#include <math.h>

#define Nn 2
#define Hh 8
#define Ss 1024
#define DHh 64
#define Dd 512
#define Pp 2047   // 2S-1
#define TPAD 2048 // padded head stride for g_T

__device__ __half g_Rh[Hh * Pp * DHh];        // rounded fp16 R
__device__ __half g_Quh[Nn * Hh * Ss * DHh];  // rounded fp16 (seqs + u_bias)
__device__ __half g_Kh[Nn * Hh * Ss * DHh];   // rounded fp16 keys
__device__ __half g_Vh[Nn * Hh * DHh * Ss];   // rounded fp16 V TRANSPOSED [hn][d][s]
__device__ float g_T[Hh * TPAD];

__device__ __forceinline__ unsigned f2tf(float x) {
    unsigned r;
    asm("cvt.rna.tf32.f32 %0, %1;" : "=r"(r) : "f"(x));
    return r;
}
__device__ __forceinline__ float tf32f(float x) { return __uint_as_float(f2tf(x)); }
__device__ __forceinline__ void mma_tf32(float c[4], unsigned a0, unsigned a1,
                                         unsigned a2, unsigned a3,
                                         unsigned b0, unsigned b1) {
    asm volatile(
        "mma.sync.aligned.m16n8k8.row.col.f32.tf32.tf32.f32 "
        "{%0,%1,%2,%3},{%4,%5,%6,%7},{%8,%9},{%0,%1,%2,%3};"
        : "+f"(c[0]), "+f"(c[1]), "+f"(c[2]), "+f"(c[3])
        : "r"(a0), "r"(a1), "r"(a2), "r"(a3), "r"(b0), "r"(b1));
}
__device__ __forceinline__ void mma_f16(float c[4], unsigned a0, unsigned a1,
                                        unsigned a2, unsigned a3,
                                        unsigned b0, unsigned b1) {
    asm volatile(
        "mma.sync.aligned.m16n8k16.row.col.f32.f16.f16.f32 "
        "{%0,%1,%2,%3},{%4,%5,%6,%7},{%8,%9},{%0,%1,%2,%3};"
        : "+f"(c[0]), "+f"(c[1]), "+f"(c[2]), "+f"(c[3])
        : "r"(a0), "r"(a1), "r"(a2), "r"(a3), "r"(b0), "r"(b1));
}
__device__ __forceinline__ unsigned ldh(const __half* p) { return *(const unsigned*)p; }
__device__ __forceinline__ unsigned packh2(float a, float b) {
    __half2 t = __floats2half2_rn(a, b);
    return reinterpret_cast<unsigned&>(t);
}
__device__ __forceinline__ void cpa16(unsigned dst, const void* src) {
    asm volatile("cp.async.cg.shared.global [%0], [%1], 16;" :: "r"(dst), "l"(src));
}
#define CP_COMMIT() asm volatile("cp.async.commit_group;")
#define CP_WAIT0()  asm volatile("cp.async.wait_group 0;")

// ---------------------------------------------------------------------------
// Prologue kernel: blocks 0..255  -> cvt Q/K fp16 + V transpose fp16
//                  blocks 256..511 -> rproj (inline sincos enc, tf32 mma)
// ---------------------------------------------------------------------------
__global__ void __launch_bounds__(256) prologue_kernel(
    const float* __restrict__ seqs, const float* __restrict__ keys,
    const float* __restrict__ values, const float* __restrict__ u_bias,
    const float* __restrict__ v_bias, const float* __restrict__ W)
{
    __shared__ __align__(16) char sA[19456];
    int tid = threadIdx.x;

    if (blockIdx.x < 256) {
        // -------- cvt: one (head, s-tile) of 64 rows --------
        __half* Tsm = (__half*)sA;   // [64 d][72 s] halves
        int hn = blockIdx.x & 15;    // n*8+h
        int h = hn & 7;
        int s0 = (blockIdx.x >> 4) * 64;
        size_t base = (size_t)hn * Ss * DHh;

        int row = tid >> 2;          // 0..63
        int dq = (tid & 3) * 16;     // 0,16,32,48
        const float* qp = seqs + base + (size_t)(s0 + row) * DHh + dq;
        const float* kp = keys + base + (size_t)(s0 + row) * DHh + dq;
        const float* vp = values + base + (size_t)(s0 + row) * DHh + dq;
        unsigned qh[8], kh[8];
#pragma unroll
        for (int j = 0; j < 16; j += 4) {
            float4 q = *(const float4*)(qp + j);
            float4 u = *(const float4*)&u_bias[h * DHh + dq + j];
            float4 k = *(const float4*)(kp + j);
            float4 v = *(const float4*)(vp + j);
            qh[j / 2]     = packh2(q.x + u.x, q.y + u.y);
            qh[j / 2 + 1] = packh2(q.z + u.z, q.w + u.w);
            kh[j / 2]     = packh2(k.x, k.y);
            kh[j / 2 + 1] = packh2(k.z, k.w);
            Tsm[(dq + j + 0) * 72 + row] = __float2half_rn(v.x);
            Tsm[(dq + j + 1) * 72 + row] = __float2half_rn(v.y);
            Tsm[(dq + j + 2) * 72 + row] = __float2half_rn(v.z);
            Tsm[(dq + j + 3) * 72 + row] = __float2half_rn(v.w);
        }
        __half* qo = g_Quh + base + (size_t)(s0 + row) * DHh + dq;
        __half* ko = g_Kh + base + (size_t)(s0 + row) * DHh + dq;
        *(uint4*)qo = *(uint4*)&qh[0];
        *(uint4*)(qo + 8) = *(uint4*)&qh[4];
        *(uint4*)ko = *(uint4*)&kh[0];
        *(uint4*)(ko + 8) = *(uint4*)&kh[4];
        __syncthreads();
        // write transposed V: rows d, cols s
        int d = tid >> 2;
        int sc = (tid & 3) * 16;
        __half* vo = g_Vh + (size_t)hn * DHh * Ss + (size_t)d * Ss + s0 + sc;
        *(uint4*)vo = *(uint4*)&Tsm[d * 72 + sc];
        *(uint4*)(vo + 8) = *(uint4*)&Tsm[d * 72 + sc + 8];
    } else {
        // -------- rproj: inline sincos enc, tf32 mma, fp16 output --------
        float* As = (float*)sA;              // [64][36]
        float* Bsm = (float*)(sA + 9216);    // [64][36]
        float* scr = (float*)(sA + 18432);   // [2][64]

        int idx = blockIdx.x - 256;
        int p0 = (idx & 31) * 64;
        int h = idx >> 5;
        int c0 = h * 64;

        int warp = tid >> 5, lane = tid & 31;
        int g = lane >> 2, tg = lane & 3;
        int wm = (warp & 3) * 16;
        int wn = warp >> 2;

        float acc[4][4] = {};
        const float coef = -9.210340371976184f / 512.0f;

        for (int j0 = 0; j0 < Dd; j0 += 32) {
            __syncthreads();
#pragma unroll
            for (int r = 0; r < 4; r++) {
                int q = tid + r * 256;
                int row = q >> 4, pj = q & 15;
                float pos = (float)(1023 - (p0 + row));
                float invf = __expf((float)(j0 + 2 * pj) * coef);
                float s, c;
                sincosf(pos * invf, &s, &c);
                float2 v; v.x = tf32f(s); v.y = tf32f(c);
                *(float2*)&As[row * 36 + 2 * pj] = v;
            }
#pragma unroll
            for (int r = 0; r < 2; r++) {
                int q2 = tid + r * 256;
                int row = q2 >> 3, qq = q2 & 7;
                float4 w = *(const float4*)&W[(size_t)(c0 + row) * Dd + j0 + 4 * qq];
                float4 o; o.x = tf32f(w.x); o.y = tf32f(w.y);
                o.z = tf32f(w.z); o.w = tf32f(w.w);
                *(float4*)&Bsm[row * 36 + 4 * qq] = o;
            }
            __syncthreads();
#pragma unroll
            for (int k0 = 0; k0 < 32; k0 += 8) {
                unsigned a0 = __float_as_uint(As[(wm + g) * 36 + k0 + tg]);
                unsigned a1 = __float_as_uint(As[(wm + g + 8) * 36 + k0 + tg]);
                unsigned a2 = __float_as_uint(As[(wm + g) * 36 + k0 + tg + 4]);
                unsigned a3 = __float_as_uint(As[(wm + g + 8) * 36 + k0 + tg + 4]);
#pragma unroll
                for (int nt = 0; nt < 4; nt++) {
                    int n0 = wn * 32 + nt * 8;
                    unsigned b0 = __float_as_uint(Bsm[(n0 + g) * 36 + k0 + tg]);
                    unsigned b1 = __float_as_uint(Bsm[(n0 + g) * 36 + k0 + tg + 4]);
                    mma_tf32(acc[nt], a0, a1, a2, a3, b0, b1);
                }
            }
        }
        int pA = p0 + wm + g, pB = pA + 8;
        __half* Rh = g_Rh + (size_t)h * (Pp * DHh);
#pragma unroll
        for (int nt = 0; nt < 4; nt++) {
            int n0 = wn * 32 + nt * 8;
            if (pA < Pp)
                *(__half2*)&Rh[(size_t)pA * DHh + n0 + 2 * tg] =
                    __floats2half2_rn(acc[nt][0], acc[nt][1]);
            if (pB < Pp)
                *(__half2*)&Rh[(size_t)pB * DHh + n0 + 2 * tg] =
                    __floats2half2_rn(acc[nt][2], acc[nt][3]);
        }
        // g_T[h][p] = (v_bias - u_bias) . R[h][p][:]
        float localA = 0.0f, localB = 0.0f;
#pragma unroll
        for (int nt = 0; nt < 4; nt++) {
            int n0 = wn * 32 + nt * 8;
            float2 u2 = *(const float2*)&u_bias[h * DHh + n0 + 2 * tg];
            float2 v2 = *(const float2*)&v_bias[h * DHh + n0 + 2 * tg];
            float db0 = v2.x - u2.x, db1 = v2.y - u2.y;
            localA += acc[nt][0] * db0 + acc[nt][1] * db1;
            localB += acc[nt][2] * db0 + acc[nt][3] * db1;
        }
        localA += __shfl_xor_sync(0xffffffffu, localA, 1);
        localA += __shfl_xor_sync(0xffffffffu, localA, 2);
        localB += __shfl_xor_sync(0xffffffffu, localB, 1);
        localB += __shfl_xor_sync(0xffffffffu, localB, 2);
        if (tg == 0) {
            scr[wn * 64 + wm + g] = localA;
            scr[wn * 64 + wm + g + 8] = localB;
        }
        __syncthreads();
        if (tid < 64 && p0 + tid < Pp)
            g_T[h * TPAD + p0 + tid] = scr[tid] + scr[64 + tid];
    }
}

// ---------------------------------------------------------------------------
// Attention: 512 threads, grid (8,16), paired qtiles {15-bx, bx}.
// All-fp16 MMAs (AC, BD, PV), k-split PV + warp-local softmax,
// cp.async double-buffered staging, P packed to half2 in registers.
// ---------------------------------------------------------------------------
// smem layout (bytes):
#define SQU_B 0                     // Qu fp16 [64][72]     9216
#define SKH_B 9216                  // K ring 2x[64][72]h  18432
#define SRH_B 27648                 // R ring 2x[64][72]h  18432
#define SVT_B 46080                 // Vt ring 2x[64][72]h 18432 (rows=d, cols=kj)
#define SBS_B 64512                 // BD ring 2x[64][68]f 34816
#define SMEM_BYTES 99328
// epilogue overlay (bytes): Xo 4x64x68 f, m/l 4x64 f
#define EPX_B 0
#define EPM_B 69632
#define EPL_B 70656

__global__ void __launch_bounds__(512) attn_kernel(float* __restrict__ out)
{
    extern __shared__ char smc[];
    __half* Quh = (__half*)(smc + SQU_B);
    __half* Khs = (__half*)(smc + SKH_B);
    __half* Rhs = (__half*)(smc + SRH_B);
    __half* Vts = (__half*)(smc + SVT_B);
    float*  Bs  = (float*)(smc + SBS_B);
    unsigned smb = (unsigned)__cvta_generic_to_shared(smc);

    int tid = threadIdx.x;
    int lane = tid & 31;
    int warp = tid >> 5;
    int g = lane >> 2, tg = lane & 3;
    int wm = (warp & 3) * 16;
    int wn = warp >> 2;             // 0..3: this warp's 16-col k-slice
    int rA = wm + g, rB = wm + g + 8;

    int bx = blockIdx.x;
    int head = blockIdx.y;
    int n = head >> 3, h = head & 7;
    int hn = head;

    size_t hoff = (size_t)hn * Ss * DHh;
    const __half* qug = g_Quh + hoff;
    const __half* khg = g_Kh + hoff;
    const __half* vtg = g_Vh + (size_t)hn * DHh * Ss;   // [d][s]
    const __half* Rhg = g_Rh + (size_t)h * (Pp * DHh);
    const float*  Th  = g_T + (size_t)h * TPAD;

    int row8 = tid >> 3, ch8 = tid & 7;     // 64 rows x 8 chunks of 16B

    const float scale = 0.125f;

    for (int ph = 0; ph < 2; ph++) {
        int qt = (ph == 0) ? (15 - bx) : bx;
        int i0 = qt * 64;
        int pb0 = (Ss - 1) - i0 - 63;

        __syncthreads();   // previous phase epilogue fully consumed

        // ---- async prologue: Qu, K/Vt tile 0, R rows 0..127 ----
        cpa16(smb + SQU_B + row8 * 144 + ch8 * 16,
              qug + (size_t)(i0 + row8) * DHh + ch8 * 8);
        cpa16(smb + SKH_B + row8 * 144 + ch8 * 16,
              khg + (size_t)row8 * DHh + ch8 * 8);
        cpa16(smb + SVT_B + row8 * 144 + ch8 * 16,
              vtg + (size_t)row8 * Ss + ch8 * 8);
#pragma unroll
        for (int r = 0; r < 2; r++) {
            int row = row8 + r * 64;     // 0..127 contiguous over R ring
            cpa16(smb + SRH_B + row * 144 + ch8 * 16,
                  Rhg + (size_t)(pb0 + row) * DHh + ch8 * 8);
        }
        CP_COMMIT();

        float mA_run = -1e30f, mB_run = -1e30f;
        float lA_run = 0.0f, lB_run = 0.0f;
        float O[8][4];
#pragma unroll
        for (int a = 0; a < 8; a++)
#pragma unroll
            for (int b = 0; b < 4; b++) O[a][b] = 0.0f;

        for (int kt = 0; kt <= qt; kt++) {
            int j0 = kt * 64;
            int pbase = (Ss - 1) - i0 + j0 - 63;
            int bufLow = kt & 1, bufHigh = bufLow ^ 1;

            CP_WAIT0();
            __syncthreads();   // S1: tiles for kt landed + prev compute done

            // prefetch next K/Vt
            if (kt < qt) {
                int jn = j0 + 64;
                cpa16(smb + SKH_B + bufHigh * 9216 + row8 * 144 + ch8 * 16,
                      khg + (size_t)(jn + row8) * DHh + ch8 * 8);
                cpa16(smb + SVT_B + bufHigh * 9216 + row8 * 144 + ch8 * 16,
                      vtg + (size_t)row8 * Ss + jn + ch8 * 8);
                CP_COMMIT();
            }

            const __half* Khb = Khs + bufLow * 4608;
            const __half* Vtb = Vts + bufLow * 4608;

            float2 tv[4];
            if (kt == 0) {
#pragma unroll
                for (int nt = 0; nt < 4; nt++)
                    tv[nt] = *(const float2*)&Th[pbase + wn * 32 + nt * 8 + 2 * tg];
            } else {
#pragma unroll
                for (int nt = 0; nt < 2; nt++)
                    tv[nt] = *(const float2*)&Th[pbase + 64 + wn * 16 + nt * 8 + 2 * tg];
            }

            // ---- merged AC + BD, fp16 m16n8k16 ----
            float cS[2][4];
#pragma unroll
            for (int t = 0; t < 2; t++)
#pragma unroll
                for (int e = 0; e < 4; e++) cS[t][e] = 0.0f;

            if (kt == 0) {
                float cB[4][4];
#pragma unroll
                for (int t = 0; t < 4; t++)
#pragma unroll
                    for (int e = 0; e < 4; e++) cB[t][e] = 0.0f;
#pragma unroll
                for (int k0 = 0; k0 < 64; k0 += 16) {
                    unsigned a0 = ldh(&Quh[rA * 72 + k0 + 2 * tg]);
                    unsigned a1 = ldh(&Quh[rB * 72 + k0 + 2 * tg]);
                    unsigned a2 = ldh(&Quh[rA * 72 + k0 + 8 + 2 * tg]);
                    unsigned a3 = ldh(&Quh[rB * 72 + k0 + 8 + 2 * tg]);
#pragma unroll
                    for (int nt = 0; nt < 2; nt++) {
                        int n0 = wn * 16 + nt * 8;
                        unsigned b0 = ldh(&Khb[(n0 + g) * 72 + k0 + 2 * tg]);
                        unsigned b1 = ldh(&Khb[(n0 + g) * 72 + k0 + 8 + 2 * tg]);
                        mma_f16(cS[nt], a0, a1, a2, a3, b0, b1);
                    }
#pragma unroll
                    for (int nt = 0; nt < 4; nt++) {
                        int o0 = wn * 32 + nt * 8;
                        unsigned b0 = ldh(&Rhs[(o0 + g) * 72 + k0 + 2 * tg]);
                        unsigned b1 = ldh(&Rhs[(o0 + g) * 72 + k0 + 8 + 2 * tg]);
                        mma_f16(cB[nt], a0, a1, a2, a3, b0, b1);
                    }
                }
#pragma unroll
                for (int nt = 0; nt < 4; nt++) {
                    int o0 = wn * 32 + nt * 8;
                    float* Bd = Bs + (o0 >> 6) * 4352 + (o0 & 63) + 2 * tg;
                    *(float2*)&Bd[rA * 68] = make_float2(cB[nt][0] + tv[nt].x, cB[nt][1] + tv[nt].y);
                    *(float2*)&Bd[rB * 68] = make_float2(cB[nt][2] + tv[nt].x, cB[nt][3] + tv[nt].y);
                }
            } else {
                float cB[2][4];
#pragma unroll
                for (int t = 0; t < 2; t++)
#pragma unroll
                    for (int e = 0; e < 4; e++) cB[t][e] = 0.0f;
                const __half* Rb = Rhs + bufHigh * 4608;
#pragma unroll
                for (int k0 = 0; k0 < 64; k0 += 16) {
                    unsigned a0 = ldh(&Quh[rA * 72 + k0 + 2 * tg]);
                    unsigned a1 = ldh(&Quh[rB * 72 + k0 + 2 * tg]);
                    unsigned a2 = ldh(&Quh[rA * 72 + k0 + 8 + 2 * tg]);
                    unsigned a3 = ldh(&Quh[rB * 72 + k0 + 8 + 2 * tg]);
#pragma unroll
                    for (int nt = 0; nt < 2; nt++) {
                        int n0 = wn * 16 + nt * 8;
                        unsigned b0 = ldh(&Khb[(n0 + g) * 72 + k0 + 2 * tg]);
                        unsigned b1 = ldh(&Khb[(n0 + g) * 72 + k0 + 8 + 2 * tg]);
                        mma_f16(cS[nt], a0, a1, a2, a3, b0, b1);
                    }
#pragma unroll
                    for (int nt = 0; nt < 2; nt++) {
                        int r0 = wn * 16 + nt * 8;
                        unsigned b0 = ldh(&Rb[(r0 + g) * 72 + k0 + 2 * tg]);
                        unsigned b1 = ldh(&Rb[(r0 + g) * 72 + k0 + 8 + 2 * tg]);
                        mma_f16(cB[nt], a0, a1, a2, a3, b0, b1);
                    }
                }
                float* Bd0 = Bs + bufHigh * 4352;
#pragma unroll
                for (int nt = 0; nt < 2; nt++) {
                    int r0 = wn * 16 + nt * 8;
                    float* Bd = Bd0 + r0 + 2 * tg;
                    *(float2*)&Bd[rA * 68] = make_float2(cB[nt][0] + tv[nt].x, cB[nt][1] + tv[nt].y);
                    *(float2*)&Bd[rB * 68] = make_float2(cB[nt][2] + tv[nt].x, cB[nt][3] + tv[nt].y);
                }
            }
            __syncthreads();   // S3: Bs visible; R[bufLow] now MMA-dead

            // prefetch next R rows into the retiring buffer
            if (kt < qt) {
                cpa16(smb + SRH_B + bufLow * 9216 + row8 * 144 + ch8 * 16,
                      Rhg + (size_t)(pbase + 128 + row8) * DHh + ch8 * 8);
                CP_COMMIT();
            }

            // ---- scores + warp-local online softmax ----
            float sv[2][4];
            float mAl = -INFINITY, mBl = -INFINITY;
            int diag = (kt == qt);
#pragma unroll
            for (int nt = 0; nt < 2; nt++) {
                int colbase = wn * 16 + nt * 8 + 2 * tg;
#pragma unroll
                for (int e = 0; e < 4; e++) {
                    int j = colbase + (e & 1);
                    int row = (e < 2) ? rA : rB;
                    int o = j - row + 63;
                    float bd = Bs[(bufLow ^ (o >> 6)) * 4352 + row * 68 + (o & 63)];
                    float s = (cS[nt][e] + bd) * scale;
                    if (diag && j > row) s = -INFINITY;
                    sv[nt][e] = s;
                    if (e < 2) mAl = fmaxf(mAl, s); else mBl = fmaxf(mBl, s);
                }
            }
            mAl = fmaxf(mAl, __shfl_xor_sync(0xffffffffu, mAl, 1));
            mAl = fmaxf(mAl, __shfl_xor_sync(0xffffffffu, mAl, 2));
            mBl = fmaxf(mBl, __shfl_xor_sync(0xffffffffu, mBl, 1));
            mBl = fmaxf(mBl, __shfl_xor_sync(0xffffffffu, mBl, 2));

            float mgA = fmaxf(mA_run, mAl);
            float mgB = fmaxf(mB_run, mBl);
            float corrA = __expf(mA_run - mgA);
            float corrB = __expf(mB_run - mgB);

            float peA0[2], peA1[2], peB0[2], peB1[2];
            float sumA = 0.0f, sumB = 0.0f;
#pragma unroll
            for (int nt = 0; nt < 2; nt++) {
                peA0[nt] = __expf(sv[nt][0] - mgA);
                peA1[nt] = __expf(sv[nt][1] - mgA);
                peB0[nt] = __expf(sv[nt][2] - mgB);
                peB1[nt] = __expf(sv[nt][3] - mgB);
                sumA += peA0[nt] + peA1[nt];
                sumB += peB0[nt] + peB1[nt];
            }
            sumA += __shfl_xor_sync(0xffffffffu, sumA, 1);
            sumA += __shfl_xor_sync(0xffffffffu, sumA, 2);
            sumB += __shfl_xor_sync(0xffffffffu, sumB, 1);
            sumB += __shfl_xor_sync(0xffffffffu, sumB, 2);
            lA_run = lA_run * corrA + sumA;
            lB_run = lB_run * corrB + sumB;
            mA_run = mgA; mB_run = mgB;

#pragma unroll
            for (int jn = 0; jn < 8; jn++) {
                O[jn][0] *= corrA; O[jn][1] *= corrA;
                O[jn][2] *= corrB; O[jn][3] *= corrB;
            }

            // ---- k-split PV (fp16, P packed directly, zero shuffles) ----
            {
                unsigned a0 = packh2(peA0[0], peA1[0]);
                unsigned a1 = packh2(peB0[0], peB1[0]);
                unsigned a2 = packh2(peA0[1], peA1[1]);
                unsigned a3 = packh2(peB0[1], peB1[1]);
                int kbase = wn * 16;
#pragma unroll
                for (int jn = 0; jn < 8; jn++) {
                    int n0 = jn * 8;
                    unsigned b0 = ldh(&Vtb[(n0 + g) * 72 + kbase + 2 * tg]);
                    unsigned b1 = ldh(&Vtb[(n0 + g) * 72 + kbase + 8 + 2 * tg]);
                    mma_f16(O[jn], a0, a1, a2, a3, b0, b1);
                }
            }
        }

        // ---- split-k merge across the 4 k-slice warps ----
        __syncthreads();
        {
            float* Xo = (float*)(smc + EPX_B);
            float* mArr = (float*)(smc + EPM_B);
            float* lArr = (float*)(smc + EPL_B);
#pragma unroll
            for (int jn = 0; jn < 8; jn++) {
                int n0 = jn * 8;
                *(float2*)&Xo[wn * 4352 + rA * 68 + n0 + 2 * tg] =
                    make_float2(O[jn][0], O[jn][1]);
                *(float2*)&Xo[wn * 4352 + rB * 68 + n0 + 2 * tg] =
                    make_float2(O[jn][2], O[jn][3]);
            }
            if (tg == 0) {
                mArr[wn * 64 + rA] = mA_run; lArr[wn * 64 + rA] = lA_run;
                mArr[wn * 64 + rB] = mB_run; lArr[wn * 64 + rB] = lB_run;
            }
            __syncthreads();

            int row = tid >> 3, cb = (tid & 7) * 8;
            float m0 = mArr[row], m1 = mArr[64 + row];
            float m2 = mArr[128 + row], m3 = mArr[192 + row];
            float mg = fmaxf(fmaxf(m0, m1), fmaxf(m2, m3));
            float f0 = __expf(m0 - mg), f1 = __expf(m1 - mg);
            float f2 = __expf(m2 - mg), f3 = __expf(m3 - mg);
            float lg = lArr[row] * f0 + lArr[64 + row] * f1
                     + lArr[128 + row] * f2 + lArr[192 + row] * f3;
            float inv = 1.0f / lg;
            float* op = out + hoff + (size_t)(i0 + row) * DHh + cb;
#pragma unroll
            for (int c = 0; c < 8; c += 4) {
                float4 x0 = *(const float4*)&Xo[0 * 4352 + row * 68 + cb + c];
                float4 x1 = *(const float4*)&Xo[1 * 4352 + row * 68 + cb + c];
                float4 x2 = *(const float4*)&Xo[2 * 4352 + row * 68 + cb + c];
                float4 x3 = *(const float4*)&Xo[3 * 4352 + row * 68 + cb + c];
                float4 o4;
                o4.x = (x0.x * f0 + x1.x * f1 + x2.x * f2 + x3.x * f3) * inv;
                o4.y = (x0.y * f0 + x1.y * f1 + x2.y * f2 + x3.y * f3) * inv;
                o4.z = (x0.z * f0 + x1.z * f1 + x2.z * f2 + x3.z * f3) * inv;
                o4.w = (x0.w * f0 + x1.w * f1 + x2.w * f2 + x3.w * f3) * inv;
                *(float4*)&op[c] = o4;
            }
        }
    }
}

// ---------------------------------------------------------------------------
extern "C" void kernel_launch(void* const* d_in, const int* in_sizes, int n_in,
                              void* d_out, int out_size) {
    const float* seqs   = (const float*)d_in[0];
    const float* keys   = (const float*)d_in[1];
    const float* values = (const float*)d_in[2];
    const float* u_bias = (const float*)d_in[3];
    const float* v_bias = (const float*)d_in[4];
    const float* rproj  = (const float*)d_in[5];
    (void)in_sizes; (void)n_in; (void)out_size;

    cudaFuncSetAttribute(attn_kernel, cudaFuncAttributeMaxDynamicSharedMemorySize,
                         SMEM_BYTES);

    prologue_kernel<<<512, 256>>>(seqs, keys, values, u_bias, v_bias, rproj);
    attn_kernel<<<dim3(8, 16), 512, SMEM_BYTES>>>((float*)d_out);
}

// round 12
// speedup vs baseline: 1.6152x; 1.0563x over previous
#include <cuda_runtime.h>
#include <cuda_fp16.h>
#include <math.h>

#define Nn 2
#define Hh 8
#define Ss 1024
#define DHh 64
#define Dd 512
#define Pp 2047   // 2S-1
#define TPAD 2048 // padded head stride for g_T

__device__ float g_ENC[Pp * Dd];
__device__ __half g_Rh[Hh * Pp * DHh];        // rounded fp16 R
__device__ __half g_Quh[Nn * Hh * Ss * DHh];  // rounded fp16 (seqs + u_bias)
__device__ __half g_Kh[Nn * Hh * Ss * DHh];   // rounded fp16 keys
__device__ __half g_Vh[Nn * Hh * DHh * Ss];   // rounded fp16 V TRANSPOSED [hn][d][s]
__device__ float g_T[Hh * TPAD];

__device__ __forceinline__ unsigned f2tf(float x) {
    unsigned r;
    asm("cvt.rna.tf32.f32 %0, %1;" : "=r"(r) : "f"(x));
    return r;
}
__device__ __forceinline__ float tf32f(float x) { return __uint_as_float(f2tf(x)); }
__device__ __forceinline__ void mma_tf32(float c[4], unsigned a0, unsigned a1,
                                         unsigned a2, unsigned a3,
                                         unsigned b0, unsigned b1) {
    asm volatile(
        "mma.sync.aligned.m16n8k8.row.col.f32.tf32.tf32.f32 "
        "{%0,%1,%2,%3},{%4,%5,%6,%7},{%8,%9},{%0,%1,%2,%3};"
        : "+f"(c[0]), "+f"(c[1]), "+f"(c[2]), "+f"(c[3])
        : "r"(a0), "r"(a1), "r"(a2), "r"(a3), "r"(b0), "r"(b1));
}
__device__ __forceinline__ void mma_f16(float c[4], unsigned a0, unsigned a1,
                                        unsigned a2, unsigned a3,
                                        unsigned b0, unsigned b1) {
    asm volatile(
        "mma.sync.aligned.m16n8k16.row.col.f32.f16.f16.f32 "
        "{%0,%1,%2,%3},{%4,%5,%6,%7},{%8,%9},{%0,%1,%2,%3};"
        : "+f"(c[0]), "+f"(c[1]), "+f"(c[2]), "+f"(c[3])
        : "r"(a0), "r"(a1), "r"(a2), "r"(a3), "r"(b0), "r"(b1));
}
__device__ __forceinline__ unsigned ldh(const __half* p) { return *(const unsigned*)p; }
__device__ __forceinline__ unsigned packh2(float a, float b) {
    __half2 t = __floats2half2_rn(a, b);
    return reinterpret_cast<unsigned&>(t);
}
__device__ __forceinline__ void cpa16(unsigned dst, const void* src) {
    asm volatile("cp.async.cg.shared.global [%0], [%1], 16;" :: "r"(dst), "l"(src));
}
#define CP_COMMIT() asm volatile("cp.async.commit_group;")
#define CP_WAIT0()  asm volatile("cp.async.wait_group 0;")

// ---------------------------------------------------------------------------
// Kernel A: blocks 0..63  -> enc by incremental rotation (cheap)
//           blocks 64..319 -> cvt Q/K fp16 + V transpose fp16
// ---------------------------------------------------------------------------
__global__ void __launch_bounds__(256) enc_cvt_kernel(
    const float* __restrict__ seqs, const float* __restrict__ keys,
    const float* __restrict__ values, const float* __restrict__ u_bias)
{
    __shared__ __align__(16) __half Tsm[64 * 72];
    int tid = threadIdx.x;

    if (blockIdx.x < 64) {
        // -------- enc: incremental rotation, 32 p-steps per block --------
        int i = tid;                      // freq index 0..255
        int p0 = blockIdx.x * 32;
        int steps = Pp - p0; if (steps > 32) steps = 32;
        const float coef = -9.210340371976184f / 512.0f;
        float invf = __expf((float)(2 * i) * coef);
        float s, c;
        sincosf((float)(1023 - p0) * invf, &s, &c);
        float rs, rc;
        sincosf(invf, &rs, &rc);
        for (int t = 0; t < steps; t++) {
            *(float2*)&g_ENC[(size_t)(p0 + t) * Dd + 2 * i] = make_float2(s, c);
            float s2 = s * rc - c * rs;
            float c2 = c * rc + s * rs;
            s = s2; c = c2;
        }
    } else {
        // -------- cvt: one (head, s-tile) of 64 rows --------
        int bid = blockIdx.x - 64;
        int hn = bid & 15;               // n*8+h
        int h = hn & 7;
        int s0 = (bid >> 4) * 64;
        size_t base = (size_t)hn * Ss * DHh;

        int row = tid >> 2;              // 0..63
        int dq = (tid & 3) * 16;         // 0,16,32,48
        const float* qp = seqs + base + (size_t)(s0 + row) * DHh + dq;
        const float* kp = keys + base + (size_t)(s0 + row) * DHh + dq;
        const float* vp = values + base + (size_t)(s0 + row) * DHh + dq;
        unsigned qh[8], kh[8];
#pragma unroll
        for (int j = 0; j < 16; j += 4) {
            float4 q = *(const float4*)(qp + j);
            float4 u = *(const float4*)&u_bias[h * DHh + dq + j];
            float4 k = *(const float4*)(kp + j);
            float4 v = *(const float4*)(vp + j);
            qh[j / 2]     = packh2(q.x + u.x, q.y + u.y);
            qh[j / 2 + 1] = packh2(q.z + u.z, q.w + u.w);
            kh[j / 2]     = packh2(k.x, k.y);
            kh[j / 2 + 1] = packh2(k.z, k.w);
            Tsm[(dq + j + 0) * 72 + row] = __float2half_rn(v.x);
            Tsm[(dq + j + 1) * 72 + row] = __float2half_rn(v.y);
            Tsm[(dq + j + 2) * 72 + row] = __float2half_rn(v.z);
            Tsm[(dq + j + 3) * 72 + row] = __float2half_rn(v.w);
        }
        __half* qo = g_Quh + base + (size_t)(s0 + row) * DHh + dq;
        __half* ko = g_Kh + base + (size_t)(s0 + row) * DHh + dq;
        *(uint4*)qo = *(uint4*)&qh[0];
        *(uint4*)(qo + 8) = *(uint4*)&qh[4];
        *(uint4*)ko = *(uint4*)&kh[0];
        *(uint4*)(ko + 8) = *(uint4*)&kh[4];
        __syncthreads();
        int d = tid >> 2;
        int sc = (tid & 3) * 16;
        __half* vo = g_Vh + (size_t)hn * DHh * Ss + (size_t)d * Ss + s0 + sc;
        *(uint4*)vo = *(uint4*)&Tsm[d * 72 + sc];
        *(uint4*)(vo + 8) = *(uint4*)&Tsm[d * 72 + sc + 8];
    }
}

// ---------------------------------------------------------------------------
// Kernel B: r-projection (tf32 mma, reads g_ENC) -> fp16 g_Rh + rank-1 g_T.
// ---------------------------------------------------------------------------
__global__ void __launch_bounds__(256) rproj_mma_kernel(
    const float* __restrict__ W, const float* __restrict__ u_bias,
    const float* __restrict__ v_bias)
{
    __shared__ float As[64 * 36];
    __shared__ float Bsm[64 * 36];
    __shared__ float scr[2 * 64];

    int tid = threadIdx.x;
    int warp = tid >> 5, lane = tid & 31;
    int g = lane >> 2, tg = lane & 3;
    int wm = (warp & 3) * 16;
    int wn = warp >> 2;

    int p0 = blockIdx.x * 64;
    int h = blockIdx.y;
    int c0 = h * 64;

    float acc[4][4] = {};

    for (int j0 = 0; j0 < Dd; j0 += 32) {
        __syncthreads();
#pragma unroll
        for (int r = 0; r < 2; r++) {
            int q = tid + r * 256;
            int row = q >> 3, qq = q & 7;
            int p = p0 + row;
            float4 e = make_float4(0.f, 0.f, 0.f, 0.f);
            if (p < Pp) e = *(const float4*)&g_ENC[(size_t)p * Dd + j0 + 4 * qq];
            float4 o; o.x = tf32f(e.x); o.y = tf32f(e.y); o.z = tf32f(e.z); o.w = tf32f(e.w);
            *(float4*)&As[row * 36 + 4 * qq] = o;
        }
#pragma unroll
        for (int r = 0; r < 2; r++) {
            int q2 = tid + r * 256;
            int row = q2 >> 3, qq = q2 & 7;
            float4 w = *(const float4*)&W[(size_t)(c0 + row) * Dd + j0 + 4 * qq];
            float4 o; o.x = tf32f(w.x); o.y = tf32f(w.y); o.z = tf32f(w.z); o.w = tf32f(w.w);
            *(float4*)&Bsm[row * 36 + 4 * qq] = o;
        }
        __syncthreads();
#pragma unroll
        for (int k0 = 0; k0 < 32; k0 += 8) {
            unsigned a0 = __float_as_uint(As[(wm + g) * 36 + k0 + tg]);
            unsigned a1 = __float_as_uint(As[(wm + g + 8) * 36 + k0 + tg]);
            unsigned a2 = __float_as_uint(As[(wm + g) * 36 + k0 + tg + 4]);
            unsigned a3 = __float_as_uint(As[(wm + g + 8) * 36 + k0 + tg + 4]);
#pragma unroll
            for (int nt = 0; nt < 4; nt++) {
                int n0 = wn * 32 + nt * 8;
                unsigned b0 = __float_as_uint(Bsm[(n0 + g) * 36 + k0 + tg]);
                unsigned b1 = __float_as_uint(Bsm[(n0 + g) * 36 + k0 + tg + 4]);
                mma_tf32(acc[nt], a0, a1, a2, a3, b0, b1);
            }
        }
    }
    int pA = p0 + wm + g, pB = pA + 8;
    __half* Rh = g_Rh + (size_t)h * (Pp * DHh);
#pragma unroll
    for (int nt = 0; nt < 4; nt++) {
        int n0 = wn * 32 + nt * 8;
        if (pA < Pp)
            *(__half2*)&Rh[(size_t)pA * DHh + n0 + 2 * tg] =
                __floats2half2_rn(acc[nt][0], acc[nt][1]);
        if (pB < Pp)
            *(__half2*)&Rh[(size_t)pB * DHh + n0 + 2 * tg] =
                __floats2half2_rn(acc[nt][2], acc[nt][3]);
    }

    // g_T[h][p] = (v_bias - u_bias) . R[h][p][:]
    float localA = 0.0f, localB = 0.0f;
#pragma unroll
    for (int nt = 0; nt < 4; nt++) {
        int n0 = wn * 32 + nt * 8;
        float2 u2 = *(const float2*)&u_bias[h * DHh + n0 + 2 * tg];
        float2 v2 = *(const float2*)&v_bias[h * DHh + n0 + 2 * tg];
        float db0 = v2.x - u2.x, db1 = v2.y - u2.y;
        localA += acc[nt][0] * db0 + acc[nt][1] * db1;
        localB += acc[nt][2] * db0 + acc[nt][3] * db1;
    }
    localA += __shfl_xor_sync(0xffffffffu, localA, 1);
    localA += __shfl_xor_sync(0xffffffffu, localA, 2);
    localB += __shfl_xor_sync(0xffffffffu, localB, 1);
    localB += __shfl_xor_sync(0xffffffffu, localB, 2);
    if (tg == 0) {
        scr[wn * 64 + wm + g] = localA;
        scr[wn * 64 + wm + g + 8] = localB;
    }
    __syncthreads();
    if (tid < 64 && p0 + tid < Pp)
        g_T[h * TPAD + p0 + tid] = scr[tid] + scr[64 + tid];
}

// ---------------------------------------------------------------------------
// Kernel C: attention (unchanged from R11's verified 41 µs version).
// ---------------------------------------------------------------------------
#define SQU_B 0                     // Qu fp16 [64][72]     9216
#define SKH_B 9216                  // K ring 2x[64][72]h  18432
#define SRH_B 27648                 // R ring 2x[64][72]h  18432
#define SVT_B 46080                 // Vt ring 2x[64][72]h 18432 (rows=d, cols=kj)
#define SBS_B 64512                 // BD ring 2x[64][68]f 34816
#define SMEM_BYTES 99328
#define EPX_B 0
#define EPM_B 69632
#define EPL_B 70656

__global__ void __launch_bounds__(512) attn_kernel(float* __restrict__ out)
{
    extern __shared__ char smc[];
    __half* Quh = (__half*)(smc + SQU_B);
    __half* Khs = (__half*)(smc + SKH_B);
    __half* Rhs = (__half*)(smc + SRH_B);
    __half* Vts = (__half*)(smc + SVT_B);
    float*  Bs  = (float*)(smc + SBS_B);
    unsigned smb = (unsigned)__cvta_generic_to_shared(smc);

    int tid = threadIdx.x;
    int lane = tid & 31;
    int warp = tid >> 5;
    int g = lane >> 2, tg = lane & 3;
    int wm = (warp & 3) * 16;
    int wn = warp >> 2;
    int rA = wm + g, rB = wm + g + 8;

    int bx = blockIdx.x;
    int head = blockIdx.y;
    int h = head & 7;
    int hn = head;

    size_t hoff = (size_t)hn * Ss * DHh;
    const __half* qug = g_Quh + hoff;
    const __half* khg = g_Kh + hoff;
    const __half* vtg = g_Vh + (size_t)hn * DHh * Ss;
    const __half* Rhg = g_Rh + (size_t)h * (Pp * DHh);
    const float*  Th  = g_T + (size_t)h * TPAD;

    int row8 = tid >> 3, ch8 = tid & 7;

    const float scale = 0.125f;

    for (int ph = 0; ph < 2; ph++) {
        int qt = (ph == 0) ? (15 - bx) : bx;
        int i0 = qt * 64;
        int pb0 = (Ss - 1) - i0 - 63;

        __syncthreads();

        cpa16(smb + SQU_B + row8 * 144 + ch8 * 16,
              qug + (size_t)(i0 + row8) * DHh + ch8 * 8);
        cpa16(smb + SKH_B + row8 * 144 + ch8 * 16,
              khg + (size_t)row8 * DHh + ch8 * 8);
        cpa16(smb + SVT_B + row8 * 144 + ch8 * 16,
              vtg + (size_t)row8 * Ss + ch8 * 8);
#pragma unroll
        for (int r = 0; r < 2; r++) {
            int row = row8 + r * 64;
            cpa16(smb + SRH_B + row * 144 + ch8 * 16,
                  Rhg + (size_t)(pb0 + row) * DHh + ch8 * 8);
        }
        CP_COMMIT();

        float mA_run = -1e30f, mB_run = -1e30f;
        float lA_run = 0.0f, lB_run = 0.0f;
        float O[8][4];
#pragma unroll
        for (int a = 0; a < 8; a++)
#pragma unroll
            for (int b = 0; b < 4; b++) O[a][b] = 0.0f;

        for (int kt = 0; kt <= qt; kt++) {
            int j0 = kt * 64;
            int pbase = (Ss - 1) - i0 + j0 - 63;
            int bufLow = kt & 1, bufHigh = bufLow ^ 1;

            CP_WAIT0();
            __syncthreads();

            if (kt < qt) {
                int jn = j0 + 64;
                cpa16(smb + SKH_B + bufHigh * 9216 + row8 * 144 + ch8 * 16,
                      khg + (size_t)(jn + row8) * DHh + ch8 * 8);
                cpa16(smb + SVT_B + bufHigh * 9216 + row8 * 144 + ch8 * 16,
                      vtg + (size_t)row8 * Ss + jn + ch8 * 8);
                CP_COMMIT();
            }

            const __half* Khb = Khs + bufLow * 4608;
            const __half* Vtb = Vts + bufLow * 4608;

            float2 tv[4];
            if (kt == 0) {
#pragma unroll
                for (int nt = 0; nt < 4; nt++)
                    tv[nt] = *(const float2*)&Th[pbase + wn * 32 + nt * 8 + 2 * tg];
            } else {
#pragma unroll
                for (int nt = 0; nt < 2; nt++)
                    tv[nt] = *(const float2*)&Th[pbase + 64 + wn * 16 + nt * 8 + 2 * tg];
            }

            float cS[2][4];
#pragma unroll
            for (int t = 0; t < 2; t++)
#pragma unroll
                for (int e = 0; e < 4; e++) cS[t][e] = 0.0f;

            if (kt == 0) {
                float cB[4][4];
#pragma unroll
                for (int t = 0; t < 4; t++)
#pragma unroll
                    for (int e = 0; e < 4; e++) cB[t][e] = 0.0f;
#pragma unroll
                for (int k0 = 0; k0 < 64; k0 += 16) {
                    unsigned a0 = ldh(&Quh[rA * 72 + k0 + 2 * tg]);
                    unsigned a1 = ldh(&Quh[rB * 72 + k0 + 2 * tg]);
                    unsigned a2 = ldh(&Quh[rA * 72 + k0 + 8 + 2 * tg]);
                    unsigned a3 = ldh(&Quh[rB * 72 + k0 + 8 + 2 * tg]);
#pragma unroll
                    for (int nt = 0; nt < 2; nt++) {
                        int n0 = wn * 16 + nt * 8;
                        unsigned b0 = ldh(&Khb[(n0 + g) * 72 + k0 + 2 * tg]);
                        unsigned b1 = ldh(&Khb[(n0 + g) * 72 + k0 + 8 + 2 * tg]);
                        mma_f16(cS[nt], a0, a1, a2, a3, b0, b1);
                    }
#pragma unroll
                    for (int nt = 0; nt < 4; nt++) {
                        int o0 = wn * 32 + nt * 8;
                        unsigned b0 = ldh(&Rhs[(o0 + g) * 72 + k0 + 2 * tg]);
                        unsigned b1 = ldh(&Rhs[(o0 + g) * 72 + k0 + 8 + 2 * tg]);
                        mma_f16(cB[nt], a0, a1, a2, a3, b0, b1);
                    }
                }
#pragma unroll
                for (int nt = 0; nt < 4; nt++) {
                    int o0 = wn * 32 + nt * 8;
                    float* Bd = Bs + (o0 >> 6) * 4352 + (o0 & 63) + 2 * tg;
                    *(float2*)&Bd[rA * 68] = make_float2(cB[nt][0] + tv[nt].x, cB[nt][1] + tv[nt].y);
                    *(float2*)&Bd[rB * 68] = make_float2(cB[nt][2] + tv[nt].x, cB[nt][3] + tv[nt].y);
                }
            } else {
                float cB[2][4];
#pragma unroll
                for (int t = 0; t < 2; t++)
#pragma unroll
                    for (int e = 0; e < 4; e++) cB[t][e] = 0.0f;
                const __half* Rb = Rhs + bufHigh * 4608;
#pragma unroll
                for (int k0 = 0; k0 < 64; k0 += 16) {
                    unsigned a0 = ldh(&Quh[rA * 72 + k0 + 2 * tg]);
                    unsigned a1 = ldh(&Quh[rB * 72 + k0 + 2 * tg]);
                    unsigned a2 = ldh(&Quh[rA * 72 + k0 + 8 + 2 * tg]);
                    unsigned a3 = ldh(&Quh[rB * 72 + k0 + 8 + 2 * tg]);
#pragma unroll
                    for (int nt = 0; nt < 2; nt++) {
                        int n0 = wn * 16 + nt * 8;
                        unsigned b0 = ldh(&Khb[(n0 + g) * 72 + k0 + 2 * tg]);
                        unsigned b1 = ldh(&Khb[(n0 + g) * 72 + k0 + 8 + 2 * tg]);
                        mma_f16(cS[nt], a0, a1, a2, a3, b0, b1);
                    }
#pragma unroll
                    for (int nt = 0; nt < 2; nt++) {
                        int r0 = wn * 16 + nt * 8;
                        unsigned b0 = ldh(&Rb[(r0 + g) * 72 + k0 + 2 * tg]);
                        unsigned b1 = ldh(&Rb[(r0 + g) * 72 + k0 + 8 + 2 * tg]);
                        mma_f16(cB[nt], a0, a1, a2, a3, b0, b1);
                    }
                }
                float* Bd0 = Bs + bufHigh * 4352;
#pragma unroll
                for (int nt = 0; nt < 2; nt++) {
                    int r0 = wn * 16 + nt * 8;
                    float* Bd = Bd0 + r0 + 2 * tg;
                    *(float2*)&Bd[rA * 68] = make_float2(cB[nt][0] + tv[nt].x, cB[nt][1] + tv[nt].y);
                    *(float2*)&Bd[rB * 68] = make_float2(cB[nt][2] + tv[nt].x, cB[nt][3] + tv[nt].y);
                }
            }
            __syncthreads();

            if (kt < qt) {
                cpa16(smb + SRH_B + bufLow * 9216 + row8 * 144 + ch8 * 16,
                      Rhg + (size_t)(pbase + 128 + row8) * DHh + ch8 * 8);
                CP_COMMIT();
            }

            float sv[2][4];
            float mAl = -INFINITY, mBl = -INFINITY;
            int diag = (kt == qt);
#pragma unroll
            for (int nt = 0; nt < 2; nt++) {
                int colbase = wn * 16 + nt * 8 + 2 * tg;
#pragma unroll
                for (int e = 0; e < 4; e++) {
                    int j = colbase + (e & 1);
                    int row = (e < 2) ? rA : rB;
                    int o = j - row + 63;
                    float bd = Bs[(bufLow ^ (o >> 6)) * 4352 + row * 68 + (o & 63)];
                    float s = (cS[nt][e] + bd) * scale;
                    if (diag && j > row) s = -INFINITY;
                    sv[nt][e] = s;
                    if (e < 2) mAl = fmaxf(mAl, s); else mBl = fmaxf(mBl, s);
                }
            }
            mAl = fmaxf(mAl, __shfl_xor_sync(0xffffffffu, mAl, 1));
            mAl = fmaxf(mAl, __shfl_xor_sync(0xffffffffu, mAl, 2));
            mBl = fmaxf(mBl, __shfl_xor_sync(0xffffffffu, mBl, 1));
            mBl = fmaxf(mBl, __shfl_xor_sync(0xffffffffu, mBl, 2));

            float mgA = fmaxf(mA_run, mAl);
            float mgB = fmaxf(mB_run, mBl);
            float corrA = __expf(mA_run - mgA);
            float corrB = __expf(mB_run - mgB);

            float peA0[2], peA1[2], peB0[2], peB1[2];
            float sumA = 0.0f, sumB = 0.0f;
#pragma unroll
            for (int nt = 0; nt < 2; nt++) {
                peA0[nt] = __expf(sv[nt][0] - mgA);
                peA1[nt] = __expf(sv[nt][1] - mgA);
                peB0[nt] = __expf(sv[nt][2] - mgB);
                peB1[nt] = __expf(sv[nt][3] - mgB);
                sumA += peA0[nt] + peA1[nt];
                sumB += peB0[nt] + peB1[nt];
            }
            sumA += __shfl_xor_sync(0xffffffffu, sumA, 1);
            sumA += __shfl_xor_sync(0xffffffffu, sumA, 2);
            sumB += __shfl_xor_sync(0xffffffffu, sumB, 1);
            sumB += __shfl_xor_sync(0xffffffffu, sumB, 2);
            lA_run = lA_run * corrA + sumA;
            lB_run = lB_run * corrB + sumB;
            mA_run = mgA; mB_run = mgB;

#pragma unroll
            for (int jn = 0; jn < 8; jn++) {
                O[jn][0] *= corrA; O[jn][1] *= corrA;
                O[jn][2] *= corrB; O[jn][3] *= corrB;
            }

            {
                unsigned a0 = packh2(peA0[0], peA1[0]);
                unsigned a1 = packh2(peB0[0], peB1[0]);
                unsigned a2 = packh2(peA0[1], peA1[1]);
                unsigned a3 = packh2(peB0[1], peB1[1]);
                int kbase = wn * 16;
#pragma unroll
                for (int jn = 0; jn < 8; jn++) {
                    int n0 = jn * 8;
                    unsigned b0 = ldh(&Vtb[(n0 + g) * 72 + kbase + 2 * tg]);
                    unsigned b1 = ldh(&Vtb[(n0 + g) * 72 + kbase + 8 + 2 * tg]);
                    mma_f16(O[jn], a0, a1, a2, a3, b0, b1);
                }
            }
        }

        __syncthreads();
        {
            float* Xo = (float*)(smc + EPX_B);
            float* mArr = (float*)(smc + EPM_B);
            float* lArr = (float*)(smc + EPL_B);
#pragma unroll
            for (int jn = 0; jn < 8; jn++) {
                int n0 = jn * 8;
                *(float2*)&Xo[wn * 4352 + rA * 68 + n0 + 2 * tg] =
                    make_float2(O[jn][0], O[jn][1]);
                *(float2*)&Xo[wn * 4352 + rB * 68 + n0 + 2 * tg] =
                    make_float2(O[jn][2], O[jn][3]);
            }
            if (tg == 0) {
                mArr[wn * 64 + rA] = mA_run; lArr[wn * 64 + rA] = lA_run;
                mArr[wn * 64 + rB] = mB_run; lArr[wn * 64 + rB] = lB_run;
            }
            __syncthreads();

            int row = tid >> 3, cb = (tid & 7) * 8;
            float m0 = mArr[row], m1 = mArr[64 + row];
            float m2 = mArr[128 + row], m3 = mArr[192 + row];
            float mg = fmaxf(fmaxf(m0, m1), fmaxf(m2, m3));
            float f0 = __expf(m0 - mg), f1 = __expf(m1 - mg);
            float f2 = __expf(m2 - mg), f3 = __expf(m3 - mg);
            float lg = lArr[row] * f0 + lArr[64 + row] * f1
                     + lArr[128 + row] * f2 + lArr[192 + row] * f3;
            float inv = 1.0f / lg;
            float* op = out + hoff + (size_t)(i0 + row) * DHh + cb;
#pragma unroll
            for (int c = 0; c < 8; c += 4) {
                float4 x0 = *(const float4*)&Xo[0 * 4352 + row * 68 + cb + c];
                float4 x1 = *(const float4*)&Xo[1 * 4352 + row * 68 + cb + c];
                float4 x2 = *(const float4*)&Xo[2 * 4352 + row * 68 + cb + c];
                float4 x3 = *(const float4*)&Xo[3 * 4352 + row * 68 + cb + c];
                float4 o4;
                o4.x = (x0.x * f0 + x1.x * f1 + x2.x * f2 + x3.x * f3) * inv;
                o4.y = (x0.y * f0 + x1.y * f1 + x2.y * f2 + x3.y * f3) * inv;
                o4.z = (x0.z * f0 + x1.z * f1 + x2.z * f2 + x3.z * f3) * inv;
                o4.w = (x0.w * f0 + x1.w * f1 + x2.w * f2 + x3.w * f3) * inv;
                *(float4*)&op[c] = o4;
            }
        }
    }
}

// ---------------------------------------------------------------------------
extern "C" void kernel_launch(void* const* d_in, const int* in_sizes, int n_in,
                              void* d_out, int out_size) {
    const float* seqs   = (const float*)d_in[0];
    const float* keys   = (const float*)d_in[1];
    const float* values = (const float*)d_in[2];
    const float* u_bias = (const float*)d_in[3];
    const float* v_bias = (const float*)d_in[4];
    const float* rproj  = (const float*)d_in[5];
    (void)in_sizes; (void)n_in; (void)out_size;

    cudaFuncSetAttribute(attn_kernel, cudaFuncAttributeMaxDynamicSharedMemorySize,
                         SMEM_BYTES);

    enc_cvt_kernel<<<320, 256>>>(seqs, keys, values, u_bias);
    rproj_mma_kernel<<<dim3(32, 8), 256>>>(rproj, u_bias, v_bias);
    attn_kernel<<<dim3(8, 16), 512, SMEM_BYTES>>>((float*)d_out);
}

// round 13
// speedup vs baseline: 1.8494x; 1.1450x over previous
#include <cuda_runtime.h>
#include <cuda_fp16.h>
#include <math.h>

#define Nn 2
#define Hh 8
#define Ss 1024
#define DHh 64
#define Dd 512
#define Pp 2047   // 2S-1
#define TPAD 2048 // padded head stride for g_T

__device__ __half g_ENCh[Pp * Dd];            // fp16 positional encodings
__device__ __half g_Rh[Hh * Pp * DHh];        // rounded fp16 R
__device__ __half g_Quh[Nn * Hh * Ss * DHh];  // rounded fp16 (seqs + u_bias)
__device__ __half g_Kh[Nn * Hh * Ss * DHh];   // rounded fp16 keys
__device__ __half g_Vh[Nn * Hh * DHh * Ss];   // rounded fp16 V TRANSPOSED [hn][d][s]
__device__ float g_T[Hh * TPAD];

__device__ __forceinline__ void mma_f16(float c[4], unsigned a0, unsigned a1,
                                        unsigned a2, unsigned a3,
                                        unsigned b0, unsigned b1) {
    asm volatile(
        "mma.sync.aligned.m16n8k16.row.col.f32.f16.f16.f32 "
        "{%0,%1,%2,%3},{%4,%5,%6,%7},{%8,%9},{%0,%1,%2,%3};"
        : "+f"(c[0]), "+f"(c[1]), "+f"(c[2]), "+f"(c[3])
        : "r"(a0), "r"(a1), "r"(a2), "r"(a3), "r"(b0), "r"(b1));
}
__device__ __forceinline__ unsigned ldh(const __half* p) { return *(const unsigned*)p; }
__device__ __forceinline__ unsigned packh2(float a, float b) {
    __half2 t = __floats2half2_rn(a, b);
    return reinterpret_cast<unsigned&>(t);
}
__device__ __forceinline__ void cpa16(unsigned dst, const void* src) {
    asm volatile("cp.async.cg.shared.global [%0], [%1], 16;" :: "r"(dst), "l"(src));
}
#define CP_COMMIT() asm volatile("cp.async.commit_group;")
#define CP_WAIT0()  asm volatile("cp.async.wait_group 0;")

// ---------------------------------------------------------------------------
// Kernel A: blocks 0..255  -> enc (8-step incremental rotation, fp16 out)
//           blocks 256..511 -> cvt Q/K fp16 + V transpose fp16
// ---------------------------------------------------------------------------
__global__ void __launch_bounds__(256) enc_cvt_kernel(
    const float* __restrict__ seqs, const float* __restrict__ keys,
    const float* __restrict__ values, const float* __restrict__ u_bias)
{
    __shared__ __align__(16) __half Tsm[64 * 72];
    int tid = threadIdx.x;

    if (blockIdx.x < 256) {
        // -------- enc: 8 p-steps per block, fp16 output --------
        int i = tid;                      // freq index 0..255
        int p0 = blockIdx.x * 8;
        int steps = Pp - p0; if (steps > 8) steps = 8;
        const float coef = -9.210340371976184f / 512.0f;
        float invf = __expf((float)(2 * i) * coef);
        float s, c;
        sincosf((float)(1023 - p0) * invf, &s, &c);
        float rs, rc;
        sincosf(invf, &rs, &rc);
        for (int t = 0; t < steps; t++) {
            *(__half2*)&g_ENCh[(size_t)(p0 + t) * Dd + 2 * i] =
                __floats2half2_rn(s, c);
            float s2 = s * rc - c * rs;
            float c2 = c * rc + s * rs;
            s = s2; c = c2;
        }
    } else {
        // -------- cvt: one (head, s-tile) of 64 rows --------
        int bid = blockIdx.x - 256;
        int hn = bid & 15;               // n*8+h
        int h = hn & 7;
        int s0 = (bid >> 4) * 64;
        size_t base = (size_t)hn * Ss * DHh;

        int row = tid >> 2;              // 0..63
        int dq = (tid & 3) * 16;         // 0,16,32,48
        const float* qp = seqs + base + (size_t)(s0 + row) * DHh + dq;
        const float* kp = keys + base + (size_t)(s0 + row) * DHh + dq;
        const float* vp = values + base + (size_t)(s0 + row) * DHh + dq;
        unsigned qh[8], kh[8];
#pragma unroll
        for (int j = 0; j < 16; j += 4) {
            float4 q = *(const float4*)(qp + j);
            float4 u = *(const float4*)&u_bias[h * DHh + dq + j];
            float4 k = *(const float4*)(kp + j);
            float4 v = *(const float4*)(vp + j);
            qh[j / 2]     = packh2(q.x + u.x, q.y + u.y);
            qh[j / 2 + 1] = packh2(q.z + u.z, q.w + u.w);
            kh[j / 2]     = packh2(k.x, k.y);
            kh[j / 2 + 1] = packh2(k.z, k.w);
            Tsm[(dq + j + 0) * 72 + row] = __float2half_rn(v.x);
            Tsm[(dq + j + 1) * 72 + row] = __float2half_rn(v.y);
            Tsm[(dq + j + 2) * 72 + row] = __float2half_rn(v.z);
            Tsm[(dq + j + 3) * 72 + row] = __float2half_rn(v.w);
        }
        __half* qo = g_Quh + base + (size_t)(s0 + row) * DHh + dq;
        __half* ko = g_Kh + base + (size_t)(s0 + row) * DHh + dq;
        *(uint4*)qo = *(uint4*)&qh[0];
        *(uint4*)(qo + 8) = *(uint4*)&qh[4];
        *(uint4*)ko = *(uint4*)&kh[0];
        *(uint4*)(ko + 8) = *(uint4*)&kh[4];
        __syncthreads();
        int d = tid >> 2;
        int sc = (tid & 3) * 16;
        __half* vo = g_Vh + (size_t)hn * DHh * Ss + (size_t)d * Ss + s0 + sc;
        *(uint4*)vo = *(uint4*)&Tsm[d * 72 + sc];
        *(uint4*)(vo + 8) = *(uint4*)&Tsm[d * 72 + sc + 8];
    }
}

// ---------------------------------------------------------------------------
// Kernel B: r-projection, fp16 m16n8k16 (A=ENCh, B=W packed fp16).
// grid (32 p-tiles, 8 heads), 256 threads. Outputs fp16 g_Rh + fp32 g_T.
// ---------------------------------------------------------------------------
__global__ void __launch_bounds__(256) rproj_mma_kernel(
    const float* __restrict__ W, const float* __restrict__ u_bias,
    const float* __restrict__ v_bias)
{
    __shared__ __align__(16) __half As[64 * 72];    // ENC tile [p][k]
    __shared__ __align__(16) __half Bsm[64 * 72];   // W tile [c][k]
    __shared__ float scr[2 * 64];

    int tid = threadIdx.x;
    int warp = tid >> 5, lane = tid & 31;
    int g = lane >> 2, tg = lane & 3;
    int wm = (warp & 3) * 16;
    int wn = warp >> 2;

    int p0 = blockIdx.x * 64;
    int h = blockIdx.y;
    int c0 = h * 64;

    float acc[4][4] = {};

    for (int j0 = 0; j0 < Dd; j0 += 64) {
        __syncthreads();
#pragma unroll
        for (int r = 0; r < 2; r++) {
            int q = tid + r * 256;
            int row = q >> 3, ch = q & 7;
            int p = p0 + row;
            uint4 e = make_uint4(0, 0, 0, 0);
            if (p < Pp)
                e = *(const uint4*)&g_ENCh[(size_t)p * Dd + j0 + ch * 8];
            *(uint4*)&As[row * 72 + ch * 8] = e;

            float4 w0 = *(const float4*)&W[(size_t)(c0 + row) * Dd + j0 + ch * 8];
            float4 w1 = *(const float4*)&W[(size_t)(c0 + row) * Dd + j0 + ch * 8 + 4];
            uint4 wp;
            wp.x = packh2(w0.x, w0.y); wp.y = packh2(w0.z, w0.w);
            wp.z = packh2(w1.x, w1.y); wp.w = packh2(w1.z, w1.w);
            *(uint4*)&Bsm[row * 72 + ch * 8] = wp;
        }
        __syncthreads();
#pragma unroll
        for (int k0 = 0; k0 < 64; k0 += 16) {
            unsigned a0 = ldh(&As[(wm + g) * 72 + k0 + 2 * tg]);
            unsigned a1 = ldh(&As[(wm + g + 8) * 72 + k0 + 2 * tg]);
            unsigned a2 = ldh(&As[(wm + g) * 72 + k0 + 8 + 2 * tg]);
            unsigned a3 = ldh(&As[(wm + g + 8) * 72 + k0 + 8 + 2 * tg]);
#pragma unroll
            for (int nt = 0; nt < 4; nt++) {
                int n0 = wn * 32 + nt * 8;
                unsigned b0 = ldh(&Bsm[(n0 + g) * 72 + k0 + 2 * tg]);
                unsigned b1 = ldh(&Bsm[(n0 + g) * 72 + k0 + 8 + 2 * tg]);
                mma_f16(acc[nt], a0, a1, a2, a3, b0, b1);
            }
        }
    }
    int pA = p0 + wm + g, pB = pA + 8;
    __half* Rh = g_Rh + (size_t)h * (Pp * DHh);
#pragma unroll
    for (int nt = 0; nt < 4; nt++) {
        int n0 = wn * 32 + nt * 8;
        if (pA < Pp)
            *(__half2*)&Rh[(size_t)pA * DHh + n0 + 2 * tg] =
                __floats2half2_rn(acc[nt][0], acc[nt][1]);
        if (pB < Pp)
            *(__half2*)&Rh[(size_t)pB * DHh + n0 + 2 * tg] =
                __floats2half2_rn(acc[nt][2], acc[nt][3]);
    }

    // g_T[h][p] = (v_bias - u_bias) . R[h][p][:]
    float localA = 0.0f, localB = 0.0f;
#pragma unroll
    for (int nt = 0; nt < 4; nt++) {
        int n0 = wn * 32 + nt * 8;
        float2 u2 = *(const float2*)&u_bias[h * DHh + n0 + 2 * tg];
        float2 v2 = *(const float2*)&v_bias[h * DHh + n0 + 2 * tg];
        float db0 = v2.x - u2.x, db1 = v2.y - u2.y;
        localA += acc[nt][0] * db0 + acc[nt][1] * db1;
        localB += acc[nt][2] * db0 + acc[nt][3] * db1;
    }
    localA += __shfl_xor_sync(0xffffffffu, localA, 1);
    localA += __shfl_xor_sync(0xffffffffu, localA, 2);
    localB += __shfl_xor_sync(0xffffffffu, localB, 1);
    localB += __shfl_xor_sync(0xffffffffu, localB, 2);
    if (tg == 0) {
        scr[wn * 64 + wm + g] = localA;
        scr[wn * 64 + wm + g + 8] = localB;
    }
    __syncthreads();
    if (tid < 64 && p0 + tid < Pp)
        g_T[h * TPAD + p0 + tid] = scr[tid] + scr[64 + tid];
}

// ---------------------------------------------------------------------------
// Kernel C: attention (unchanged, verified 41 µs).
// ---------------------------------------------------------------------------
#define SQU_B 0                     // Qu fp16 [64][72]     9216
#define SKH_B 9216                  // K ring 2x[64][72]h  18432
#define SRH_B 27648                 // R ring 2x[64][72]h  18432
#define SVT_B 46080                 // Vt ring 2x[64][72]h 18432 (rows=d, cols=kj)
#define SBS_B 64512                 // BD ring 2x[64][68]f 34816
#define SMEM_BYTES 99328
#define EPX_B 0
#define EPM_B 69632
#define EPL_B 70656

__global__ void __launch_bounds__(512) attn_kernel(float* __restrict__ out)
{
    extern __shared__ char smc[];
    __half* Quh = (__half*)(smc + SQU_B);
    __half* Khs = (__half*)(smc + SKH_B);
    __half* Rhs = (__half*)(smc + SRH_B);
    __half* Vts = (__half*)(smc + SVT_B);
    float*  Bs  = (float*)(smc + SBS_B);
    unsigned smb = (unsigned)__cvta_generic_to_shared(smc);

    int tid = threadIdx.x;
    int lane = tid & 31;
    int warp = tid >> 5;
    int g = lane >> 2, tg = lane & 3;
    int wm = (warp & 3) * 16;
    int wn = warp >> 2;
    int rA = wm + g, rB = wm + g + 8;

    int bx = blockIdx.x;
    int head = blockIdx.y;
    int h = head & 7;
    int hn = head;

    size_t hoff = (size_t)hn * Ss * DHh;
    const __half* qug = g_Quh + hoff;
    const __half* khg = g_Kh + hoff;
    const __half* vtg = g_Vh + (size_t)hn * DHh * Ss;
    const __half* Rhg = g_Rh + (size_t)h * (Pp * DHh);
    const float*  Th  = g_T + (size_t)h * TPAD;

    int row8 = tid >> 3, ch8 = tid & 7;

    const float scale = 0.125f;

    for (int ph = 0; ph < 2; ph++) {
        int qt = (ph == 0) ? (15 - bx) : bx;
        int i0 = qt * 64;
        int pb0 = (Ss - 1) - i0 - 63;

        __syncthreads();

        cpa16(smb + SQU_B + row8 * 144 + ch8 * 16,
              qug + (size_t)(i0 + row8) * DHh + ch8 * 8);
        cpa16(smb + SKH_B + row8 * 144 + ch8 * 16,
              khg + (size_t)row8 * DHh + ch8 * 8);
        cpa16(smb + SVT_B + row8 * 144 + ch8 * 16,
              vtg + (size_t)row8 * Ss + ch8 * 8);
#pragma unroll
        for (int r = 0; r < 2; r++) {
            int row = row8 + r * 64;
            cpa16(smb + SRH_B + row * 144 + ch8 * 16,
                  Rhg + (size_t)(pb0 + row) * DHh + ch8 * 8);
        }
        CP_COMMIT();

        float mA_run = -1e30f, mB_run = -1e30f;
        float lA_run = 0.0f, lB_run = 0.0f;
        float O[8][4];
#pragma unroll
        for (int a = 0; a < 8; a++)
#pragma unroll
            for (int b = 0; b < 4; b++) O[a][b] = 0.0f;

        for (int kt = 0; kt <= qt; kt++) {
            int j0 = kt * 64;
            int pbase = (Ss - 1) - i0 + j0 - 63;
            int bufLow = kt & 1, bufHigh = bufLow ^ 1;

            CP_WAIT0();
            __syncthreads();

            if (kt < qt) {
                int jn = j0 + 64;
                cpa16(smb + SKH_B + bufHigh * 9216 + row8 * 144 + ch8 * 16,
                      khg + (size_t)(jn + row8) * DHh + ch8 * 8);
                cpa16(smb + SVT_B + bufHigh * 9216 + row8 * 144 + ch8 * 16,
                      vtg + (size_t)row8 * Ss + jn + ch8 * 8);
                CP_COMMIT();
            }

            const __half* Khb = Khs + bufLow * 4608;
            const __half* Vtb = Vts + bufLow * 4608;

            float2 tv[4];
            if (kt == 0) {
#pragma unroll
                for (int nt = 0; nt < 4; nt++)
                    tv[nt] = *(const float2*)&Th[pbase + wn * 32 + nt * 8 + 2 * tg];
            } else {
#pragma unroll
                for (int nt = 0; nt < 2; nt++)
                    tv[nt] = *(const float2*)&Th[pbase + 64 + wn * 16 + nt * 8 + 2 * tg];
            }

            float cS[2][4];
#pragma unroll
            for (int t = 0; t < 2; t++)
#pragma unroll
                for (int e = 0; e < 4; e++) cS[t][e] = 0.0f;

            if (kt == 0) {
                float cB[4][4];
#pragma unroll
                for (int t = 0; t < 4; t++)
#pragma unroll
                    for (int e = 0; e < 4; e++) cB[t][e] = 0.0f;
#pragma unroll
                for (int k0 = 0; k0 < 64; k0 += 16) {
                    unsigned a0 = ldh(&Quh[rA * 72 + k0 + 2 * tg]);
                    unsigned a1 = ldh(&Quh[rB * 72 + k0 + 2 * tg]);
                    unsigned a2 = ldh(&Quh[rA * 72 + k0 + 8 + 2 * tg]);
                    unsigned a3 = ldh(&Quh[rB * 72 + k0 + 8 + 2 * tg]);
#pragma unroll
                    for (int nt = 0; nt < 2; nt++) {
                        int n0 = wn * 16 + nt * 8;
                        unsigned b0 = ldh(&Khb[(n0 + g) * 72 + k0 + 2 * tg]);
                        unsigned b1 = ldh(&Khb[(n0 + g) * 72 + k0 + 8 + 2 * tg]);
                        mma_f16(cS[nt], a0, a1, a2, a3, b0, b1);
                    }
#pragma unroll
                    for (int nt = 0; nt < 4; nt++) {
                        int o0 = wn * 32 + nt * 8;
                        unsigned b0 = ldh(&Rhs[(o0 + g) * 72 + k0 + 2 * tg]);
                        unsigned b1 = ldh(&Rhs[(o0 + g) * 72 + k0 + 8 + 2 * tg]);
                        mma_f16(cB[nt], a0, a1, a2, a3, b0, b1);
                    }
                }
#pragma unroll
                for (int nt = 0; nt < 4; nt++) {
                    int o0 = wn * 32 + nt * 8;
                    float* Bd = Bs + (o0 >> 6) * 4352 + (o0 & 63) + 2 * tg;
                    *(float2*)&Bd[rA * 68] = make_float2(cB[nt][0] + tv[nt].x, cB[nt][1] + tv[nt].y);
                    *(float2*)&Bd[rB * 68] = make_float2(cB[nt][2] + tv[nt].x, cB[nt][3] + tv[nt].y);
                }
            } else {
                float cB[2][4];
#pragma unroll
                for (int t = 0; t < 2; t++)
#pragma unroll
                    for (int e = 0; e < 4; e++) cB[t][e] = 0.0f;
                const __half* Rb = Rhs + bufHigh * 4608;
#pragma unroll
                for (int k0 = 0; k0 < 64; k0 += 16) {
                    unsigned a0 = ldh(&Quh[rA * 72 + k0 + 2 * tg]);
                    unsigned a1 = ldh(&Quh[rB * 72 + k0 + 2 * tg]);
                    unsigned a2 = ldh(&Quh[rA * 72 + k0 + 8 + 2 * tg]);
                    unsigned a3 = ldh(&Quh[rB * 72 + k0 + 8 + 2 * tg]);
#pragma unroll
                    for (int nt = 0; nt < 2; nt++) {
                        int n0 = wn * 16 + nt * 8;
                        unsigned b0 = ldh(&Khb[(n0 + g) * 72 + k0 + 2 * tg]);
                        unsigned b1 = ldh(&Khb[(n0 + g) * 72 + k0 + 8 + 2 * tg]);
                        mma_f16(cS[nt], a0, a1, a2, a3, b0, b1);
                    }
#pragma unroll
                    for (int nt = 0; nt < 2; nt++) {
                        int r0 = wn * 16 + nt * 8;
                        unsigned b0 = ldh(&Rb[(r0 + g) * 72 + k0 + 2 * tg]);
                        unsigned b1 = ldh(&Rb[(r0 + g) * 72 + k0 + 8 + 2 * tg]);
                        mma_f16(cB[nt], a0, a1, a2, a3, b0, b1);
                    }
                }
                float* Bd0 = Bs + bufHigh * 4352;
#pragma unroll
                for (int nt = 0; nt < 2; nt++) {
                    int r0 = wn * 16 + nt * 8;
                    float* Bd = Bd0 + r0 + 2 * tg;
                    *(float2*)&Bd[rA * 68] = make_float2(cB[nt][0] + tv[nt].x, cB[nt][1] + tv[nt].y);
                    *(float2*)&Bd[rB * 68] = make_float2(cB[nt][2] + tv[nt].x, cB[nt][3] + tv[nt].y);
                }
            }
            __syncthreads();

            if (kt < qt) {
                cpa16(smb + SRH_B + bufLow * 9216 + row8 * 144 + ch8 * 16,
                      Rhg + (size_t)(pbase + 128 + row8) * DHh + ch8 * 8);
                CP_COMMIT();
            }

            float sv[2][4];
            float mAl = -INFINITY, mBl = -INFINITY;
            int diag = (kt == qt);
#pragma unroll
            for (int nt = 0; nt < 2; nt++) {
                int colbase = wn * 16 + nt * 8 + 2 * tg;
#pragma unroll
                for (int e = 0; e < 4; e++) {
                    int j = colbase + (e & 1);
                    int row = (e < 2) ? rA : rB;
                    int o = j - row + 63;
                    float bd = Bs[(bufLow ^ (o >> 6)) * 4352 + row * 68 + (o & 63)];
                    float s = (cS[nt][e] + bd) * scale;
                    if (diag && j > row) s = -INFINITY;
                    sv[nt][e] = s;
                    if (e < 2) mAl = fmaxf(mAl, s); else mBl = fmaxf(mBl, s);
                }
            }
            mAl = fmaxf(mAl, __shfl_xor_sync(0xffffffffu, mAl, 1));
            mAl = fmaxf(mAl, __shfl_xor_sync(0xffffffffu, mAl, 2));
            mBl = fmaxf(mBl, __shfl_xor_sync(0xffffffffu, mBl, 1));
            mBl = fmaxf(mBl, __shfl_xor_sync(0xffffffffu, mBl, 2));

            float mgA = fmaxf(mA_run, mAl);
            float mgB = fmaxf(mB_run, mBl);
            float corrA = __expf(mA_run - mgA);
            float corrB = __expf(mB_run - mgB);

            float peA0[2], peA1[2], peB0[2], peB1[2];
            float sumA = 0.0f, sumB = 0.0f;
#pragma unroll
            for (int nt = 0; nt < 2; nt++) {
                peA0[nt] = __expf(sv[nt][0] - mgA);
                peA1[nt] = __expf(sv[nt][1] - mgA);
                peB0[nt] = __expf(sv[nt][2] - mgB);
                peB1[nt] = __expf(sv[nt][3] - mgB);
                sumA += peA0[nt] + peA1[nt];
                sumB += peB0[nt] + peB1[nt];
            }
            sumA += __shfl_xor_sync(0xffffffffu, sumA, 1);
            sumA += __shfl_xor_sync(0xffffffffu, sumA, 2);
            sumB += __shfl_xor_sync(0xffffffffu, sumB, 1);
            sumB += __shfl_xor_sync(0xffffffffu, sumB, 2);
            lA_run = lA_run * corrA + sumA;
            lB_run = lB_run * corrB + sumB;
            mA_run = mgA; mB_run = mgB;

#pragma unroll
            for (int jn = 0; jn < 8; jn++) {
                O[jn][0] *= corrA; O[jn][1] *= corrA;
                O[jn][2] *= corrB; O[jn][3] *= corrB;
            }

            {
                unsigned a0 = packh2(peA0[0], peA1[0]);
                unsigned a1 = packh2(peB0[0], peB1[0]);
                unsigned a2 = packh2(peA0[1], peA1[1]);
                unsigned a3 = packh2(peB0[1], peB1[1]);
                int kbase = wn * 16;
#pragma unroll
                for (int jn = 0; jn < 8; jn++) {
                    int n0 = jn * 8;
                    unsigned b0 = ldh(&Vtb[(n0 + g) * 72 + kbase + 2 * tg]);
                    unsigned b1 = ldh(&Vtb[(n0 + g) * 72 + kbase + 8 + 2 * tg]);
                    mma_f16(O[jn], a0, a1, a2, a3, b0, b1);
                }
            }
        }

        __syncthreads();
        {
            float* Xo = (float*)(smc + EPX_B);
            float* mArr = (float*)(smc + EPM_B);
            float* lArr = (float*)(smc + EPL_B);
#pragma unroll
            for (int jn = 0; jn < 8; jn++) {
                int n0 = jn * 8;
                *(float2*)&Xo[wn * 4352 + rA * 68 + n0 + 2 * tg] =
                    make_float2(O[jn][0], O[jn][1]);
                *(float2*)&Xo[wn * 4352 + rB * 68 + n0 + 2 * tg] =
                    make_float2(O[jn][2], O[jn][3]);
            }
            if (tg == 0) {
                mArr[wn * 64 + rA] = mA_run; lArr[wn * 64 + rA] = lA_run;
                mArr[wn * 64 + rB] = mB_run; lArr[wn * 64 + rB] = lB_run;
            }
            __syncthreads();

            int row = tid >> 3, cb = (tid & 7) * 8;
            float m0 = mArr[row], m1 = mArr[64 + row];
            float m2 = mArr[128 + row], m3 = mArr[192 + row];
            float mg = fmaxf(fmaxf(m0, m1), fmaxf(m2, m3));
            float f0 = __expf(m0 - mg), f1 = __expf(m1 - mg);
            float f2 = __expf(m2 - mg), f3 = __expf(m3 - mg);
            float lg = lArr[row] * f0 + lArr[64 + row] * f1
                     + lArr[128 + row] * f2 + lArr[192 + row] * f3;
            float inv = 1.0f / lg;
            float* op = out + hoff + (size_t)(i0 + row) * DHh + cb;
#pragma unroll
            for (int c = 0; c < 8; c += 4) {
                float4 x0 = *(const float4*)&Xo[0 * 4352 + row * 68 + cb + c];
                float4 x1 = *(const float4*)&Xo[1 * 4352 + row * 68 + cb + c];
                float4 x2 = *(const float4*)&Xo[2 * 4352 + row * 68 + cb + c];
                float4 x3 = *(const float4*)&Xo[3 * 4352 + row * 68 + cb + c];
                float4 o4;
                o4.x = (x0.x * f0 + x1.x * f1 + x2.x * f2 + x3.x * f3) * inv;
                o4.y = (x0.y * f0 + x1.y * f1 + x2.y * f2 + x3.y * f3) * inv;
                o4.z = (x0.z * f0 + x1.z * f1 + x2.z * f2 + x3.z * f3) * inv;
                o4.w = (x0.w * f0 + x1.w * f1 + x2.w * f2 + x3.w * f3) * inv;
                *(float4*)&op[c] = o4;
            }
        }
    }
}

// ---------------------------------------------------------------------------
extern "C" void kernel_launch(void* const* d_in, const int* in_sizes, int n_in,
                              void* d_out, int out_size) {
    const float* seqs   = (const float*)d_in[0];
    const float* keys   = (const float*)d_in[1];
    const float* values = (const float*)d_in[2];
    const float* u_bias = (const float*)d_in[3];
    const float* v_bias = (const float*)d_in[4];
    const float* rproj  = (const float*)d_in[5];
    (void)in_sizes; (void)n_in; (void)out_size;

    cudaFuncSetAttribute(attn_kernel, cudaFuncAttributeMaxDynamicSharedMemorySize,
                         SMEM_BYTES);

    enc_cvt_kernel<<<512, 256>>>(seqs, keys, values, u_bias);
    rproj_mma_kernel<<<dim3(32, 8), 256>>>(rproj, u_bias, v_bias);
    attn_kernel<<<dim3(8, 16), 512, SMEM_BYTES>>>((float*)d_out);
}

// round 14
// speedup vs baseline: 1.9934x; 1.0778x over previous
#include <cuda_runtime.h>
#include <cuda_fp16.h>
#include <math.h>

#define Nn 2
#define Hh 8
#define Ss 1024
#define DHh 64
#define Dd 512
#define Pp 2047   // 2S-1
#define TPAD 2048 // padded head stride for g_T

__device__ __half g_ENCh[Pp * Dd];            // fp16 positional encodings
__device__ __half g_Rh[Hh * Pp * DHh];        // rounded fp16 R
__device__ __half g_Kh[Nn * Hh * Ss * DHh];   // rounded fp16 keys
__device__ __half g_Vh[Nn * Hh * DHh * Ss];   // rounded fp16 V TRANSPOSED [hn][d][s]
__device__ float g_T[Hh * TPAD];

// balanced causal schedule: 17 groups per head-pair, each exactly 16 k-iters
__device__ const int c_qtA[17] = {15,15,14,14,13,13,12,12,11,11,10,10,9,9,8,8,7};
__device__ const int c_hA[17]  = { 0, 1, 0, 1, 0, 1, 0, 1, 0, 1, 0, 1,0,1,0,1,0};
__device__ const int c_qtB[17] = {-1,-1, 0, 0, 1, 1, 2, 2, 3, 3, 4, 4,5,5,6,6,7};
__device__ const int c_hB[17]  = { 0, 1, 0, 1, 0, 1, 0, 1, 0, 1, 0, 1,0,1,0,1,1};

__device__ __forceinline__ void mma_f16(float c[4], unsigned a0, unsigned a1,
                                        unsigned a2, unsigned a3,
                                        unsigned b0, unsigned b1) {
    asm volatile(
        "mma.sync.aligned.m16n8k16.row.col.f32.f16.f16.f32 "
        "{%0,%1,%2,%3},{%4,%5,%6,%7},{%8,%9},{%0,%1,%2,%3};"
        : "+f"(c[0]), "+f"(c[1]), "+f"(c[2]), "+f"(c[3])
        : "r"(a0), "r"(a1), "r"(a2), "r"(a3), "r"(b0), "r"(b1));
}
__device__ __forceinline__ unsigned ldh(const __half* p) { return *(const unsigned*)p; }
__device__ __forceinline__ unsigned packh2(float a, float b) {
    __half2 t = __floats2half2_rn(a, b);
    return reinterpret_cast<unsigned&>(t);
}
__device__ __forceinline__ void cpa16(unsigned dst, const void* src) {
    asm volatile("cp.async.cg.shared.global [%0], [%1], 16;" :: "r"(dst), "l"(src));
}
#define CP_COMMIT() asm volatile("cp.async.commit_group;")
#define CP_WAIT0()  asm volatile("cp.async.wait_group 0;")

// ---------------------------------------------------------------------------
// Kernel A: blocks 0..255  -> enc (8-step incremental rotation, fp16 out)
//           blocks 256..511 -> cvt K fp16 + V transpose fp16 (Q handled in attn)
// ---------------------------------------------------------------------------
__global__ void __launch_bounds__(256) enc_cvt_kernel(
    const float* __restrict__ keys, const float* __restrict__ values)
{
    __shared__ __align__(16) __half Tsm[64 * 72];
    int tid = threadIdx.x;

    if (blockIdx.x < 256) {
        int i = tid;
        int p0 = blockIdx.x * 8;
        int steps = Pp - p0; if (steps > 8) steps = 8;
        const float coef = -9.210340371976184f / 512.0f;
        float invf = __expf((float)(2 * i) * coef);
        float s, c;
        sincosf((float)(1023 - p0) * invf, &s, &c);
        float rs, rc;
        sincosf(invf, &rs, &rc);
        for (int t = 0; t < steps; t++) {
            *(__half2*)&g_ENCh[(size_t)(p0 + t) * Dd + 2 * i] =
                __floats2half2_rn(s, c);
            float s2 = s * rc - c * rs;
            float c2 = c * rc + s * rs;
            s = s2; c = c2;
        }
    } else {
        int bid = blockIdx.x - 256;
        int hn = bid & 15;
        int s0 = (bid >> 4) * 64;
        size_t base = (size_t)hn * Ss * DHh;

        int row = tid >> 2;
        int dq = (tid & 3) * 16;
        const float* kp = keys + base + (size_t)(s0 + row) * DHh + dq;
        const float* vp = values + base + (size_t)(s0 + row) * DHh + dq;
        unsigned kh[8];
#pragma unroll
        for (int j = 0; j < 16; j += 4) {
            float4 k = *(const float4*)(kp + j);
            float4 v = *(const float4*)(vp + j);
            kh[j / 2]     = packh2(k.x, k.y);
            kh[j / 2 + 1] = packh2(k.z, k.w);
            Tsm[(dq + j + 0) * 72 + row] = __float2half_rn(v.x);
            Tsm[(dq + j + 1) * 72 + row] = __float2half_rn(v.y);
            Tsm[(dq + j + 2) * 72 + row] = __float2half_rn(v.z);
            Tsm[(dq + j + 3) * 72 + row] = __float2half_rn(v.w);
        }
        __half* ko = g_Kh + base + (size_t)(s0 + row) * DHh + dq;
        *(uint4*)ko = *(uint4*)&kh[0];
        *(uint4*)(ko + 8) = *(uint4*)&kh[4];
        __syncthreads();
        int d = tid >> 2;
        int sc = (tid & 3) * 16;
        __half* vo = g_Vh + (size_t)hn * DHh * Ss + (size_t)d * Ss + s0 + sc;
        *(uint4*)vo = *(uint4*)&Tsm[d * 72 + sc];
        *(uint4*)(vo + 8) = *(uint4*)&Tsm[d * 72 + sc + 8];
    }
}

// ---------------------------------------------------------------------------
// Kernel B: r-projection, fp16 m16n8k16 (A=ENCh, B=W packed fp16).
// ---------------------------------------------------------------------------
__global__ void __launch_bounds__(256) rproj_mma_kernel(
    const float* __restrict__ W, const float* __restrict__ u_bias,
    const float* __restrict__ v_bias)
{
    __shared__ __align__(16) __half As[64 * 72];
    __shared__ __align__(16) __half Bsm[64 * 72];
    __shared__ float scr[2 * 64];

    int tid = threadIdx.x;
    int warp = tid >> 5, lane = tid & 31;
    int g = lane >> 2, tg = lane & 3;
    int wm = (warp & 3) * 16;
    int wn = warp >> 2;

    int p0 = blockIdx.x * 64;
    int h = blockIdx.y;
    int c0 = h * 64;

    float acc[4][4] = {};

    for (int j0 = 0; j0 < Dd; j0 += 64) {
        __syncthreads();
#pragma unroll
        for (int r = 0; r < 2; r++) {
            int q = tid + r * 256;
            int row = q >> 3, ch = q & 7;
            int p = p0 + row;
            uint4 e = make_uint4(0, 0, 0, 0);
            if (p < Pp)
                e = *(const uint4*)&g_ENCh[(size_t)p * Dd + j0 + ch * 8];
            *(uint4*)&As[row * 72 + ch * 8] = e;

            float4 w0 = *(const float4*)&W[(size_t)(c0 + row) * Dd + j0 + ch * 8];
            float4 w1 = *(const float4*)&W[(size_t)(c0 + row) * Dd + j0 + ch * 8 + 4];
            uint4 wp;
            wp.x = packh2(w0.x, w0.y); wp.y = packh2(w0.z, w0.w);
            wp.z = packh2(w1.x, w1.y); wp.w = packh2(w1.z, w1.w);
            *(uint4*)&Bsm[row * 72 + ch * 8] = wp;
        }
        __syncthreads();
#pragma unroll
        for (int k0 = 0; k0 < 64; k0 += 16) {
            unsigned a0 = ldh(&As[(wm + g) * 72 + k0 + 2 * tg]);
            unsigned a1 = ldh(&As[(wm + g + 8) * 72 + k0 + 2 * tg]);
            unsigned a2 = ldh(&As[(wm + g) * 72 + k0 + 8 + 2 * tg]);
            unsigned a3 = ldh(&As[(wm + g + 8) * 72 + k0 + 8 + 2 * tg]);
#pragma unroll
            for (int nt = 0; nt < 4; nt++) {
                int n0 = wn * 32 + nt * 8;
                unsigned b0 = ldh(&Bsm[(n0 + g) * 72 + k0 + 2 * tg]);
                unsigned b1 = ldh(&Bsm[(n0 + g) * 72 + k0 + 8 + 2 * tg]);
                mma_f16(acc[nt], a0, a1, a2, a3, b0, b1);
            }
        }
    }
    int pA = p0 + wm + g, pB = pA + 8;
    __half* Rh = g_Rh + (size_t)h * (Pp * DHh);
#pragma unroll
    for (int nt = 0; nt < 4; nt++) {
        int n0 = wn * 32 + nt * 8;
        if (pA < Pp)
            *(__half2*)&Rh[(size_t)pA * DHh + n0 + 2 * tg] =
                __floats2half2_rn(acc[nt][0], acc[nt][1]);
        if (pB < Pp)
            *(__half2*)&Rh[(size_t)pB * DHh + n0 + 2 * tg] =
                __floats2half2_rn(acc[nt][2], acc[nt][3]);
    }

    float localA = 0.0f, localB = 0.0f;
#pragma unroll
    for (int nt = 0; nt < 4; nt++) {
        int n0 = wn * 32 + nt * 8;
        float2 u2 = *(const float2*)&u_bias[h * DHh + n0 + 2 * tg];
        float2 v2 = *(const float2*)&v_bias[h * DHh + n0 + 2 * tg];
        float db0 = v2.x - u2.x, db1 = v2.y - u2.y;
        localA += acc[nt][0] * db0 + acc[nt][1] * db1;
        localB += acc[nt][2] * db0 + acc[nt][3] * db1;
    }
    localA += __shfl_xor_sync(0xffffffffu, localA, 1);
    localA += __shfl_xor_sync(0xffffffffu, localA, 2);
    localB += __shfl_xor_sync(0xffffffffu, localB, 1);
    localB += __shfl_xor_sync(0xffffffffu, localB, 2);
    if (tg == 0) {
        scr[wn * 64 + wm + g] = localA;
        scr[wn * 64 + wm + g + 8] = localB;
    }
    __syncthreads();
    if (tid < 64 && p0 + tid < Pp)
        g_T[h * TPAD + p0 + tid] = scr[tid] + scr[64 + tid];
}

// ---------------------------------------------------------------------------
// Kernel C: attention. grid (17, 8) = 136 blocks, each 16 k-iters total via
// the balanced schedule table. Q converted in-kernel (fp32 -> fp16 smem).
// ---------------------------------------------------------------------------
#define SQU_B 0                     // Qu fp16 [64][72]     9216
#define SKH_B 9216                  // K ring 2x[64][72]h  18432
#define SRH_B 27648                 // R ring 2x[64][72]h  18432
#define SVT_B 46080                 // Vt ring 2x[64][72]h 18432
#define SBS_B 64512                 // BD ring 2x[64][68]f 34816
#define SMEM_BYTES 99328
#define EPX_B 0
#define EPM_B 69632
#define EPL_B 70656

__global__ void __launch_bounds__(512) attn_kernel(
    const float* __restrict__ seqs, const float* __restrict__ u_bias,
    float* __restrict__ out)
{
    extern __shared__ char smc[];
    __half* Quh = (__half*)(smc + SQU_B);
    __half* Khs = (__half*)(smc + SKH_B);
    __half* Rhs = (__half*)(smc + SRH_B);
    __half* Vts = (__half*)(smc + SVT_B);
    float*  Bs  = (float*)(smc + SBS_B);
    unsigned smb = (unsigned)__cvta_generic_to_shared(smc);

    int tid = threadIdx.x;
    int lane = tid & 31;
    int warp = tid >> 5;
    int g = lane >> 2, tg = lane & 3;
    int wm = (warp & 3) * 16;
    int wn = warp >> 2;
    int rA = wm + g, rB = wm + g + 8;

    int bx = blockIdx.x;   // 0..16 group
    int hp = blockIdx.y;   // 0..7 head pair

    int row8 = tid >> 3, ch8 = tid & 7;
    const float scale = 0.125f;

    for (int ph = 0; ph < 2; ph++) {
        int qt = (ph == 0) ? c_qtA[bx] : c_qtB[bx];
        if (qt < 0) break;
        int hn = hp * 2 + ((ph == 0) ? c_hA[bx] : c_hB[bx]);
        int h = hn & 7;

        size_t hoff = (size_t)hn * Ss * DHh;
        const __half* khg = g_Kh + hoff;
        const __half* vtg = g_Vh + (size_t)hn * DHh * Ss;
        const __half* Rhg = g_Rh + (size_t)h * (Pp * DHh);
        const float*  Th  = g_T + (size_t)h * TPAD;

        int i0 = qt * 64;
        int pb0 = (Ss - 1) - i0 - 63;

        __syncthreads();   // previous phase fully consumed

        // ---- async prologue: K/Vt tile 0, R rows 0..127 ----
        cpa16(smb + SKH_B + row8 * 144 + ch8 * 16,
              khg + (size_t)row8 * DHh + ch8 * 8);
        cpa16(smb + SVT_B + row8 * 144 + ch8 * 16,
              vtg + (size_t)row8 * Ss + ch8 * 8);
#pragma unroll
        for (int r = 0; r < 2; r++) {
            int row = row8 + r * 64;
            cpa16(smb + SRH_B + row * 144 + ch8 * 16,
                  Rhg + (size_t)(pb0 + row) * DHh + ch8 * 8);
        }
        CP_COMMIT();

        // ---- Q: fp32 load + bias + rounded fp16 cvt to smem (overlaps cp.async)
        {
            const float* qp = seqs + hoff + (size_t)(i0 + row8) * DHh + ch8 * 8;
            float4 q0 = *(const float4*)qp;
            float4 q1 = *(const float4*)(qp + 4);
            float4 u0 = *(const float4*)&u_bias[h * DHh + ch8 * 8];
            float4 u1 = *(const float4*)&u_bias[h * DHh + ch8 * 8 + 4];
            uint4 qv;
            qv.x = packh2(q0.x + u0.x, q0.y + u0.y);
            qv.y = packh2(q0.z + u0.z, q0.w + u0.w);
            qv.z = packh2(q1.x + u1.x, q1.y + u1.y);
            qv.w = packh2(q1.z + u1.z, q1.w + u1.w);
            *(uint4*)&Quh[row8 * 72 + ch8 * 8] = qv;
        }

        float mA_run = -1e30f, mB_run = -1e30f;
        float lA_run = 0.0f, lB_run = 0.0f;
        float O[8][4];
#pragma unroll
        for (int a = 0; a < 8; a++)
#pragma unroll
            for (int b = 0; b < 4; b++) O[a][b] = 0.0f;

        for (int kt = 0; kt <= qt; kt++) {
            int j0 = kt * 64;
            int pbase = (Ss - 1) - i0 + j0 - 63;
            int bufLow = kt & 1, bufHigh = bufLow ^ 1;

            CP_WAIT0();
            __syncthreads();

            if (kt < qt) {
                int jn = j0 + 64;
                cpa16(smb + SKH_B + bufHigh * 9216 + row8 * 144 + ch8 * 16,
                      khg + (size_t)(jn + row8) * DHh + ch8 * 8);
                cpa16(smb + SVT_B + bufHigh * 9216 + row8 * 144 + ch8 * 16,
                      vtg + (size_t)row8 * Ss + jn + ch8 * 8);
                CP_COMMIT();
            }

            const __half* Khb = Khs + bufLow * 4608;
            const __half* Vtb = Vts + bufLow * 4608;

            float2 tv[4];
            if (kt == 0) {
#pragma unroll
                for (int nt = 0; nt < 4; nt++)
                    tv[nt] = *(const float2*)&Th[pbase + wn * 32 + nt * 8 + 2 * tg];
            } else {
#pragma unroll
                for (int nt = 0; nt < 2; nt++)
                    tv[nt] = *(const float2*)&Th[pbase + 64 + wn * 16 + nt * 8 + 2 * tg];
            }

            float cS[2][4];
#pragma unroll
            for (int t = 0; t < 2; t++)
#pragma unroll
                for (int e = 0; e < 4; e++) cS[t][e] = 0.0f;

            if (kt == 0) {
                float cB[4][4];
#pragma unroll
                for (int t = 0; t < 4; t++)
#pragma unroll
                    for (int e = 0; e < 4; e++) cB[t][e] = 0.0f;
#pragma unroll
                for (int k0 = 0; k0 < 64; k0 += 16) {
                    unsigned a0 = ldh(&Quh[rA * 72 + k0 + 2 * tg]);
                    unsigned a1 = ldh(&Quh[rB * 72 + k0 + 2 * tg]);
                    unsigned a2 = ldh(&Quh[rA * 72 + k0 + 8 + 2 * tg]);
                    unsigned a3 = ldh(&Quh[rB * 72 + k0 + 8 + 2 * tg]);
#pragma unroll
                    for (int nt = 0; nt < 2; nt++) {
                        int n0 = wn * 16 + nt * 8;
                        unsigned b0 = ldh(&Khb[(n0 + g) * 72 + k0 + 2 * tg]);
                        unsigned b1 = ldh(&Khb[(n0 + g) * 72 + k0 + 8 + 2 * tg]);
                        mma_f16(cS[nt], a0, a1, a2, a3, b0, b1);
                    }
#pragma unroll
                    for (int nt = 0; nt < 4; nt++) {
                        int o0 = wn * 32 + nt * 8;
                        unsigned b0 = ldh(&Rhs[(o0 + g) * 72 + k0 + 2 * tg]);
                        unsigned b1 = ldh(&Rhs[(o0 + g) * 72 + k0 + 8 + 2 * tg]);
                        mma_f16(cB[nt], a0, a1, a2, a3, b0, b1);
                    }
                }
#pragma unroll
                for (int nt = 0; nt < 4; nt++) {
                    int o0 = wn * 32 + nt * 8;
                    float* Bd = Bs + (o0 >> 6) * 4352 + (o0 & 63) + 2 * tg;
                    *(float2*)&Bd[rA * 68] = make_float2(cB[nt][0] + tv[nt].x, cB[nt][1] + tv[nt].y);
                    *(float2*)&Bd[rB * 68] = make_float2(cB[nt][2] + tv[nt].x, cB[nt][3] + tv[nt].y);
                }
            } else {
                float cB[2][4];
#pragma unroll
                for (int t = 0; t < 2; t++)
#pragma unroll
                    for (int e = 0; e < 4; e++) cB[t][e] = 0.0f;
                const __half* Rb = Rhs + bufHigh * 4608;
#pragma unroll
                for (int k0 = 0; k0 < 64; k0 += 16) {
                    unsigned a0 = ldh(&Quh[rA * 72 + k0 + 2 * tg]);
                    unsigned a1 = ldh(&Quh[rB * 72 + k0 + 2 * tg]);
                    unsigned a2 = ldh(&Quh[rA * 72 + k0 + 8 + 2 * tg]);
                    unsigned a3 = ldh(&Quh[rB * 72 + k0 + 8 + 2 * tg]);
#pragma unroll
                    for (int nt = 0; nt < 2; nt++) {
                        int n0 = wn * 16 + nt * 8;
                        unsigned b0 = ldh(&Khb[(n0 + g) * 72 + k0 + 2 * tg]);
                        unsigned b1 = ldh(&Khb[(n0 + g) * 72 + k0 + 8 + 2 * tg]);
                        mma_f16(cS[nt], a0, a1, a2, a3, b0, b1);
                    }
#pragma unroll
                    for (int nt = 0; nt < 2; nt++) {
                        int r0 = wn * 16 + nt * 8;
                        unsigned b0 = ldh(&Rb[(r0 + g) * 72 + k0 + 2 * tg]);
                        unsigned b1 = ldh(&Rb[(r0 + g) * 72 + k0 + 8 + 2 * tg]);
                        mma_f16(cB[nt], a0, a1, a2, a3, b0, b1);
                    }
                }
                float* Bd0 = Bs + bufHigh * 4352;
#pragma unroll
                for (int nt = 0; nt < 2; nt++) {
                    int r0 = wn * 16 + nt * 8;
                    float* Bd = Bd0 + r0 + 2 * tg;
                    *(float2*)&Bd[rA * 68] = make_float2(cB[nt][0] + tv[nt].x, cB[nt][1] + tv[nt].y);
                    *(float2*)&Bd[rB * 68] = make_float2(cB[nt][2] + tv[nt].x, cB[nt][3] + tv[nt].y);
                }
            }
            __syncthreads();

            if (kt < qt) {
                cpa16(smb + SRH_B + bufLow * 9216 + row8 * 144 + ch8 * 16,
                      Rhg + (size_t)(pbase + 128 + row8) * DHh + ch8 * 8);
                CP_COMMIT();
            }

            float sv[2][4];
            float mAl = -INFINITY, mBl = -INFINITY;
            int diag = (kt == qt);
#pragma unroll
            for (int nt = 0; nt < 2; nt++) {
                int colbase = wn * 16 + nt * 8 + 2 * tg;
#pragma unroll
                for (int e = 0; e < 4; e++) {
                    int j = colbase + (e & 1);
                    int row = (e < 2) ? rA : rB;
                    int o = j - row + 63;
                    float bd = Bs[(bufLow ^ (o >> 6)) * 4352 + row * 68 + (o & 63)];
                    float s = (cS[nt][e] + bd) * scale;
                    if (diag && j > row) s = -INFINITY;
                    sv[nt][e] = s;
                    if (e < 2) mAl = fmaxf(mAl, s); else mBl = fmaxf(mBl, s);
                }
            }
            mAl = fmaxf(mAl, __shfl_xor_sync(0xffffffffu, mAl, 1));
            mAl = fmaxf(mAl, __shfl_xor_sync(0xffffffffu, mAl, 2));
            mBl = fmaxf(mBl, __shfl_xor_sync(0xffffffffu, mBl, 1));
            mBl = fmaxf(mBl, __shfl_xor_sync(0xffffffffu, mBl, 2));

            float mgA = fmaxf(mA_run, mAl);
            float mgB = fmaxf(mB_run, mBl);
            float corrA = __expf(mA_run - mgA);
            float corrB = __expf(mB_run - mgB);

            float peA0[2], peA1[2], peB0[2], peB1[2];
            float sumA = 0.0f, sumB = 0.0f;
#pragma unroll
            for (int nt = 0; nt < 2; nt++) {
                peA0[nt] = __expf(sv[nt][0] - mgA);
                peA1[nt] = __expf(sv[nt][1] - mgA);
                peB0[nt] = __expf(sv[nt][2] - mgB);
                peB1[nt] = __expf(sv[nt][3] - mgB);
                sumA += peA0[nt] + peA1[nt];
                sumB += peB0[nt] + peB1[nt];
            }
            sumA += __shfl_xor_sync(0xffffffffu, sumA, 1);
            sumA += __shfl_xor_sync(0xffffffffu, sumA, 2);
            sumB += __shfl_xor_sync(0xffffffffu, sumB, 1);
            sumB += __shfl_xor_sync(0xffffffffu, sumB, 2);
            lA_run = lA_run * corrA + sumA;
            lB_run = lB_run * corrB + sumB;
            mA_run = mgA; mB_run = mgB;

#pragma unroll
            for (int jn = 0; jn < 8; jn++) {
                O[jn][0] *= corrA; O[jn][1] *= corrA;
                O[jn][2] *= corrB; O[jn][3] *= corrB;
            }

            {
                unsigned a0 = packh2(peA0[0], peA1[0]);
                unsigned a1 = packh2(peB0[0], peB1[0]);
                unsigned a2 = packh2(peA0[1], peA1[1]);
                unsigned a3 = packh2(peB0[1], peB1[1]);
                int kbase = wn * 16;
#pragma unroll
                for (int jn = 0; jn < 8; jn++) {
                    int n0 = jn * 8;
                    unsigned b0 = ldh(&Vtb[(n0 + g) * 72 + kbase + 2 * tg]);
                    unsigned b1 = ldh(&Vtb[(n0 + g) * 72 + kbase + 8 + 2 * tg]);
                    mma_f16(O[jn], a0, a1, a2, a3, b0, b1);
                }
            }
        }

        // ---- split-k merge ----
        __syncthreads();
        {
            float* Xo = (float*)(smc + EPX_B);
            float* mArr = (float*)(smc + EPM_B);
            float* lArr = (float*)(smc + EPL_B);
#pragma unroll
            for (int jn = 0; jn < 8; jn++) {
                int n0 = jn * 8;
                *(float2*)&Xo[wn * 4352 + rA * 68 + n0 + 2 * tg] =
                    make_float2(O[jn][0], O[jn][1]);
                *(float2*)&Xo[wn * 4352 + rB * 68 + n0 + 2 * tg] =
                    make_float2(O[jn][2], O[jn][3]);
            }
            if (tg == 0) {
                mArr[wn * 64 + rA] = mA_run; lArr[wn * 64 + rA] = lA_run;
                mArr[wn * 64 + rB] = mB_run; lArr[wn * 64 + rB] = lB_run;
            }
            __syncthreads();

            int row = tid >> 3, cb = (tid & 7) * 8;
            float m0 = mArr[row], m1 = mArr[64 + row];
            float m2 = mArr[128 + row], m3 = mArr[192 + row];
            float mg = fmaxf(fmaxf(m0, m1), fmaxf(m2, m3));
            float f0 = __expf(m0 - mg), f1 = __expf(m1 - mg);
            float f2 = __expf(m2 - mg), f3 = __expf(m3 - mg);
            float lg = lArr[row] * f0 + lArr[64 + row] * f1
                     + lArr[128 + row] * f2 + lArr[192 + row] * f3;
            float inv = 1.0f / lg;
            float* op = out + hoff + (size_t)(i0 + row) * DHh + cb;
#pragma unroll
            for (int c = 0; c < 8; c += 4) {
                float4 x0 = *(const float4*)&Xo[0 * 4352 + row * 68 + cb + c];
                float4 x1 = *(const float4*)&Xo[1 * 4352 + row * 68 + cb + c];
                float4 x2 = *(const float4*)&Xo[2 * 4352 + row * 68 + cb + c];
                float4 x3 = *(const float4*)&Xo[3 * 4352 + row * 68 + cb + c];
                float4 o4;
                o4.x = (x0.x * f0 + x1.x * f1 + x2.x * f2 + x3.x * f3) * inv;
                o4.y = (x0.y * f0 + x1.y * f1 + x2.y * f2 + x3.y * f3) * inv;
                o4.z = (x0.z * f0 + x1.z * f1 + x2.z * f2 + x3.z * f3) * inv;
                o4.w = (x0.w * f0 + x1.w * f1 + x2.w * f2 + x3.w * f3) * inv;
                *(float4*)&op[c] = o4;
            }
        }
    }
}

// ---------------------------------------------------------------------------
extern "C" void kernel_launch(void* const* d_in, const int* in_sizes, int n_in,
                              void* d_out, int out_size) {
    const float* seqs   = (const float*)d_in[0];
    const float* keys   = (const float*)d_in[1];
    const float* values = (const float*)d_in[2];
    const float* u_bias = (const float*)d_in[3];
    const float* v_bias = (const float*)d_in[4];
    const float* rproj  = (const float*)d_in[5];
    (void)in_sizes; (void)n_in; (void)out_size;

    cudaFuncSetAttribute(attn_kernel, cudaFuncAttributeMaxDynamicSharedMemorySize,
                         SMEM_BYTES);

    enc_cvt_kernel<<<512, 256>>>(keys, values);
    rproj_mma_kernel<<<dim3(32, 8), 256>>>(rproj, u_bias, v_bias);
    attn_kernel<<<dim3(17, 8), 512, SMEM_BYTES>>>(seqs, u_bias, (float*)d_out);
}

// round 15
// speedup vs baseline: 1.9994x; 1.0030x over previous
#include <cuda_runtime.h>
#include <cuda_fp16.h>
#include <math.h>

#define Nn 2
#define Hh 8
#define Ss 1024
#define DHh 64
#define Dd 512
#define Pp 2047   // 2S-1
#define TPAD 2048 // padded head stride for g_T

__device__ __half g_Rh[Hh * Pp * DHh];        // rounded fp16 R
__device__ __half g_Kh[Nn * Hh * Ss * DHh];   // rounded fp16 keys
__device__ __half g_Vh[Nn * Hh * DHh * Ss];   // rounded fp16 V TRANSPOSED [hn][d][s]
__device__ float g_T[Hh * TPAD];

// balanced causal schedule: 17 groups per head-pair, each exactly 16 k-iters
__device__ const int c_qtA[17] = {15,15,14,14,13,13,12,12,11,11,10,10,9,9,8,8,7};
__device__ const int c_hA[17]  = { 0, 1, 0, 1, 0, 1, 0, 1, 0, 1, 0, 1,0,1,0,1,0};
__device__ const int c_qtB[17] = {-1,-1, 0, 0, 1, 1, 2, 2, 3, 3, 4, 4,5,5,6,6,7};
__device__ const int c_hB[17]  = { 0, 1, 0, 1, 0, 1, 0, 1, 0, 1, 0, 1,0,1,0,1,1};

__device__ __forceinline__ void mma_f16(float c[4], unsigned a0, unsigned a1,
                                        unsigned a2, unsigned a3,
                                        unsigned b0, unsigned b1) {
    asm volatile(
        "mma.sync.aligned.m16n8k16.row.col.f32.f16.f16.f32 "
        "{%0,%1,%2,%3},{%4,%5,%6,%7},{%8,%9},{%0,%1,%2,%3};"
        : "+f"(c[0]), "+f"(c[1]), "+f"(c[2]), "+f"(c[3])
        : "r"(a0), "r"(a1), "r"(a2), "r"(a3), "r"(b0), "r"(b1));
}
__device__ __forceinline__ unsigned ldh(const __half* p) { return *(const unsigned*)p; }
__device__ __forceinline__ unsigned packh2(float a, float b) {
    __half2 t = __floats2half2_rn(a, b);
    return reinterpret_cast<unsigned&>(t);
}
__device__ __forceinline__ void cpa16(unsigned dst, const void* src) {
    asm volatile("cp.async.cg.shared.global [%0], [%1], 16;" :: "r"(dst), "l"(src));
}
#define CP_COMMIT() asm volatile("cp.async.commit_group;")
#define CP_WAIT0()  asm volatile("cp.async.wait_group 0;")

// ---------------------------------------------------------------------------
// Kernel 1 (merged prologue, 512 blocks):
//   blocks 0..255  -> cvt K fp16 + V transpose fp16
//   blocks 256..511 -> rproj with LOCAL smem ENC (no global ENC, no dependency)
// dynamic smem: rproj branch needs 64x520 halves ENC + 64x72 halves W + scr.
// ---------------------------------------------------------------------------
#define PRO_ENC_B 0                  // ENC tile [64][520] halves  66560 B
#define PRO_W_B   66560              // W tile   [64][72]  halves   9216 B
#define PRO_SCR_B 75776              // scr 128 floats               512 B
#define PRO_SMEM  76288

__global__ void __launch_bounds__(256) prologue_kernel(
    const float* __restrict__ keys, const float* __restrict__ values,
    const float* __restrict__ W, const float* __restrict__ u_bias,
    const float* __restrict__ v_bias)
{
    extern __shared__ __align__(16) char psm[];
    int tid = threadIdx.x;

    if (blockIdx.x < 256) {
        // -------- cvt: one (head, s-tile) of 64 rows --------
        __half* Tsm = (__half*)psm;          // [64 d][72 s]
        int bid = blockIdx.x;
        int hn = bid & 15;
        int s0 = (bid >> 4) * 64;
        size_t base = (size_t)hn * Ss * DHh;

        int row = tid >> 2;
        int dq = (tid & 3) * 16;
        const float* kp = keys + base + (size_t)(s0 + row) * DHh + dq;
        const float* vp = values + base + (size_t)(s0 + row) * DHh + dq;
        unsigned kh[8];
#pragma unroll
        for (int j = 0; j < 16; j += 4) {
            float4 k = *(const float4*)(kp + j);
            float4 v = *(const float4*)(vp + j);
            kh[j / 2]     = packh2(k.x, k.y);
            kh[j / 2 + 1] = packh2(k.z, k.w);
            Tsm[(dq + j + 0) * 72 + row] = __float2half_rn(v.x);
            Tsm[(dq + j + 1) * 72 + row] = __float2half_rn(v.y);
            Tsm[(dq + j + 2) * 72 + row] = __float2half_rn(v.z);
            Tsm[(dq + j + 3) * 72 + row] = __float2half_rn(v.w);
        }
        __half* ko = g_Kh + base + (size_t)(s0 + row) * DHh + dq;
        *(uint4*)ko = *(uint4*)&kh[0];
        *(uint4*)(ko + 8) = *(uint4*)&kh[4];
        __syncthreads();
        int d = tid >> 2;
        int sc = (tid & 3) * 16;
        __half* vo = g_Vh + (size_t)hn * DHh * Ss + (size_t)d * Ss + s0 + sc;
        *(uint4*)vo = *(uint4*)&Tsm[d * 72 + sc];
        *(uint4*)(vo + 8) = *(uint4*)&Tsm[d * 72 + sc + 8];
    } else {
        // -------- rproj: local ENC in smem, fp16 m16n8k16 --------
        __half* ENCs = (__half*)(psm + PRO_ENC_B);   // [64 p][520 k]
        __half* Bsm  = (__half*)(psm + PRO_W_B);     // [64 c][72 k]
        float*  scr  = (float*)(psm + PRO_SCR_B);

        int idx = blockIdx.x - 256;
        int p0 = (idx & 31) * 64;
        int h = idx >> 5;
        int c0 = h * 64;

        int warp = tid >> 5, lane = tid & 31;
        int g = lane >> 2, tg = lane & 3;
        int wm = (warp & 3) * 16;
        int wn = warp >> 2;

        // build ENC tile: thread owns freq pair i -> cols 2i,2i+1; 64 rotation steps
        {
            int i = tid;
            const float coef = -9.210340371976184f / 512.0f;
            float invf = __expf((float)(2 * i) * coef);
            float s, c;
            sincosf((float)(1023 - p0) * invf, &s, &c);
            float rs, rc;
            sincosf(invf, &rs, &rc);
            for (int t = 0; t < 64; t++) {
                __half2 v = (p0 + t < Pp) ? __floats2half2_rn(s, c)
                                          : __floats2half2_rn(0.0f, 0.0f);
                *(__half2*)&ENCs[t * 520 + 2 * i] = v;
                float s2 = s * rc - c * rs;
                float c2 = c * rc + s * rs;
                s = s2; c = c2;
            }
        }

        float acc[4][4] = {};

        for (int j0 = 0; j0 < Dd; j0 += 64) {
            __syncthreads();   // ENC ready (first iter) / prev Bsm consumed
#pragma unroll
            for (int r = 0; r < 2; r++) {
                int q = tid + r * 256;
                int row = q >> 3, ch = q & 7;
                float4 w0 = *(const float4*)&W[(size_t)(c0 + row) * Dd + j0 + ch * 8];
                float4 w1 = *(const float4*)&W[(size_t)(c0 + row) * Dd + j0 + ch * 8 + 4];
                uint4 wp;
                wp.x = packh2(w0.x, w0.y); wp.y = packh2(w0.z, w0.w);
                wp.z = packh2(w1.x, w1.y); wp.w = packh2(w1.z, w1.w);
                *(uint4*)&Bsm[row * 72 + ch * 8] = wp;
            }
            __syncthreads();
#pragma unroll
            for (int k0 = 0; k0 < 64; k0 += 16) {
                unsigned a0 = ldh(&ENCs[(wm + g) * 520 + j0 + k0 + 2 * tg]);
                unsigned a1 = ldh(&ENCs[(wm + g + 8) * 520 + j0 + k0 + 2 * tg]);
                unsigned a2 = ldh(&ENCs[(wm + g) * 520 + j0 + k0 + 8 + 2 * tg]);
                unsigned a3 = ldh(&ENCs[(wm + g + 8) * 520 + j0 + k0 + 8 + 2 * tg]);
#pragma unroll
                for (int nt = 0; nt < 4; nt++) {
                    int n0 = wn * 32 + nt * 8;
                    unsigned b0 = ldh(&Bsm[(n0 + g) * 72 + k0 + 2 * tg]);
                    unsigned b1 = ldh(&Bsm[(n0 + g) * 72 + k0 + 8 + 2 * tg]);
                    mma_f16(acc[nt], a0, a1, a2, a3, b0, b1);
                }
            }
        }
        int pA = p0 + wm + g, pB = pA + 8;
        __half* Rh = g_Rh + (size_t)h * (Pp * DHh);
#pragma unroll
        for (int nt = 0; nt < 4; nt++) {
            int n0 = wn * 32 + nt * 8;
            if (pA < Pp)
                *(__half2*)&Rh[(size_t)pA * DHh + n0 + 2 * tg] =
                    __floats2half2_rn(acc[nt][0], acc[nt][1]);
            if (pB < Pp)
                *(__half2*)&Rh[(size_t)pB * DHh + n0 + 2 * tg] =
                    __floats2half2_rn(acc[nt][2], acc[nt][3]);
        }

        // g_T[h][p] = (v_bias - u_bias) . R[h][p][:]
        float localA = 0.0f, localB = 0.0f;
#pragma unroll
        for (int nt = 0; nt < 4; nt++) {
            int n0 = wn * 32 + nt * 8;
            float2 u2 = *(const float2*)&u_bias[h * DHh + n0 + 2 * tg];
            float2 v2 = *(const float2*)&v_bias[h * DHh + n0 + 2 * tg];
            float db0 = v2.x - u2.x, db1 = v2.y - u2.y;
            localA += acc[nt][0] * db0 + acc[nt][1] * db1;
            localB += acc[nt][2] * db0 + acc[nt][3] * db1;
        }
        localA += __shfl_xor_sync(0xffffffffu, localA, 1);
        localA += __shfl_xor_sync(0xffffffffu, localA, 2);
        localB += __shfl_xor_sync(0xffffffffu, localB, 1);
        localB += __shfl_xor_sync(0xffffffffu, localB, 2);
        if (tg == 0) {
            scr[wn * 64 + wm + g] = localA;
            scr[wn * 64 + wm + g + 8] = localB;
        }
        __syncthreads();
        if (tid < 64 && p0 + tid < Pp)
            g_T[h * TPAD + p0 + tid] = scr[tid] + scr[64 + tid];
    }
}

// ---------------------------------------------------------------------------
// Kernel 2: attention (unchanged, verified). grid (17, 8) balanced schedule.
// ---------------------------------------------------------------------------
#define SQU_B 0                     // Qu fp16 [64][72]     9216
#define SKH_B 9216                  // K ring 2x[64][72]h  18432
#define SRH_B 27648                 // R ring 2x[64][72]h  18432
#define SVT_B 46080                 // Vt ring 2x[64][72]h 18432
#define SBS_B 64512                 // BD ring 2x[64][68]f 34816
#define SMEM_BYTES 99328
#define EPX_B 0
#define EPM_B 69632
#define EPL_B 70656

__global__ void __launch_bounds__(512) attn_kernel(
    const float* __restrict__ seqs, const float* __restrict__ u_bias,
    float* __restrict__ out)
{
    extern __shared__ char smc[];
    __half* Quh = (__half*)(smc + SQU_B);
    __half* Khs = (__half*)(smc + SKH_B);
    __half* Rhs = (__half*)(smc + SRH_B);
    __half* Vts = (__half*)(smc + SVT_B);
    float*  Bs  = (float*)(smc + SBS_B);
    unsigned smb = (unsigned)__cvta_generic_to_shared(smc);

    int tid = threadIdx.x;
    int lane = tid & 31;
    int warp = tid >> 5;
    int g = lane >> 2, tg = lane & 3;
    int wm = (warp & 3) * 16;
    int wn = warp >> 2;
    int rA = wm + g, rB = wm + g + 8;

    int bx = blockIdx.x;   // 0..16 group
    int hp = blockIdx.y;   // 0..7 head pair

    int row8 = tid >> 3, ch8 = tid & 7;
    const float scale = 0.125f;

    for (int ph = 0; ph < 2; ph++) {
        int qt = (ph == 0) ? c_qtA[bx] : c_qtB[bx];
        if (qt < 0) break;
        int hn = hp * 2 + ((ph == 0) ? c_hA[bx] : c_hB[bx]);
        int h = hn & 7;

        size_t hoff = (size_t)hn * Ss * DHh;
        const __half* khg = g_Kh + hoff;
        const __half* vtg = g_Vh + (size_t)hn * DHh * Ss;
        const __half* Rhg = g_Rh + (size_t)h * (Pp * DHh);
        const float*  Th  = g_T + (size_t)h * TPAD;

        int i0 = qt * 64;
        int pb0 = (Ss - 1) - i0 - 63;

        __syncthreads();   // previous phase fully consumed

        cpa16(smb + SKH_B + row8 * 144 + ch8 * 16,
              khg + (size_t)row8 * DHh + ch8 * 8);
        cpa16(smb + SVT_B + row8 * 144 + ch8 * 16,
              vtg + (size_t)row8 * Ss + ch8 * 8);
#pragma unroll
        for (int r = 0; r < 2; r++) {
            int row = row8 + r * 64;
            cpa16(smb + SRH_B + row * 144 + ch8 * 16,
                  Rhg + (size_t)(pb0 + row) * DHh + ch8 * 8);
        }
        CP_COMMIT();

        {
            const float* qp = seqs + hoff + (size_t)(i0 + row8) * DHh + ch8 * 8;
            float4 q0 = *(const float4*)qp;
            float4 q1 = *(const float4*)(qp + 4);
            float4 u0 = *(const float4*)&u_bias[h * DHh + ch8 * 8];
            float4 u1 = *(const float4*)&u_bias[h * DHh + ch8 * 8 + 4];
            uint4 qv;
            qv.x = packh2(q0.x + u0.x, q0.y + u0.y);
            qv.y = packh2(q0.z + u0.z, q0.w + u0.w);
            qv.z = packh2(q1.x + u1.x, q1.y + u1.y);
            qv.w = packh2(q1.z + u1.z, q1.w + u1.w);
            *(uint4*)&Quh[row8 * 72 + ch8 * 8] = qv;
        }

        float mA_run = -1e30f, mB_run = -1e30f;
        float lA_run = 0.0f, lB_run = 0.0f;
        float O[8][4];
#pragma unroll
        for (int a = 0; a < 8; a++)
#pragma unroll
            for (int b = 0; b < 4; b++) O[a][b] = 0.0f;

        for (int kt = 0; kt <= qt; kt++) {
            int j0 = kt * 64;
            int pbase = (Ss - 1) - i0 + j0 - 63;
            int bufLow = kt & 1, bufHigh = bufLow ^ 1;

            CP_WAIT0();
            __syncthreads();

            if (kt < qt) {
                int jn = j0 + 64;
                cpa16(smb + SKH_B + bufHigh * 9216 + row8 * 144 + ch8 * 16,
                      khg + (size_t)(jn + row8) * DHh + ch8 * 8);
                cpa16(smb + SVT_B + bufHigh * 9216 + row8 * 144 + ch8 * 16,
                      vtg + (size_t)row8 * Ss + jn + ch8 * 8);
                CP_COMMIT();
            }

            const __half* Khb = Khs + bufLow * 4608;
            const __half* Vtb = Vts + bufLow * 4608;

            float2 tv[4];
            if (kt == 0) {
#pragma unroll
                for (int nt = 0; nt < 4; nt++)
                    tv[nt] = *(const float2*)&Th[pbase + wn * 32 + nt * 8 + 2 * tg];
            } else {
#pragma unroll
                for (int nt = 0; nt < 2; nt++)
                    tv[nt] = *(const float2*)&Th[pbase + 64 + wn * 16 + nt * 8 + 2 * tg];
            }

            float cS[2][4];
#pragma unroll
            for (int t = 0; t < 2; t++)
#pragma unroll
                for (int e = 0; e < 4; e++) cS[t][e] = 0.0f;

            if (kt == 0) {
                float cB[4][4];
#pragma unroll
                for (int t = 0; t < 4; t++)
#pragma unroll
                    for (int e = 0; e < 4; e++) cB[t][e] = 0.0f;
#pragma unroll
                for (int k0 = 0; k0 < 64; k0 += 16) {
                    unsigned a0 = ldh(&Quh[rA * 72 + k0 + 2 * tg]);
                    unsigned a1 = ldh(&Quh[rB * 72 + k0 + 2 * tg]);
                    unsigned a2 = ldh(&Quh[rA * 72 + k0 + 8 + 2 * tg]);
                    unsigned a3 = ldh(&Quh[rB * 72 + k0 + 8 + 2 * tg]);
#pragma unroll
                    for (int nt = 0; nt < 2; nt++) {
                        int n0 = wn * 16 + nt * 8;
                        unsigned b0 = ldh(&Khb[(n0 + g) * 72 + k0 + 2 * tg]);
                        unsigned b1 = ldh(&Khb[(n0 + g) * 72 + k0 + 8 + 2 * tg]);
                        mma_f16(cS[nt], a0, a1, a2, a3, b0, b1);
                    }
#pragma unroll
                    for (int nt = 0; nt < 4; nt++) {
                        int o0 = wn * 32 + nt * 8;
                        unsigned b0 = ldh(&Rhs[(o0 + g) * 72 + k0 + 2 * tg]);
                        unsigned b1 = ldh(&Rhs[(o0 + g) * 72 + k0 + 8 + 2 * tg]);
                        mma_f16(cB[nt], a0, a1, a2, a3, b0, b1);
                    }
                }
#pragma unroll
                for (int nt = 0; nt < 4; nt++) {
                    int o0 = wn * 32 + nt * 8;
                    float* Bd = Bs + (o0 >> 6) * 4352 + (o0 & 63) + 2 * tg;
                    *(float2*)&Bd[rA * 68] = make_float2(cB[nt][0] + tv[nt].x, cB[nt][1] + tv[nt].y);
                    *(float2*)&Bd[rB * 68] = make_float2(cB[nt][2] + tv[nt].x, cB[nt][3] + tv[nt].y);
                }
            } else {
                float cB[2][4];
#pragma unroll
                for (int t = 0; t < 2; t++)
#pragma unroll
                    for (int e = 0; e < 4; e++) cB[t][e] = 0.0f;
                const __half* Rb = Rhs + bufHigh * 4608;
#pragma unroll
                for (int k0 = 0; k0 < 64; k0 += 16) {
                    unsigned a0 = ldh(&Quh[rA * 72 + k0 + 2 * tg]);
                    unsigned a1 = ldh(&Quh[rB * 72 + k0 + 2 * tg]);
                    unsigned a2 = ldh(&Quh[rA * 72 + k0 + 8 + 2 * tg]);
                    unsigned a3 = ldh(&Quh[rB * 72 + k0 + 8 + 2 * tg]);
#pragma unroll
                    for (int nt = 0; nt < 2; nt++) {
                        int n0 = wn * 16 + nt * 8;
                        unsigned b0 = ldh(&Khb[(n0 + g) * 72 + k0 + 2 * tg]);
                        unsigned b1 = ldh(&Khb[(n0 + g) * 72 + k0 + 8 + 2 * tg]);
                        mma_f16(cS[nt], a0, a1, a2, a3, b0, b1);
                    }
#pragma unroll
                    for (int nt = 0; nt < 2; nt++) {
                        int r0 = wn * 16 + nt * 8;
                        unsigned b0 = ldh(&Rb[(r0 + g) * 72 + k0 + 2 * tg]);
                        unsigned b1 = ldh(&Rb[(r0 + g) * 72 + k0 + 8 + 2 * tg]);
                        mma_f16(cB[nt], a0, a1, a2, a3, b0, b1);
                    }
                }
                float* Bd0 = Bs + bufHigh * 4352;
#pragma unroll
                for (int nt = 0; nt < 2; nt++) {
                    int r0 = wn * 16 + nt * 8;
                    float* Bd = Bd0 + r0 + 2 * tg;
                    *(float2*)&Bd[rA * 68] = make_float2(cB[nt][0] + tv[nt].x, cB[nt][1] + tv[nt].y);
                    *(float2*)&Bd[rB * 68] = make_float2(cB[nt][2] + tv[nt].x, cB[nt][3] + tv[nt].y);
                }
            }
            __syncthreads();

            if (kt < qt) {
                cpa16(smb + SRH_B + bufLow * 9216 + row8 * 144 + ch8 * 16,
                      Rhg + (size_t)(pbase + 128 + row8) * DHh + ch8 * 8);
                CP_COMMIT();
            }

            float sv[2][4];
            float mAl = -INFINITY, mBl = -INFINITY;
            int diag = (kt == qt);
#pragma unroll
            for (int nt = 0; nt < 2; nt++) {
                int colbase = wn * 16 + nt * 8 + 2 * tg;
#pragma unroll
                for (int e = 0; e < 4; e++) {
                    int j = colbase + (e & 1);
                    int row = (e < 2) ? rA : rB;
                    int o = j - row + 63;
                    float bd = Bs[(bufLow ^ (o >> 6)) * 4352 + row * 68 + (o & 63)];
                    float s = (cS[nt][e] + bd) * scale;
                    if (diag && j > row) s = -INFINITY;
                    sv[nt][e] = s;
                    if (e < 2) mAl = fmaxf(mAl, s); else mBl = fmaxf(mBl, s);
                }
            }
            mAl = fmaxf(mAl, __shfl_xor_sync(0xffffffffu, mAl, 1));
            mAl = fmaxf(mAl, __shfl_xor_sync(0xffffffffu, mAl, 2));
            mBl = fmaxf(mBl, __shfl_xor_sync(0xffffffffu, mBl, 1));
            mBl = fmaxf(mBl, __shfl_xor_sync(0xffffffffu, mBl, 2));

            float mgA = fmaxf(mA_run, mAl);
            float mgB = fmaxf(mB_run, mBl);
            float corrA = __expf(mA_run - mgA);
            float corrB = __expf(mB_run - mgB);

            float peA0[2], peA1[2], peB0[2], peB1[2];
            float sumA = 0.0f, sumB = 0.0f;
#pragma unroll
            for (int nt = 0; nt < 2; nt++) {
                peA0[nt] = __expf(sv[nt][0] - mgA);
                peA1[nt] = __expf(sv[nt][1] - mgA);
                peB0[nt] = __expf(sv[nt][2] - mgB);
                peB1[nt] = __expf(sv[nt][3] - mgB);
                sumA += peA0[nt] + peA1[nt];
                sumB += peB0[nt] + peB1[nt];
            }
            sumA += __shfl_xor_sync(0xffffffffu, sumA, 1);
            sumA += __shfl_xor_sync(0xffffffffu, sumA, 2);
            sumB += __shfl_xor_sync(0xffffffffu, sumB, 1);
            sumB += __shfl_xor_sync(0xffffffffu, sumB, 2);
            lA_run = lA_run * corrA + sumA;
            lB_run = lB_run * corrB + sumB;
            mA_run = mgA; mB_run = mgB;

#pragma unroll
            for (int jn = 0; jn < 8; jn++) {
                O[jn][0] *= corrA; O[jn][1] *= corrA;
                O[jn][2] *= corrB; O[jn][3] *= corrB;
            }

            {
                unsigned a0 = packh2(peA0[0], peA1[0]);
                unsigned a1 = packh2(peB0[0], peB1[0]);
                unsigned a2 = packh2(peA0[1], peA1[1]);
                unsigned a3 = packh2(peB0[1], peB1[1]);
                int kbase = wn * 16;
#pragma unroll
                for (int jn = 0; jn < 8; jn++) {
                    int n0 = jn * 8;
                    unsigned b0 = ldh(&Vtb[(n0 + g) * 72 + kbase + 2 * tg]);
                    unsigned b1 = ldh(&Vtb[(n0 + g) * 72 + kbase + 8 + 2 * tg]);
                    mma_f16(O[jn], a0, a1, a2, a3, b0, b1);
                }
            }
        }

        __syncthreads();
        {
            float* Xo = (float*)(smc + EPX_B);
            float* mArr = (float*)(smc + EPM_B);
            float* lArr = (float*)(smc + EPL_B);
#pragma unroll
            for (int jn = 0; jn < 8; jn++) {
                int n0 = jn * 8;
                *(float2*)&Xo[wn * 4352 + rA * 68 + n0 + 2 * tg] =
                    make_float2(O[jn][0], O[jn][1]);
                *(float2*)&Xo[wn * 4352 + rB * 68 + n0 + 2 * tg] =
                    make_float2(O[jn][2], O[jn][3]);
            }
            if (tg == 0) {
                mArr[wn * 64 + rA] = mA_run; lArr[wn * 64 + rA] = lA_run;
                mArr[wn * 64 + rB] = mB_run; lArr[wn * 64 + rB] = lB_run;
            }
            __syncthreads();

            int row = tid >> 3, cb = (tid & 7) * 8;
            float m0 = mArr[row], m1 = mArr[64 + row];
            float m2 = mArr[128 + row], m3 = mArr[192 + row];
            float mg = fmaxf(fmaxf(m0, m1), fmaxf(m2, m3));
            float f0 = __expf(m0 - mg), f1 = __expf(m1 - mg);
            float f2 = __expf(m2 - mg), f3 = __expf(m3 - mg);
            float lg = lArr[row] * f0 + lArr[64 + row] * f1
                     + lArr[128 + row] * f2 + lArr[192 + row] * f3;
            float inv = 1.0f / lg;
            float* op = out + hoff + (size_t)(i0 + row) * DHh + cb;
#pragma unroll
            for (int c = 0; c < 8; c += 4) {
                float4 x0 = *(const float4*)&Xo[0 * 4352 + row * 68 + cb + c];
                float4 x1 = *(const float4*)&Xo[1 * 4352 + row * 68 + cb + c];
                float4 x2 = *(const float4*)&Xo[2 * 4352 + row * 68 + cb + c];
                float4 x3 = *(const float4*)&Xo[3 * 4352 + row * 68 + cb + c];
                float4 o4;
                o4.x = (x0.x * f0 + x1.x * f1 + x2.x * f2 + x3.x * f3) * inv;
                o4.y = (x0.y * f0 + x1.y * f1 + x2.y * f2 + x3.y * f3) * inv;
                o4.z = (x0.z * f0 + x1.z * f1 + x2.z * f2 + x3.z * f3) * inv;
                o4.w = (x0.w * f0 + x1.w * f1 + x2.w * f2 + x3.w * f3) * inv;
                *(float4*)&op[c] = o4;
            }
        }
    }
}

// ---------------------------------------------------------------------------
extern "C" void kernel_launch(void* const* d_in, const int* in_sizes, int n_in,
                              void* d_out, int out_size) {
    const float* seqs   = (const float*)d_in[0];
    const float* keys   = (const float*)d_in[1];
    const float* values = (const float*)d_in[2];
    const float* u_bias = (const float*)d_in[3];
    const float* v_bias = (const float*)d_in[4];
    const float* rproj  = (const float*)d_in[5];
    (void)in_sizes; (void)n_in; (void)out_size;

    cudaFuncSetAttribute(prologue_kernel, cudaFuncAttributeMaxDynamicSharedMemorySize,
                         PRO_SMEM);
    cudaFuncSetAttribute(attn_kernel, cudaFuncAttributeMaxDynamicSharedMemorySize,
                         SMEM_BYTES);

    prologue_kernel<<<512, 256, PRO_SMEM>>>(keys, values, rproj, u_bias, v_bias);
    attn_kernel<<<dim3(17, 8), 512, SMEM_BYTES>>>(seqs, u_bias, (float*)d_out);
}

// round 16
// speedup vs baseline: 2.0806x; 1.0406x over previous
#include <cuda_runtime.h>
#include <cuda_fp16.h>
#include <math.h>

#define Nn 2
#define Hh 8
#define Ss 1024
#define DHh 64
#define Dd 512
#define Pp 2047   // 2S-1
#define TPAD 2048 // padded head stride for g_T
#define NBLK 136u

__device__ __half g_Rh[Hh * Pp * DHh];        // rounded fp16 R
__device__ __half g_Kh[Nn * Hh * Ss * DHh];   // rounded fp16 keys
__device__ __half g_Vh[Nn * Hh * DHh * Ss];   // rounded fp16 V TRANSPOSED [hn][d][s]
__device__ float g_T[Hh * TPAD];
__device__ unsigned g_bar = 0;                // global barrier ticket counter

// balanced causal schedule: 17 groups per head-pair, each exactly 16 k-iters
__device__ const int c_qtA[17] = {15,15,14,14,13,13,12,12,11,11,10,10,9,9,8,8,7};
__device__ const int c_hA[17]  = { 0, 1, 0, 1, 0, 1, 0, 1, 0, 1, 0, 1,0,1,0,1,0};
__device__ const int c_qtB[17] = {-1,-1, 0, 0, 1, 1, 2, 2, 3, 3, 4, 4,5,5,6,6,7};
__device__ const int c_hB[17]  = { 0, 1, 0, 1, 0, 1, 0, 1, 0, 1, 0, 1,0,1,0,1,1};

__device__ __forceinline__ void mma_f16(float c[4], unsigned a0, unsigned a1,
                                        unsigned a2, unsigned a3,
                                        unsigned b0, unsigned b1) {
    asm volatile(
        "mma.sync.aligned.m16n8k16.row.col.f32.f16.f16.f32 "
        "{%0,%1,%2,%3},{%4,%5,%6,%7},{%8,%9},{%0,%1,%2,%3};"
        : "+f"(c[0]), "+f"(c[1]), "+f"(c[2]), "+f"(c[3])
        : "r"(a0), "r"(a1), "r"(a2), "r"(a3), "r"(b0), "r"(b1));
}
__device__ __forceinline__ unsigned ldh(const __half* p) { return *(const unsigned*)p; }
__device__ __forceinline__ unsigned packh2(float a, float b) {
    __half2 t = __floats2half2_rn(a, b);
    return reinterpret_cast<unsigned&>(t);
}
__device__ __forceinline__ void cpa16(unsigned dst, const void* src) {
    asm volatile("cp.async.cg.shared.global [%0], [%1], 16;" :: "r"(dst), "l"(src));
}
#define CP_COMMIT() asm volatile("cp.async.commit_group;")
#define CP_WAIT0()  asm volatile("cp.async.wait_group 0;")

// attn smem layout (bytes)
#define SQU_B 0
#define SKH_B 9216
#define SRH_B 27648
#define SVT_B 46080
#define SBS_B 64512
#define SMEM_BYTES 99328
#define EPX_B 0
#define EPM_B 69632
#define EPL_B 70656
// prologue overlays (within same 99328 window)
#define PRO_ENC_B 0        // ENC [64][520] halves  66560
#define PRO_W_B   66560    // 2 x W [64][72] halves 18432
#define PRO_SCR_B 84992    // 2 x 128 floats         1024

__global__ void __launch_bounds__(512) fused_kernel(
    const float* __restrict__ seqs, const float* __restrict__ keys,
    const float* __restrict__ values, const float* __restrict__ u_bias,
    const float* __restrict__ v_bias, const float* __restrict__ W,
    float* __restrict__ out)
{
    extern __shared__ __align__(16) char smc[];
    int tid = threadIdx.x;
    int b = blockIdx.y * 17 + blockIdx.x;   // 0..135
    int halfId = tid >> 8;                  // 0/1
    int t256 = tid & 255;

    // =====================================================================
    // Stage 1: cvt — block handles units b*2 (half 0) and b*2+1 (half 1)
    // =====================================================================
    {
        int u = b * 2 + halfId;
        bool act = (u < 256);
        int uc = act ? u : 255;
        int hn = uc & 15;
        int s0 = (uc >> 4) * 64;
        size_t base = (size_t)hn * Ss * DHh;
        __half* Tsm = (__half*)smc + halfId * 4608;   // [64][72]

        int row = t256 >> 2;
        int dq = (t256 & 3) * 16;
        const float* kp = keys + base + (size_t)(s0 + row) * DHh + dq;
        const float* vp = values + base + (size_t)(s0 + row) * DHh + dq;
        unsigned kh[8];
#pragma unroll
        for (int j = 0; j < 16; j += 4) {
            float4 k = *(const float4*)(kp + j);
            float4 v = *(const float4*)(vp + j);
            kh[j / 2]     = packh2(k.x, k.y);
            kh[j / 2 + 1] = packh2(k.z, k.w);
            Tsm[(dq + j + 0) * 72 + row] = __float2half_rn(v.x);
            Tsm[(dq + j + 1) * 72 + row] = __float2half_rn(v.y);
            Tsm[(dq + j + 2) * 72 + row] = __float2half_rn(v.z);
            Tsm[(dq + j + 3) * 72 + row] = __float2half_rn(v.w);
        }
        if (act) {
            __half* ko = g_Kh + base + (size_t)(s0 + row) * DHh + dq;
            *(uint4*)ko = *(uint4*)&kh[0];
            *(uint4*)(ko + 8) = *(uint4*)&kh[4];
        }
        __syncthreads();
        int d = t256 >> 2;
        int sc = (t256 & 3) * 16;
        if (act) {
            __half* vo = g_Vh + (size_t)hn * DHh * Ss + (size_t)d * Ss + s0 + sc;
            *(uint4*)vo = *(uint4*)&Tsm[d * 72 + sc];
            *(uint4*)(vo + 8) = *(uint4*)&Tsm[d * 72 + sc + 8];
        }
    }
    __syncthreads();   // Tsm dead; ENC region may be written

    // =====================================================================
    // Stage 2: rproj — blocks 0..127, unit (p0, hpair); halves share ENC
    // =====================================================================
    {
        bool ract = (b < 128);
        int bb = ract ? b : 0;
        int p0 = (bb & 31) * 64;
        int hpair = bb >> 5;                 // 0..3
        int h = hpair + halfId * 4;          // two heads per block
        int c0 = h * 64;

        __half* ENCs = (__half*)(smc + PRO_ENC_B);                 // [64][520]
        __half* Bsm  = (__half*)(smc + PRO_W_B) + halfId * 4608;   // [64][72]
        float*  scr  = (float*)(smc + PRO_SCR_B) + halfId * 128;

        // ENC build: freq i = t256; half 0 rows 0..31, half 1 rows 32..63
        {
            int i = t256;
            const float coef = -9.210340371976184f / 512.0f;
            float invf = __expf((float)(2 * i) * coef);
            int pstart = p0 + halfId * 32;
            float s, c;
            sincosf((float)(1023 - pstart) * invf, &s, &c);
            float rs, rc;
            sincosf(invf, &rs, &rc);
            for (int t = 0; t < 32; t++) {
                int p = pstart + t;
                __half2 v = (p < Pp) ? __floats2half2_rn(s, c)
                                     : __floats2half2_rn(0.0f, 0.0f);
                *(__half2*)&ENCs[(halfId * 32 + t) * 520 + 2 * i] = v;
                float s2 = s * rc - c * rs;
                float c2 = c * rc + s * rs;
                s = s2; c = c2;
            }
        }

        int warp4 = t256 >> 5;               // 0..7 within half
        int lane = t256 & 31;
        int g = lane >> 2, tg = lane & 3;
        int wm = (warp4 & 3) * 16;
        int wn2 = warp4 >> 2;                // 0/1

        float acc[4][4] = {};

        for (int j0 = 0; j0 < Dd; j0 += 64) {
            __syncthreads();   // ENC ready / prev Bsm consumed
#pragma unroll
            for (int r = 0; r < 2; r++) {
                int q = t256 + r * 256;
                int row = q >> 3, ch = q & 7;
                float4 w0 = *(const float4*)&W[(size_t)(c0 + row) * Dd + j0 + ch * 8];
                float4 w1 = *(const float4*)&W[(size_t)(c0 + row) * Dd + j0 + ch * 8 + 4];
                uint4 wp;
                wp.x = packh2(w0.x, w0.y); wp.y = packh2(w0.z, w0.w);
                wp.z = packh2(w1.x, w1.y); wp.w = packh2(w1.z, w1.w);
                *(uint4*)&Bsm[row * 72 + ch * 8] = wp;
            }
            __syncthreads();
#pragma unroll
            for (int k0 = 0; k0 < 64; k0 += 16) {
                unsigned a0 = ldh(&ENCs[(wm + g) * 520 + j0 + k0 + 2 * tg]);
                unsigned a1 = ldh(&ENCs[(wm + g + 8) * 520 + j0 + k0 + 2 * tg]);
                unsigned a2 = ldh(&ENCs[(wm + g) * 520 + j0 + k0 + 8 + 2 * tg]);
                unsigned a3 = ldh(&ENCs[(wm + g + 8) * 520 + j0 + k0 + 8 + 2 * tg]);
#pragma unroll
                for (int nt = 0; nt < 4; nt++) {
                    int n0 = wn2 * 32 + nt * 8;
                    unsigned b0 = ldh(&Bsm[(n0 + g) * 72 + k0 + 2 * tg]);
                    unsigned b1 = ldh(&Bsm[(n0 + g) * 72 + k0 + 8 + 2 * tg]);
                    mma_f16(acc[nt], a0, a1, a2, a3, b0, b1);
                }
            }
        }
        int pA = p0 + wm + g, pB = pA + 8;
        __half* Rh = g_Rh + (size_t)h * (Pp * DHh);
        if (ract) {
#pragma unroll
            for (int nt = 0; nt < 4; nt++) {
                int n0 = wn2 * 32 + nt * 8;
                if (pA < Pp)
                    *(__half2*)&Rh[(size_t)pA * DHh + n0 + 2 * tg] =
                        __floats2half2_rn(acc[nt][0], acc[nt][1]);
                if (pB < Pp)
                    *(__half2*)&Rh[(size_t)pB * DHh + n0 + 2 * tg] =
                        __floats2half2_rn(acc[nt][2], acc[nt][3]);
            }
        }
        // g_T
        float localA = 0.0f, localB = 0.0f;
#pragma unroll
        for (int nt = 0; nt < 4; nt++) {
            int n0 = wn2 * 32 + nt * 8;
            float2 u2 = *(const float2*)&u_bias[h * DHh + n0 + 2 * tg];
            float2 v2 = *(const float2*)&v_bias[h * DHh + n0 + 2 * tg];
            float db0 = v2.x - u2.x, db1 = v2.y - u2.y;
            localA += acc[nt][0] * db0 + acc[nt][1] * db1;
            localB += acc[nt][2] * db0 + acc[nt][3] * db1;
        }
        localA += __shfl_xor_sync(0xffffffffu, localA, 1);
        localA += __shfl_xor_sync(0xffffffffu, localA, 2);
        localB += __shfl_xor_sync(0xffffffffu, localB, 1);
        localB += __shfl_xor_sync(0xffffffffu, localB, 2);
        if (tg == 0) {
            scr[wn2 * 64 + wm + g] = localA;
            scr[wn2 * 64 + wm + g + 8] = localB;
        }
        __syncthreads();
        if (ract && t256 < 64 && p0 + t256 < Pp)
            g_T[h * TPAD + p0 + t256] = scr[t256] + scr[64 + t256];
    }

    // =====================================================================
    // Global barrier (all 136 blocks resident: 1 CTA/SM, 136 <= 148)
    // =====================================================================
    __syncthreads();
    if (tid == 0) {
        __threadfence();
        unsigned t = atomicAdd(&g_bar, 1u);
        unsigned target = (t / NBLK + 1u) * NBLK;
        while (atomicAdd(&g_bar, 0u) < target) { __nanosleep(64); }
        __threadfence();
    }
    __syncthreads();

    // =====================================================================
    // Stage 3: attention (verified code)
    // =====================================================================
    __half* Quh = (__half*)(smc + SQU_B);
    __half* Khs = (__half*)(smc + SKH_B);
    __half* Rhs = (__half*)(smc + SRH_B);
    __half* Vts = (__half*)(smc + SVT_B);
    float*  Bs  = (float*)(smc + SBS_B);
    unsigned smb = (unsigned)__cvta_generic_to_shared(smc);

    int lane = tid & 31;
    int warp = tid >> 5;
    int g = lane >> 2, tg = lane & 3;
    int wm = (warp & 3) * 16;
    int wn = warp >> 2;
    int rA = wm + g, rB = wm + g + 8;

    int bx = blockIdx.x;
    int hp = blockIdx.y;

    int row8 = tid >> 3, ch8 = tid & 7;
    const float scale = 0.125f;

    for (int ph = 0; ph < 2; ph++) {
        int qt = (ph == 0) ? c_qtA[bx] : c_qtB[bx];
        if (qt < 0) break;
        int hn = hp * 2 + ((ph == 0) ? c_hA[bx] : c_hB[bx]);
        int h = hn & 7;

        size_t hoff = (size_t)hn * Ss * DHh;
        const __half* khg = g_Kh + hoff;
        const __half* vtg = g_Vh + (size_t)hn * DHh * Ss;
        const __half* Rhg = g_Rh + (size_t)h * (Pp * DHh);
        const float*  Th  = g_T + (size_t)h * TPAD;

        int i0 = qt * 64;
        int pb0 = (Ss - 1) - i0 - 63;

        __syncthreads();

        cpa16(smb + SKH_B + row8 * 144 + ch8 * 16,
              khg + (size_t)row8 * DHh + ch8 * 8);
        cpa16(smb + SVT_B + row8 * 144 + ch8 * 16,
              vtg + (size_t)row8 * Ss + ch8 * 8);
#pragma unroll
        for (int r = 0; r < 2; r++) {
            int row = row8 + r * 64;
            cpa16(smb + SRH_B + row * 144 + ch8 * 16,
                  Rhg + (size_t)(pb0 + row) * DHh + ch8 * 8);
        }
        CP_COMMIT();

        {
            const float* qp = seqs + hoff + (size_t)(i0 + row8) * DHh + ch8 * 8;
            float4 q0 = *(const float4*)qp;
            float4 q1 = *(const float4*)(qp + 4);
            float4 u0 = *(const float4*)&u_bias[h * DHh + ch8 * 8];
            float4 u1 = *(const float4*)&u_bias[h * DHh + ch8 * 8 + 4];
            uint4 qv;
            qv.x = packh2(q0.x + u0.x, q0.y + u0.y);
            qv.y = packh2(q0.z + u0.z, q0.w + u0.w);
            qv.z = packh2(q1.x + u1.x, q1.y + u1.y);
            qv.w = packh2(q1.z + u1.z, q1.w + u1.w);
            *(uint4*)&Quh[row8 * 72 + ch8 * 8] = qv;
        }

        float mA_run = -1e30f, mB_run = -1e30f;
        float lA_run = 0.0f, lB_run = 0.0f;
        float O[8][4];
#pragma unroll
        for (int a = 0; a < 8; a++)
#pragma unroll
            for (int bq = 0; bq < 4; bq++) O[a][bq] = 0.0f;

        for (int kt = 0; kt <= qt; kt++) {
            int j0 = kt * 64;
            int pbase = (Ss - 1) - i0 + j0 - 63;
            int bufLow = kt & 1, bufHigh = bufLow ^ 1;

            CP_WAIT0();
            __syncthreads();

            if (kt < qt) {
                int jn = j0 + 64;
                cpa16(smb + SKH_B + bufHigh * 9216 + row8 * 144 + ch8 * 16,
                      khg + (size_t)(jn + row8) * DHh + ch8 * 8);
                cpa16(smb + SVT_B + bufHigh * 9216 + row8 * 144 + ch8 * 16,
                      vtg + (size_t)row8 * Ss + jn + ch8 * 8);
                CP_COMMIT();
            }

            const __half* Khb = Khs + bufLow * 4608;
            const __half* Vtb = Vts + bufLow * 4608;

            float2 tv[4];
            if (kt == 0) {
#pragma unroll
                for (int nt = 0; nt < 4; nt++)
                    tv[nt] = *(const float2*)&Th[pbase + wn * 32 + nt * 8 + 2 * tg];
            } else {
#pragma unroll
                for (int nt = 0; nt < 2; nt++)
                    tv[nt] = *(const float2*)&Th[pbase + 64 + wn * 16 + nt * 8 + 2 * tg];
            }

            float cS[2][4];
#pragma unroll
            for (int t = 0; t < 2; t++)
#pragma unroll
                for (int e = 0; e < 4; e++) cS[t][e] = 0.0f;

            if (kt == 0) {
                float cB[4][4];
#pragma unroll
                for (int t = 0; t < 4; t++)
#pragma unroll
                    for (int e = 0; e < 4; e++) cB[t][e] = 0.0f;
#pragma unroll
                for (int k0 = 0; k0 < 64; k0 += 16) {
                    unsigned a0 = ldh(&Quh[rA * 72 + k0 + 2 * tg]);
                    unsigned a1 = ldh(&Quh[rB * 72 + k0 + 2 * tg]);
                    unsigned a2 = ldh(&Quh[rA * 72 + k0 + 8 + 2 * tg]);
                    unsigned a3 = ldh(&Quh[rB * 72 + k0 + 8 + 2 * tg]);
#pragma unroll
                    for (int nt = 0; nt < 2; nt++) {
                        int n0 = wn * 16 + nt * 8;
                        unsigned b0 = ldh(&Khb[(n0 + g) * 72 + k0 + 2 * tg]);
                        unsigned b1 = ldh(&Khb[(n0 + g) * 72 + k0 + 8 + 2 * tg]);
                        mma_f16(cS[nt], a0, a1, a2, a3, b0, b1);
                    }
#pragma unroll
                    for (int nt = 0; nt < 4; nt++) {
                        int o0 = wn * 32 + nt * 8;
                        unsigned b0 = ldh(&Rhs[(o0 + g) * 72 + k0 + 2 * tg]);
                        unsigned b1 = ldh(&Rhs[(o0 + g) * 72 + k0 + 8 + 2 * tg]);
                        mma_f16(cB[nt], a0, a1, a2, a3, b0, b1);
                    }
                }
#pragma unroll
                for (int nt = 0; nt < 4; nt++) {
                    int o0 = wn * 32 + nt * 8;
                    float* Bd = Bs + (o0 >> 6) * 4352 + (o0 & 63) + 2 * tg;
                    *(float2*)&Bd[rA * 68] = make_float2(cB[nt][0] + tv[nt].x, cB[nt][1] + tv[nt].y);
                    *(float2*)&Bd[rB * 68] = make_float2(cB[nt][2] + tv[nt].x, cB[nt][3] + tv[nt].y);
                }
            } else {
                float cB[2][4];
#pragma unroll
                for (int t = 0; t < 2; t++)
#pragma unroll
                    for (int e = 0; e < 4; e++) cB[t][e] = 0.0f;
                const __half* Rb = Rhs + bufHigh * 4608;
#pragma unroll
                for (int k0 = 0; k0 < 64; k0 += 16) {
                    unsigned a0 = ldh(&Quh[rA * 72 + k0 + 2 * tg]);
                    unsigned a1 = ldh(&Quh[rB * 72 + k0 + 2 * tg]);
                    unsigned a2 = ldh(&Quh[rA * 72 + k0 + 8 + 2 * tg]);
                    unsigned a3 = ldh(&Quh[rB * 72 + k0 + 8 + 2 * tg]);
#pragma unroll
                    for (int nt = 0; nt < 2; nt++) {
                        int n0 = wn * 16 + nt * 8;
                        unsigned b0 = ldh(&Khb[(n0 + g) * 72 + k0 + 2 * tg]);
                        unsigned b1 = ldh(&Khb[(n0 + g) * 72 + k0 + 8 + 2 * tg]);
                        mma_f16(cS[nt], a0, a1, a2, a3, b0, b1);
                    }
#pragma unroll
                    for (int nt = 0; nt < 2; nt++) {
                        int r0 = wn * 16 + nt * 8;
                        unsigned b0 = ldh(&Rb[(r0 + g) * 72 + k0 + 2 * tg]);
                        unsigned b1 = ldh(&Rb[(r0 + g) * 72 + k0 + 8 + 2 * tg]);
                        mma_f16(cB[nt], a0, a1, a2, a3, b0, b1);
                    }
                }
                float* Bd0 = Bs + bufHigh * 4352;
#pragma unroll
                for (int nt = 0; nt < 2; nt++) {
                    int r0 = wn * 16 + nt * 8;
                    float* Bd = Bd0 + r0 + 2 * tg;
                    *(float2*)&Bd[rA * 68] = make_float2(cB[nt][0] + tv[nt].x, cB[nt][1] + tv[nt].y);
                    *(float2*)&Bd[rB * 68] = make_float2(cB[nt][2] + tv[nt].x, cB[nt][3] + tv[nt].y);
                }
            }
            __syncthreads();

            if (kt < qt) {
                cpa16(smb + SRH_B + bufLow * 9216 + row8 * 144 + ch8 * 16,
                      Rhg + (size_t)(pbase + 128 + row8) * DHh + ch8 * 8);
                CP_COMMIT();
            }

            float sv[2][4];
            float mAl = -INFINITY, mBl = -INFINITY;
            int diag = (kt == qt);
#pragma unroll
            for (int nt = 0; nt < 2; nt++) {
                int colbase = wn * 16 + nt * 8 + 2 * tg;
#pragma unroll
                for (int e = 0; e < 4; e++) {
                    int j = colbase + (e & 1);
                    int row = (e < 2) ? rA : rB;
                    int o = j - row + 63;
                    float bd = Bs[(bufLow ^ (o >> 6)) * 4352 + row * 68 + (o & 63)];
                    float s = (cS[nt][e] + bd) * scale;
                    if (diag && j > row) s = -INFINITY;
                    sv[nt][e] = s;
                    if (e < 2) mAl = fmaxf(mAl, s); else mBl = fmaxf(mBl, s);
                }
            }
            mAl = fmaxf(mAl, __shfl_xor_sync(0xffffffffu, mAl, 1));
            mAl = fmaxf(mAl, __shfl_xor_sync(0xffffffffu, mAl, 2));
            mBl = fmaxf(mBl, __shfl_xor_sync(0xffffffffu, mBl, 1));
            mBl = fmaxf(mBl, __shfl_xor_sync(0xffffffffu, mBl, 2));

            float mgA = fmaxf(mA_run, mAl);
            float mgB = fmaxf(mB_run, mBl);
            float corrA = __expf(mA_run - mgA);
            float corrB = __expf(mB_run - mgB);

            float peA0[2], peA1[2], peB0[2], peB1[2];
            float sumA = 0.0f, sumB = 0.0f;
#pragma unroll
            for (int nt = 0; nt < 2; nt++) {
                peA0[nt] = __expf(sv[nt][0] - mgA);
                peA1[nt] = __expf(sv[nt][1] - mgA);
                peB0[nt] = __expf(sv[nt][2] - mgB);
                peB1[nt] = __expf(sv[nt][3] - mgB);
                sumA += peA0[nt] + peA1[nt];
                sumB += peB0[nt] + peB1[nt];
            }
            sumA += __shfl_xor_sync(0xffffffffu, sumA, 1);
            sumA += __shfl_xor_sync(0xffffffffu, sumA, 2);
            sumB += __shfl_xor_sync(0xffffffffu, sumB, 1);
            sumB += __shfl_xor_sync(0xffffffffu, sumB, 2);
            lA_run = lA_run * corrA + sumA;
            lB_run = lB_run * corrB + sumB;
            mA_run = mgA; mB_run = mgB;

#pragma unroll
            for (int jn = 0; jn < 8; jn++) {
                O[jn][0] *= corrA; O[jn][1] *= corrA;
                O[jn][2] *= corrB; O[jn][3] *= corrB;
            }

            {
                unsigned a0 = packh2(peA0[0], peA1[0]);
                unsigned a1 = packh2(peB0[0], peB1[0]);
                unsigned a2 = packh2(peA0[1], peA1[1]);
                unsigned a3 = packh2(peB0[1], peB1[1]);
                int kbase = wn * 16;
#pragma unroll
                for (int jn = 0; jn < 8; jn++) {
                    int n0 = jn * 8;
                    unsigned b0 = ldh(&Vtb[(n0 + g) * 72 + kbase + 2 * tg]);
                    unsigned b1 = ldh(&Vtb[(n0 + g) * 72 + kbase + 8 + 2 * tg]);
                    mma_f16(O[jn], a0, a1, a2, a3, b0, b1);
                }
            }
        }

        __syncthreads();
        {
            float* Xo = (float*)(smc + EPX_B);
            float* mArr = (float*)(smc + EPM_B);
            float* lArr = (float*)(smc + EPL_B);
#pragma unroll
            for (int jn = 0; jn < 8; jn++) {
                int n0 = jn * 8;
                *(float2*)&Xo[wn * 4352 + rA * 68 + n0 + 2 * tg] =
                    make_float2(O[jn][0], O[jn][1]);
                *(float2*)&Xo[wn * 4352 + rB * 68 + n0 + 2 * tg] =
                    make_float2(O[jn][2], O[jn][3]);
            }
            if (tg == 0) {
                mArr[wn * 64 + rA] = mA_run; lArr[wn * 64 + rA] = lA_run;
                mArr[wn * 64 + rB] = mB_run; lArr[wn * 64 + rB] = lB_run;
            }
            __syncthreads();

            int row = tid >> 3, cb = (tid & 7) * 8;
            float m0 = mArr[row], m1 = mArr[64 + row];
            float m2 = mArr[128 + row], m3 = mArr[192 + row];
            float mg = fmaxf(fmaxf(m0, m1), fmaxf(m2, m3));
            float f0 = __expf(m0 - mg), f1 = __expf(m1 - mg);
            float f2 = __expf(m2 - mg), f3 = __expf(m3 - mg);
            float lg = lArr[row] * f0 + lArr[64 + row] * f1
                     + lArr[128 + row] * f2 + lArr[192 + row] * f3;
            float inv = 1.0f / lg;
            float* op = out + hoff + (size_t)(i0 + row) * DHh + cb;
#pragma unroll
            for (int c = 0; c < 8; c += 4) {
                float4 x0 = *(const float4*)&Xo[0 * 4352 + row * 68 + cb + c];
                float4 x1 = *(const float4*)&Xo[1 * 4352 + row * 68 + cb + c];
                float4 x2 = *(const float4*)&Xo[2 * 4352 + row * 68 + cb + c];
                float4 x3 = *(const float4*)&Xo[3 * 4352 + row * 68 + cb + c];
                float4 o4;
                o4.x = (x0.x * f0 + x1.x * f1 + x2.x * f2 + x3.x * f3) * inv;
                o4.y = (x0.y * f0 + x1.y * f1 + x2.y * f2 + x3.y * f3) * inv;
                o4.z = (x0.z * f0 + x1.z * f1 + x2.z * f2 + x3.z * f3) * inv;
                o4.w = (x0.w * f0 + x1.w * f1 + x2.w * f2 + x3.w * f3) * inv;
                *(float4*)&op[c] = o4;
            }
        }
    }
}

// ---------------------------------------------------------------------------
extern "C" void kernel_launch(void* const* d_in, const int* in_sizes, int n_in,
                              void* d_out, int out_size) {
    const float* seqs   = (const float*)d_in[0];
    const float* keys   = (const float*)d_in[1];
    const float* values = (const float*)d_in[2];
    const float* u_bias = (const float*)d_in[3];
    const float* v_bias = (const float*)d_in[4];
    const float* rproj  = (const float*)d_in[5];
    (void)in_sizes; (void)n_in; (void)out_size;

    cudaFuncSetAttribute(fused_kernel, cudaFuncAttributeMaxDynamicSharedMemorySize,
                         SMEM_BYTES);

    fused_kernel<<<dim3(17, 8), 512, SMEM_BYTES>>>(seqs, keys, values,
                                                   u_bias, v_bias, rproj,
                                                   (float*)d_out);
}